// round 5
// baseline (speedup 1.0000x reference)
#include <cuda_runtime.h>
#include <cuda_bf16.h>
#include <math.h>
#include <stdint.h>

#define BATCH 4
#define SEQ   1024
#define EMB   2048
#define NH    16
#define HD    128
#define MROWS (BATCH*SEQ)   /* 4096 */

// ---------------- scratch (device globals; no allocation allowed) ----------------
__device__ float g_Q[(size_t)64*1024*128];    // [B,H,S,D]
__device__ float g_K[(size_t)64*1024*128];
__device__ float g_V[(size_t)64*1024*128];
__device__ float g_ctx[(size_t)MROWS*EMB];    // [B,S,E]
__device__ __nv_bfloat16 g_Xh[(size_t)MROWS*EMB];
__device__ __nv_bfloat16 g_Xl[(size_t)MROWS*EMB];
__device__ __nv_bfloat16 g_Wh[(size_t)EMB*EMB];
__device__ __nv_bfloat16 g_Wl[(size_t)EMB*EMB];

// ======================= portable PTX helpers (sm_80+) ===========================
__device__ __forceinline__ uint32_t smem_u32(const void* p) {
    uint32_t a;
    asm("{ .reg .u64 t; cvta.to.shared.u64 t, %1; cvt.u32.u64 %0, t; }" : "=r"(a) : "l"(p));
    return a;
}
#define CP_ASYNC16(dst, src) \
    asm volatile("cp.async.cg.shared.global [%0], [%1], 16;" :: "r"(dst), "l"(src) : "memory")
#define CP_COMMIT()   asm volatile("cp.async.commit_group;" ::: "memory")
#define CP_WAIT2()    asm volatile("cp.async.wait_group 2;" ::: "memory")

__device__ __forceinline__ void ldsm_x4(uint32_t& r0, uint32_t& r1, uint32_t& r2,
                                        uint32_t& r3, uint32_t addr) {
    asm volatile("ldmatrix.sync.aligned.m8n8.x4.shared.b16 {%0,%1,%2,%3}, [%4];"
                 : "=r"(r0), "=r"(r1), "=r"(r2), "=r"(r3) : "r"(addr));
}
__device__ __forceinline__ void mma16816(float* d, const uint32_t* a, const uint32_t* b) {
    asm volatile("mma.sync.aligned.m16n8k16.row.col.f32.bf16.bf16.f32 "
                 "{%0,%1,%2,%3}, {%4,%5,%6,%7}, {%8,%9}, {%0,%1,%2,%3};"
                 : "+f"(d[0]), "+f"(d[1]), "+f"(d[2]), "+f"(d[3])
                 : "r"(a[0]), "r"(a[1]), "r"(a[2]), "r"(a[3]), "r"(b[0]), "r"(b[1]));
}
// 64B rows, 16B chunks; swizzle keeps 8x8 ldmatrix (8 rows x 16B) conflict-free.
__device__ __forceinline__ uint32_t swz64(int row, int colByte) {
    return (uint32_t)(row * 64 + ((((colByte >> 4) ^ (row >> 1)) & 3) * 16));
}
// fast 2^x for x <= 0 (softmax domain); deg-4 poly on f in [-0.5,0.5], err ~5e-5
__device__ __forceinline__ float exp2s(float x) {
    x = fmaxf(x, -126.0f);
    int i = __float2int_rn(x);
    float f = x - (float)i;
    float p = 0.00961812911f;
    p = fmaf(p, f, 0.0555041087f);
    p = fmaf(p, f, 0.240226507f);
    p = fmaf(p, f, 0.693147182f);
    p = fmaf(p, f, 1.0f);
    return p * __int_as_float((i + 127) << 23);
}

// ======================= split fp32 -> bf16 hi/lo ================================
__global__ __launch_bounds__(256)
void split_bf16(const float* __restrict__ X, __nv_bfloat16* __restrict__ Hi,
                __nv_bfloat16* __restrict__ Lo, int n4)
{
    int i = blockIdx.x * 256 + threadIdx.x;
    if (i >= n4) return;
    float4 v = ((const float4*)X)[i];
    __nv_bfloat16 h0 = __float2bfloat16(v.x);
    __nv_bfloat16 h1 = __float2bfloat16(v.y);
    __nv_bfloat16 h2 = __float2bfloat16(v.z);
    __nv_bfloat16 h3 = __float2bfloat16(v.w);
    __nv_bfloat16 l0 = __float2bfloat16(v.x - __bfloat162float(h0));
    __nv_bfloat16 l1 = __float2bfloat16(v.y - __bfloat162float(h1));
    __nv_bfloat16 l2 = __float2bfloat16(v.z - __bfloat162float(h2));
    __nv_bfloat16 l3 = __float2bfloat16(v.w - __bfloat162float(h3));
    __nv_bfloat162* H2 = (__nv_bfloat162*)Hi;
    __nv_bfloat162* L2 = (__nv_bfloat162*)Lo;
    H2[2*i]   = __nv_bfloat162(h0, h1);
    H2[2*i+1] = __nv_bfloat162(h2, h3);
    L2[2*i]   = __nv_bfloat162(l0, l1);
    L2[2*i+1] = __nv_bfloat162(l2, l3);
}

// ======================= mma.sync split-bf16 GEMM ================================
// Y[M,N] = (Ah+Al)[M,K] @ (Bh+Bl)[N,K]^T  (drop Al*Bl), fp32 accum in registers.
// CTA 128x256, BK=32, 512 threads (16 warps, warp tile 32x64), 3-stage cp.async.
// mode 0: scatter to [B,H,S,D]; mode 1: plain [M,EMB].
#define GBM 128
#define GBN 256
#define GBK 32
#define OFF_AH 0
#define OFF_AL 8192
#define OFF_BH 16384
#define OFF_BL 32768
#define STAGE_BYTES 49152
#define GEMM_SMEM (3 * STAGE_BYTES)   /* 147456 */

__global__ __launch_bounds__(512, 1)
void gemm_split_mma(const __nv_bfloat16* __restrict__ Ah, const __nv_bfloat16* __restrict__ Al,
                    const __nv_bfloat16* __restrict__ Bh, const __nv_bfloat16* __restrict__ Bl,
                    float* __restrict__ Y, int mode)
{
    extern __shared__ __align__(128) char smc[];
    const uint32_t sb = smem_u32(smc);
    const int tid = threadIdx.x, lane = tid & 31, wid = tid >> 5;
    const int m0 = blockIdx.y * GBM, n0 = blockIdx.x * GBN;
    const int warp_m = wid & 3;    // 4 groups x 32 rows
    const int warp_n = wid >> 2;   // 4 groups x 64 cols

    float acc[2][8][4];
#pragma unroll
    for (int i = 0; i < 2; ++i)
#pragma unroll
        for (int j = 0; j < 8; ++j)
#pragma unroll
            for (int r = 0; r < 4; ++r) acc[i][j][r] = 0.0f;

    auto issue_stage = [&](int c) {
        const uint32_t st = sb + (uint32_t)(c % 3) * STAGE_BYTES;
        const int kc = c * GBK;
#pragma unroll
        for (int u = 0; u < 6; ++u) {
            int f = tid + u * 512;
            uint32_t dst; const __nv_bfloat16* gp;
            if (f < 1024) {
                int rel = f & 511;
                int row = rel >> 2, ch = rel & 3;
                const __nv_bfloat16* base = (f < 512) ? Ah : Al;
                gp  = base + (size_t)(m0 + row) * EMB + kc + ch * 8;
                dst = st + ((f < 512) ? OFF_AH : OFF_AL) + swz64(row, ch * 16);
            } else {
                int rel = (f - 1024) & 1023;
                int row = rel >> 2, ch = rel & 3;
                const __nv_bfloat16* base = (f < 2048) ? Bh : Bl;
                gp  = base + (size_t)(n0 + row) * EMB + kc + ch * 8;
                dst = st + ((f < 2048) ? OFF_BH : OFF_BL) + swz64(row, ch * 16);
            }
            CP_ASYNC16(dst, gp);
        }
        CP_COMMIT();
    };

    issue_stage(0); issue_stage(1); issue_stage(2);

    const int a_row = warp_m * 32 + ((lane >> 3) & 1) * 8 + (lane & 7);
    const int a_cb  = (lane >> 4) * 16;
    const int b_row = warp_n * 64 + ((lane >> 4) & 1) * 8 + (lane & 7);
    const int b_cb  = ((lane >> 3) & 1) * 16;

    const int NC = EMB / GBK;   // 64
    for (int c = 0; c < NC; ++c) {
        CP_WAIT2();
        __syncthreads();
        const uint32_t st = sb + (uint32_t)(c % 3) * STAGE_BYTES;

#pragma unroll
        for (int ks = 0; ks < 2; ++ks) {
            const int cb = ks * 32;
            uint32_t a[2][2][4];
#pragma unroll
            for (int i = 0; i < 2; ++i) {
                ldsm_x4(a[0][i][0], a[0][i][1], a[0][i][2], a[0][i][3],
                        st + OFF_AH + swz64(a_row + i * 16, a_cb + cb));
                ldsm_x4(a[1][i][0], a[1][i][1], a[1][i][2], a[1][i][3],
                        st + OFF_AL + swz64(a_row + i * 16, a_cb + cb));
            }
            uint32_t b[8][2];
#pragma unroll
            for (int q = 0; q < 4; ++q)
                ldsm_x4(b[2*q][0], b[2*q][1], b[2*q+1][0], b[2*q+1][1],
                        st + OFF_BH + swz64(b_row + q * 16, b_cb + cb));
#pragma unroll
            for (int i = 0; i < 2; ++i)
#pragma unroll
                for (int j = 0; j < 8; ++j) {
                    mma16816(acc[i][j], a[0][i], b[j]);
                    mma16816(acc[i][j], a[1][i], b[j]);
                }
#pragma unroll
            for (int q = 0; q < 4; ++q)
                ldsm_x4(b[2*q][0], b[2*q][1], b[2*q+1][0], b[2*q+1][1],
                        st + OFF_BL + swz64(b_row + q * 16, b_cb + cb));
#pragma unroll
            for (int i = 0; i < 2; ++i)
#pragma unroll
                for (int j = 0; j < 8; ++j)
                    mma16816(acc[i][j], a[0][i], b[j]);
        }

        __syncthreads();
        if (c + 3 < NC) issue_stage(c + 3);
        else CP_COMMIT();
    }

    const int r0q = lane >> 2, c0q = (lane & 3) * 2;
#pragma unroll
    for (int i = 0; i < 2; ++i) {
#pragma unroll
        for (int j = 0; j < 8; ++j) {
            int mrow0 = m0 + warp_m * 32 + i * 16 + r0q;
            int ncol  = n0 + warp_n * 64 + j * 8 + c0q;
            float* p0; float* p1;
            if (mode == 0) {
                int h = ncol >> 7, dc = ncol & 127;
                int b0 = mrow0 >> 10, s0 = mrow0 & 1023;
                int b1 = (mrow0 + 8) >> 10, s1 = (mrow0 + 8) & 1023;
                p0 = Y + (((size_t)(b0 * NH + h)) * SEQ + s0) * HD + dc;
                p1 = Y + (((size_t)(b1 * NH + h)) * SEQ + s1) * HD + dc;
            } else {
                p0 = Y + (size_t)mrow0 * EMB + ncol;
                p1 = Y + (size_t)(mrow0 + 8) * EMB + ncol;
            }
            *(float2*)p0 = make_float2(acc[i][j][0], acc[i][j][1]);
            *(float2*)p1 = make_float2(acc[i][j][2], acc[i][j][3]);
        }
    }
}

// =================================================================================
// RoPE in place on Q and K, layout [B,H,S,D].
// =================================================================================
__global__ __launch_bounds__(256)
void rope_kernel(float* __restrict__ Q, float* __restrict__ K,
                 const float* __restrict__ cosT, const float* __restrict__ sinT)
{
    int idx = blockIdx.x * 256 + threadIdx.x;
    int d  = idx & 63;
    int s2 = (idx >> 6) & 1023;
    int bh = idx >> 16;
    size_t base = ((size_t)bh * SEQ + s2) * HD;
    float c  = cosT[s2*HD + d];
    float sn = sinT[s2*HD + d];
    float q1 = Q[base + d], q2 = Q[base + d + 64];
    Q[base + d]      = q1*c - q2*sn;
    Q[base + d + 64] = q2*c + q1*sn;
    float k1 = K[base + d], k2 = K[base + d + 64];
    K[base + d]      = k1*c - k2*sn;
    K[base + d + 64] = k2*c + k1*sn;
}

// =================================================================================
// Flash attention, fp32, causal — exp2-domain softmax (no MUFU).
// Q pre-scaled by log2(e)/sqrt(HD) at smem load; exp via FFMA polynomial.
// =================================================================================
#define SM_QS  0
#define SM_KST 16896
#define SM_VS  25600
#define SM_PS  34048
#define ATTN_SMEM_BYTES (42752 * 4)

__global__ __launch_bounds__(512)
void attn_kernel(const float* __restrict__ Q, const float* __restrict__ K,
                 const float* __restrict__ V, float* __restrict__ ctx)
{
    extern __shared__ __align__(16) float smf[];
    float* Qs  = smf + SM_QS;
    float* Kst = smf + SM_KST;
    float* Vs  = smf + SM_VS;
    float* Ps  = smf + SM_PS;

    const int bh = blockIdx.y;
    const int qt = blockIdx.x;
    const int q0 = qt * 128;
    const int tid = threadIdx.x;
    const int tx = tid & 15;
    const int ty = tid >> 4;
    const float scale = 0.12751743f;   // log2(e)/sqrt(128)

    const float* Qg = Q + ((size_t)bh * SEQ + q0) * HD;
    for (int f = tid; f < (128*128)/4; f += 512) {
        int row = f >> 5;
        int col = (f & 31) << 2;
        float4 v = *(const float4*)(Qg + row*HD + col);
        v.x *= scale; v.y *= scale; v.z *= scale; v.w *= scale;
        *(float4*)&Qs[row*132 + col] = v;
    }

    float acc[4][8];
    float mrow[4], lrow[4];
#pragma unroll
    for (int i = 0; i < 4; ++i) {
        mrow[i] = -1e30f; lrow[i] = 0.0f;
#pragma unroll
        for (int j = 0; j < 8; ++j) acc[i][j] = 0.0f;
    }

    const int nfull = q0 >> 6;
    const int ktmax = nfull + 1;

    for (int kt = 0; kt <= ktmax; ++kt) {
        __syncthreads();
        const float* Kg = K + ((size_t)bh * SEQ + kt*64) * HD;
        const float* Vg = V + ((size_t)bh * SEQ + kt*64) * HD;
        for (int f = tid; f < (64*128)/4; f += 512) {
            int row = f >> 5;
            int col = (f & 31) << 2;
            float4 kv = *(const float4*)(Kg + row*HD + col);
            Kst[(col+0)*68 + row] = kv.x;
            Kst[(col+1)*68 + row] = kv.y;
            Kst[(col+2)*68 + row] = kv.z;
            Kst[(col+3)*68 + row] = kv.w;
            float4 vv = *(const float4*)(Vg + row*HD + col);
            *(float4*)&Vs[row*132 + col] = vv;
        }
        __syncthreads();

        float s[4][4];
#pragma unroll
        for (int i = 0; i < 4; ++i)
#pragma unroll
            for (int j = 0; j < 4; ++j) s[i][j] = 0.0f;

        for (int d = 0; d < HD; d += 4) {
            float4 kb0 = *(const float4*)&Kst[(d+0)*68 + tx*4];
            float4 kb1 = *(const float4*)&Kst[(d+1)*68 + tx*4];
            float4 kb2 = *(const float4*)&Kst[(d+2)*68 + tx*4];
            float4 kb3 = *(const float4*)&Kst[(d+3)*68 + tx*4];
#pragma unroll
            for (int i = 0; i < 4; ++i) {
                float4 qa = *(const float4*)&Qs[(ty*4+i)*132 + d];
                s[i][0] += qa.x*kb0.x + qa.y*kb1.x + qa.z*kb2.x + qa.w*kb3.x;
                s[i][1] += qa.x*kb0.y + qa.y*kb1.y + qa.z*kb2.y + qa.w*kb3.y;
                s[i][2] += qa.x*kb0.z + qa.y*kb1.z + qa.z*kb2.z + qa.w*kb3.z;
                s[i][3] += qa.x*kb0.w + qa.y*kb1.w + qa.z*kb2.w + qa.w*kb3.w;
            }
        }

        if (kt >= nfull) {
#pragma unroll
            for (int i = 0; i < 4; ++i) {
                int qg = q0 + ty*4 + i;
#pragma unroll
                for (int jj = 0; jj < 4; ++jj) {
                    int kg = kt*64 + tx*4 + jj;
                    if (kg > qg) s[i][jj] = -1e30f;
                }
            }
        }

#pragma unroll
        for (int i = 0; i < 4; ++i) {
            float tm = fmaxf(fmaxf(s[i][0], s[i][1]), fmaxf(s[i][2], s[i][3]));
#pragma unroll
            for (int o = 8; o > 0; o >>= 1)
                tm = fmaxf(tm, __shfl_xor_sync(0xffffffffu, tm, o));
            float mnew = fmaxf(mrow[i], tm);
            float alpha = exp2s(mrow[i] - mnew);
            mrow[i] = mnew;
            float p0 = exp2s(s[i][0] - mnew);
            float p1 = exp2s(s[i][1] - mnew);
            float p2 = exp2s(s[i][2] - mnew);
            float p3 = exp2s(s[i][3] - mnew);
            float ts = (p0 + p1) + (p2 + p3);
#pragma unroll
            for (int o = 8; o > 0; o >>= 1)
                ts += __shfl_xor_sync(0xffffffffu, ts, o);
            lrow[i] = lrow[i] * alpha + ts;
#pragma unroll
            for (int j = 0; j < 8; ++j) acc[i][j] *= alpha;
            *(float4*)&Ps[(ty*4+i)*68 + tx*4] = make_float4(p0, p1, p2, p3);
        }
        __syncthreads();

        for (int sc = 0; sc < 64; ++sc) {
            float4 v1 = *(const float4*)&Vs[sc*132 + tx*4];
            float4 v2 = *(const float4*)&Vs[sc*132 + 64 + tx*4];
#pragma unroll
            for (int i = 0; i < 4; ++i) {
                float pa = Ps[(ty*4+i)*68 + sc];
                acc[i][0] += pa*v1.x; acc[i][1] += pa*v1.y;
                acc[i][2] += pa*v1.z; acc[i][3] += pa*v1.w;
                acc[i][4] += pa*v2.x; acc[i][5] += pa*v2.y;
                acc[i][6] += pa*v2.z; acc[i][7] += pa*v2.w;
            }
        }
    }

    const int b = bh >> 4, h = bh & 15;
#pragma unroll
    for (int i = 0; i < 4; ++i) {
        int q = q0 + ty*4 + i;
        float inv = 1.0f / lrow[i];
        float* row = ctx + ((size_t)(b*SEQ + q)) * EMB + h*HD;
        *(float4*)(row + tx*4) =
            make_float4(acc[i][0]*inv, acc[i][1]*inv, acc[i][2]*inv, acc[i][3]*inv);
        *(float4*)(row + 64 + tx*4) =
            make_float4(acc[i][4]*inv, acc[i][5]*inv, acc[i][6]*inv, acc[i][7]*inv);
    }
}

// =================================================================================
extern "C" void kernel_launch(void* const* d_in, const int* in_sizes, int n_in,
                              void* d_out, int out_size)
{
    const float* query = (const float*)d_in[0];
    const float* key   = (const float*)d_in[1];
    const float* value = (const float*)d_in[2];
    const float* cosT  = (const float*)d_in[4];
    const float* sinT  = (const float*)d_in[5];
    const float* Wq    = (const float*)d_in[6];
    const float* Wk    = (const float*)d_in[7];
    const float* Wv    = (const float*)d_in[8];
    const float* Wo    = (const float*)d_in[9];

    float *pQ, *pK, *pV, *pC;
    __nv_bfloat16 *pXh, *pXl, *pWh, *pWl;
    cudaGetSymbolAddress((void**)&pQ,  g_Q);
    cudaGetSymbolAddress((void**)&pK,  g_K);
    cudaGetSymbolAddress((void**)&pV,  g_V);
    cudaGetSymbolAddress((void**)&pC,  g_ctx);
    cudaGetSymbolAddress((void**)&pXh, g_Xh);
    cudaGetSymbolAddress((void**)&pXl, g_Xl);
    cudaGetSymbolAddress((void**)&pWh, g_Wh);
    cudaGetSymbolAddress((void**)&pWl, g_Wl);

    cudaFuncSetAttribute(gemm_split_mma, cudaFuncAttributeMaxDynamicSharedMemorySize,
                         GEMM_SMEM);
    cudaFuncSetAttribute(attn_kernel, cudaFuncAttributeMaxDynamicSharedMemorySize,
                         ATTN_SMEM_BYTES);

    const int nX4 = MROWS * EMB / 4;
    const int nW4 = EMB * EMB / 4;
    dim3 gGemm(EMB / GBN, MROWS / GBM);   // (8, 32)

    // Q projection
    split_bf16<<<nX4/256, 256>>>(query, pXh, pXl, nX4);
    split_bf16<<<nW4/256, 256>>>(Wq, pWh, pWl, nW4);
    gemm_split_mma<<<gGemm, 512, GEMM_SMEM>>>(pXh, pXl, pWh, pWl, pQ, 0);
    // K projection
    split_bf16<<<nX4/256, 256>>>(key, pXh, pXl, nX4);
    split_bf16<<<nW4/256, 256>>>(Wk, pWh, pWl, nW4);
    gemm_split_mma<<<gGemm, 512, GEMM_SMEM>>>(pXh, pXl, pWh, pWl, pK, 0);
    // V projection
    split_bf16<<<nX4/256, 256>>>(value, pXh, pXl, nX4);
    split_bf16<<<nW4/256, 256>>>(Wv, pWh, pWl, nW4);
    gemm_split_mma<<<gGemm, 512, GEMM_SMEM>>>(pXh, pXl, pWh, pWl, pV, 0);

    rope_kernel<<<(64*1024*64)/256, 256>>>(pQ, pK, cosT, sinT);

    attn_kernel<<<dim3(8, 64), 512, ATTN_SMEM_BYTES>>>(pQ, pK, pV, pC);

    // output projection
    split_bf16<<<nX4/256, 256>>>(pC, pXh, pXl, nX4);
    split_bf16<<<nW4/256, 256>>>(Wo, pWh, pWl, nW4);
    gemm_split_mma<<<gGemm, 512, GEMM_SMEM>>>(pXh, pXl, pWh, pWl, (float*)d_out, 1);
}

// round 7
// speedup vs baseline: 1.4014x; 1.4014x over previous
#include <cuda_runtime.h>
#include <cuda_bf16.h>
#include <math.h>
#include <stdint.h>

#define BATCH 4
#define SEQ   1024
#define EMB   2048
#define NH    16
#define HD    128
#define MROWS (BATCH*SEQ)   /* 4096 */

// ---------------- scratch (device globals; no allocation allowed) ----------------
__device__ float g_Q[(size_t)64*1024*128];    // [B,H,S,D]
__device__ float g_K[(size_t)64*1024*128];
__device__ float g_V[(size_t)64*1024*128];
__device__ float g_ctx[(size_t)MROWS*EMB];    // [B,S,E]
__device__ __nv_bfloat16 g_Xh[(size_t)MROWS*EMB];
__device__ __nv_bfloat16 g_Xl[(size_t)MROWS*EMB];
__device__ __nv_bfloat16 g_Wh[(size_t)EMB*EMB];
__device__ __nv_bfloat16 g_Wl[(size_t)EMB*EMB];
__device__ __nv_bfloat16 g_Kh[(size_t)MROWS*EMB];   // K splits (FULL size — R4/R6 bug fix)
__device__ __nv_bfloat16 g_Kl[(size_t)MROWS*EMB];
__device__ __nv_bfloat16 g_Vh[(size_t)MROWS*EMB];
__device__ __nv_bfloat16 g_Vl[(size_t)MROWS*EMB];

// ======================= portable PTX helpers (sm_80+) ===========================
__device__ __forceinline__ uint32_t smem_u32(const void* p) {
    uint32_t a;
    asm("{ .reg .u64 t; cvta.to.shared.u64 t, %1; cvt.u32.u64 %0, t; }" : "=r"(a) : "l"(p));
    return a;
}
#define CP_ASYNC16(dst, src) \
    asm volatile("cp.async.cg.shared.global [%0], [%1], 16;" :: "r"(dst), "l"(src) : "memory")
#define CP_COMMIT()   asm volatile("cp.async.commit_group;" ::: "memory")
#define CP_WAIT1()    asm volatile("cp.async.wait_group 1;" ::: "memory")
#define CP_WAIT2()    asm volatile("cp.async.wait_group 2;" ::: "memory")

__device__ __forceinline__ void ldsm_x4(uint32_t& r0, uint32_t& r1, uint32_t& r2,
                                        uint32_t& r3, uint32_t addr) {
    asm volatile("ldmatrix.sync.aligned.m8n8.x4.shared.b16 {%0,%1,%2,%3}, [%4];"
                 : "=r"(r0), "=r"(r1), "=r"(r2), "=r"(r3) : "r"(addr));
}
__device__ __forceinline__ void ldsm_x4_t(uint32_t& r0, uint32_t& r1, uint32_t& r2,
                                          uint32_t& r3, uint32_t addr) {
    asm volatile("ldmatrix.sync.aligned.m8n8.x4.trans.shared.b16 {%0,%1,%2,%3}, [%4];"
                 : "=r"(r0), "=r"(r1), "=r"(r2), "=r"(r3) : "r"(addr));
}
__device__ __forceinline__ void mma16816(float* d, const uint32_t* a, const uint32_t* b) {
    asm volatile("mma.sync.aligned.m16n8k16.row.col.f32.bf16.bf16.f32 "
                 "{%0,%1,%2,%3}, {%4,%5,%6,%7}, {%8,%9}, {%0,%1,%2,%3};"
                 : "+f"(d[0]), "+f"(d[1]), "+f"(d[2]), "+f"(d[3])
                 : "r"(a[0]), "r"(a[1]), "r"(a[2]), "r"(a[3]), "r"(b[0]), "r"(b[1]));
}
// 64B rows, 16B chunks; conflict-free ldmatrix.
__device__ __forceinline__ uint32_t swz64(int row, int colByte) {
    return (uint32_t)(row * 64 + ((((colByte >> 4) ^ (row >> 1)) & 3) * 16));
}
// 256B rows, 16 chunks of 16B; XOR low-3 chunk bits with row&7.
__device__ __forceinline__ uint32_t swz256(int row, int cb) {
    int ch = cb >> 4;
    int sw = (ch & 8) | ((ch ^ row) & 7);
    return (uint32_t)(row * 256 + sw * 16);
}
__device__ __forceinline__ uint32_t packbf(float lo, float hi) {
    __nv_bfloat162 t = __floats2bfloat162_rn(lo, hi);
    return *(uint32_t*)&t;
}
// fast 2^x for x <= 0 (softmax domain)
__device__ __forceinline__ float exp2s(float x) {
    x = fmaxf(x, -126.0f);
    int i = __float2int_rn(x);
    float f = x - (float)i;
    float p = 0.00961812911f;
    p = fmaf(p, f, 0.0555041087f);
    p = fmaf(p, f, 0.240226507f);
    p = fmaf(p, f, 0.693147182f);
    p = fmaf(p, f, 1.0f);
    return p * __int_as_float((i + 127) << 23);
}

// ======================= split fp32 -> bf16 hi/lo ================================
__global__ __launch_bounds__(256)
void split_bf16(const float* __restrict__ X, __nv_bfloat16* __restrict__ Hi,
                __nv_bfloat16* __restrict__ Lo, int n4)
{
    int i = blockIdx.x * 256 + threadIdx.x;
    if (i >= n4) return;
    float4 v = ((const float4*)X)[i];
    __nv_bfloat16 h0 = __float2bfloat16(v.x);
    __nv_bfloat16 h1 = __float2bfloat16(v.y);
    __nv_bfloat16 h2 = __float2bfloat16(v.z);
    __nv_bfloat16 h3 = __float2bfloat16(v.w);
    __nv_bfloat16 l0 = __float2bfloat16(v.x - __bfloat162float(h0));
    __nv_bfloat16 l1 = __float2bfloat16(v.y - __bfloat162float(h1));
    __nv_bfloat16 l2 = __float2bfloat16(v.z - __bfloat162float(h2));
    __nv_bfloat16 l3 = __float2bfloat16(v.w - __bfloat162float(h3));
    __nv_bfloat162* H2 = (__nv_bfloat162*)Hi;
    __nv_bfloat162* L2 = (__nv_bfloat162*)Lo;
    H2[2*i]   = __nv_bfloat162(h0, h1);
    H2[2*i+1] = __nv_bfloat162(h2, h3);
    L2[2*i]   = __nv_bfloat162(l0, l1);
    L2[2*i+1] = __nv_bfloat162(l2, l3);
}

// ======================= mma.sync split-bf16 GEMM (R3/R5 proven) =================
#define GBM 128
#define GBN 256
#define GBK 32
#define OFF_AH 0
#define OFF_AL 8192
#define OFF_BH 16384
#define OFF_BL 32768
#define STAGE_BYTES 49152
#define GEMM_SMEM (3 * STAGE_BYTES)   /* 147456 */

__global__ __launch_bounds__(512, 1)
void gemm_split_mma(const __nv_bfloat16* __restrict__ Ah, const __nv_bfloat16* __restrict__ Al,
                    const __nv_bfloat16* __restrict__ Bh, const __nv_bfloat16* __restrict__ Bl,
                    float* __restrict__ Y, int mode)
{
    extern __shared__ __align__(128) char smc[];
    const uint32_t sb = smem_u32(smc);
    const int tid = threadIdx.x, lane = tid & 31, wid = tid >> 5;
    const int m0 = blockIdx.y * GBM, n0 = blockIdx.x * GBN;
    const int warp_m = wid & 3;
    const int warp_n = wid >> 2;

    float acc[2][8][4];
#pragma unroll
    for (int i = 0; i < 2; ++i)
#pragma unroll
        for (int j = 0; j < 8; ++j)
#pragma unroll
            for (int r = 0; r < 4; ++r) acc[i][j][r] = 0.0f;

    auto issue_stage = [&](int c) {
        const uint32_t st = sb + (uint32_t)(c % 3) * STAGE_BYTES;
        const int kc = c * GBK;
#pragma unroll
        for (int u = 0; u < 6; ++u) {
            int f = tid + u * 512;
            uint32_t dst; const __nv_bfloat16* gp;
            if (f < 1024) {
                int rel = f & 511;
                int row = rel >> 2, ch = rel & 3;
                const __nv_bfloat16* base = (f < 512) ? Ah : Al;
                gp  = base + (size_t)(m0 + row) * EMB + kc + ch * 8;
                dst = st + ((f < 512) ? OFF_AH : OFF_AL) + swz64(row, ch * 16);
            } else {
                int rel = (f - 1024) & 1023;
                int row = rel >> 2, ch = rel & 3;
                const __nv_bfloat16* base = (f < 2048) ? Bh : Bl;
                gp  = base + (size_t)(n0 + row) * EMB + kc + ch * 8;
                dst = st + ((f < 2048) ? OFF_BH : OFF_BL) + swz64(row, ch * 16);
            }
            CP_ASYNC16(dst, gp);
        }
        CP_COMMIT();
    };

    issue_stage(0); issue_stage(1); issue_stage(2);

    const int a_row = warp_m * 32 + ((lane >> 3) & 1) * 8 + (lane & 7);
    const int a_cb  = (lane >> 4) * 16;
    const int b_row = warp_n * 64 + ((lane >> 4) & 1) * 8 + (lane & 7);
    const int b_cb  = ((lane >> 3) & 1) * 16;

    const int NC = EMB / GBK;   // 64
    for (int c = 0; c < NC; ++c) {
        CP_WAIT2();
        __syncthreads();
        const uint32_t st = sb + (uint32_t)(c % 3) * STAGE_BYTES;

#pragma unroll
        for (int ks = 0; ks < 2; ++ks) {
            const int cb = ks * 32;
            uint32_t a[2][2][4];
#pragma unroll
            for (int i = 0; i < 2; ++i) {
                ldsm_x4(a[0][i][0], a[0][i][1], a[0][i][2], a[0][i][3],
                        st + OFF_AH + swz64(a_row + i * 16, a_cb + cb));
                ldsm_x4(a[1][i][0], a[1][i][1], a[1][i][2], a[1][i][3],
                        st + OFF_AL + swz64(a_row + i * 16, a_cb + cb));
            }
            uint32_t b[8][2];
#pragma unroll
            for (int q = 0; q < 4; ++q)
                ldsm_x4(b[2*q][0], b[2*q][1], b[2*q+1][0], b[2*q+1][1],
                        st + OFF_BH + swz64(b_row + q * 16, b_cb + cb));
#pragma unroll
            for (int i = 0; i < 2; ++i)
#pragma unroll
                for (int j = 0; j < 8; ++j) {
                    mma16816(acc[i][j], a[0][i], b[j]);
                    mma16816(acc[i][j], a[1][i], b[j]);
                }
#pragma unroll
            for (int q = 0; q < 4; ++q)
                ldsm_x4(b[2*q][0], b[2*q][1], b[2*q+1][0], b[2*q+1][1],
                        st + OFF_BL + swz64(b_row + q * 16, b_cb + cb));
#pragma unroll
            for (int i = 0; i < 2; ++i)
#pragma unroll
                for (int j = 0; j < 8; ++j)
                    mma16816(acc[i][j], a[0][i], b[j]);
        }

        __syncthreads();
        if (c + 3 < NC) issue_stage(c + 3);
        else CP_COMMIT();
    }

    const int r0q = lane >> 2, c0q = (lane & 3) * 2;
#pragma unroll
    for (int i = 0; i < 2; ++i) {
#pragma unroll
        for (int j = 0; j < 8; ++j) {
            int mrow0 = m0 + warp_m * 32 + i * 16 + r0q;
            int ncol  = n0 + warp_n * 64 + j * 8 + c0q;
            float* p0; float* p1;
            if (mode == 0) {
                int h = ncol >> 7, dc = ncol & 127;
                int b0 = mrow0 >> 10, s0 = mrow0 & 1023;
                int b1 = (mrow0 + 8) >> 10, s1 = (mrow0 + 8) & 1023;
                p0 = Y + (((size_t)(b0 * NH + h)) * SEQ + s0) * HD + dc;
                p1 = Y + (((size_t)(b1 * NH + h)) * SEQ + s1) * HD + dc;
            } else {
                p0 = Y + (size_t)mrow0 * EMB + ncol;
                p1 = Y + (size_t)(mrow0 + 8) * EMB + ncol;
            }
            *(float2*)p0 = make_float2(acc[i][j][0], acc[i][j][1]);
            *(float2*)p1 = make_float2(acc[i][j][2], acc[i][j][3]);
        }
    }
}

// =================================================================================
// RoPE in place on Q and K, layout [B,H,S,D]  (proven).
// =================================================================================
__global__ __launch_bounds__(256)
void rope_kernel(float* __restrict__ Q, float* __restrict__ K,
                 const float* __restrict__ cosT, const float* __restrict__ sinT)
{
    int idx = blockIdx.x * 256 + threadIdx.x;
    int d  = idx & 63;
    int s2 = (idx >> 6) & 1023;
    int bh = idx >> 16;
    size_t base = ((size_t)bh * SEQ + s2) * HD;
    float c  = cosT[s2*HD + d];
    float sn = sinT[s2*HD + d];
    float q1 = Q[base + d], q2 = Q[base + d + 64];
    Q[base + d]      = q1*c - q2*sn;
    Q[base + d + 64] = q2*c + q1*sn;
    float k1 = K[base + d], k2 = K[base + d + 64];
    K[base + d]      = k1*c - k2*sn;
    K[base + d + 64] = k2*c + k1*sn;
}

// =================================================================================
// Tensor-core flash attention, causal. bf16 split Q/K/V (unscaled), scale applied
// inside exp2. P staged through smem (hi/lo), per-warp private. fp32 ctx out.
// 256 thr (8 warps x 16 rows). Q tile 128, K tile 64.
// =================================================================================
#define AT_QH 0u
#define AT_QL 32768u
#define AT_KV(s) (65536u + (uint32_t)(s) * 65536u)
#define AT_PH 196608u
#define AT_PL 212992u
#define AT2_SMEM 229376

__global__ __launch_bounds__(256, 1)
void attn_tc2(const __nv_bfloat16* __restrict__ Qh_g, const __nv_bfloat16* __restrict__ Ql_g,
              const __nv_bfloat16* __restrict__ Kh_g, const __nv_bfloat16* __restrict__ Kl_g,
              const __nv_bfloat16* __restrict__ Vh_g, const __nv_bfloat16* __restrict__ Vl_g,
              float* __restrict__ ctx)
{
    extern __shared__ __align__(128) char smc[];
    const uint32_t sb = smem_u32(smc);
    const int tid = threadIdx.x, lane = tid & 31, w = tid >> 5;
    const int qt = blockIdx.x, bh = blockIdx.y;
    const int q0 = qt * 128;
    const float SC = 0.12751743f;   // log2(e)/sqrt(128)

    {
        const size_t gbase = ((size_t)bh * SEQ + q0) * HD;
#pragma unroll
        for (int u = 0; u < 16; ++u) {
            int f = tid + u * 256;
            int rel = f & 2047;
            int row = rel >> 4, ch = rel & 15;
            const __nv_bfloat16* gp = ((f < 2048) ? Qh_g : Ql_g) + gbase + (size_t)row * HD + ch * 8;
            uint32_t dst = sb + ((f < 2048) ? AT_QH : AT_QL) + swz256(row, ch * 16);
            CP_ASYNC16(dst, gp);
        }
        CP_COMMIT();
    }

    auto issue_kv = [&](int kt) {
        const uint32_t st = sb + AT_KV(kt & 1);
        const size_t gbase = ((size_t)bh * SEQ + kt * 64) * HD;
#pragma unroll
        for (int u = 0; u < 16; ++u) {
            int f = tid + u * 256;
            int rel = f & 1023;
            int row = rel >> 4, ch = rel & 15;
            int arr = f >> 10;
            const __nv_bfloat16* gb = (arr == 0) ? Kh_g : (arr == 1) ? Kl_g
                                     : (arr == 2) ? Vh_g : Vl_g;
            const __nv_bfloat16* gp = gb + gbase + (size_t)row * HD + ch * 8;
            uint32_t dst = st + (uint32_t)arr * 16384u + swz256(row, ch * 16);
            CP_ASYNC16(dst, gp);
        }
        CP_COMMIT();
    };

    const int nkt = 2 * qt + 2;
    issue_kv(0);
    if (nkt > 1) issue_kv(1); else CP_COMMIT();

    const int rA = w * 16 + (lane >> 2);
    const int qa = q0 + rA, qb = qa + 8;
    float O[16][4];
#pragma unroll
    for (int j = 0; j < 16; ++j)
#pragma unroll
        for (int r = 0; r < 4; ++r) O[j][r] = 0.0f;
    float m_a = -1e30f, m_b = -1e30f, l_a = 0.0f, l_b = 0.0f;

    const int qa_row = w * 16 + ((lane >> 3) & 1) * 8 + (lane & 7);
    const int qa_cb  = (lane >> 4) * 16;
    const int kb_row = ((lane >> 4) & 1) * 8 + (lane & 7);
    const int kb_cb  = ((lane >> 3) & 1) * 16;
    const int vt_row = ((lane >> 3) & 1) * 8 + (lane & 7);
    const int vt_cb  = (lane >> 4) * 16;
    const int p_row = w * 16 + ((lane >> 3) & 1) * 8 + (lane & 7);
    const int p_ch  = (lane >> 4);

    for (int kt = 0; kt < nkt; ++kt) {
        CP_WAIT1();
        __syncthreads();
        const uint32_t st = sb + AT_KV(kt & 1);
        const bool skip = (kt * 64 > q0 + w * 16 + 15);

        if (!skip) {
            float sa[8][4];
#pragma unroll
            for (int j = 0; j < 8; ++j)
#pragma unroll
                for (int r = 0; r < 4; ++r) sa[j][r] = 0.0f;

#pragma unroll
            for (int kk = 0; kk < 8; ++kk) {
                const int cb = kk * 32;
                uint32_t aH[4], aL[4];
                ldsm_x4(aH[0], aH[1], aH[2], aH[3], sb + AT_QH + swz256(qa_row, qa_cb + cb));
                ldsm_x4(aL[0], aL[1], aL[2], aL[3], sb + AT_QL + swz256(qa_row, qa_cb + cb));
#pragma unroll
                for (int g = 0; g < 4; ++g) {
                    uint32_t b[4];
                    ldsm_x4(b[0], b[1], b[2], b[3],
                            st + swz256(g * 16 + kb_row, kb_cb + cb));          // Kh
                    mma16816(sa[2*g],   aH, b);
                    mma16816(sa[2*g+1], aH, b + 2);
                    mma16816(sa[2*g],   aL, b);
                    mma16816(sa[2*g+1], aL, b + 2);
                    ldsm_x4(b[0], b[1], b[2], b[3],
                            st + 16384u + swz256(g * 16 + kb_row, kb_cb + cb)); // Kl
                    mma16816(sa[2*g],   aH, b);
                    mma16816(sa[2*g+1], aH, b + 2);
                }
            }

            if (kt * 64 + 63 > q0 + w * 16) {
                const int colb = kt * 64 + (lane & 3) * 2;
#pragma unroll
                for (int j = 0; j < 8; ++j) {
                    int c0 = colb + j * 8, c1 = c0 + 1;
                    if (c0 > qa) sa[j][0] = -1e30f;
                    if (c1 > qa) sa[j][1] = -1e30f;
                    if (c0 > qb) sa[j][2] = -1e30f;
                    if (c1 > qb) sa[j][3] = -1e30f;
                }
            }

            float mxa = sa[0][0], mxb = sa[0][2];
#pragma unroll
            for (int j = 0; j < 8; ++j) {
                mxa = fmaxf(mxa, fmaxf(sa[j][0], sa[j][1]));
                mxb = fmaxf(mxb, fmaxf(sa[j][2], sa[j][3]));
            }
            mxa = fmaxf(mxa, __shfl_xor_sync(0xffffffffu, mxa, 1));
            mxa = fmaxf(mxa, __shfl_xor_sync(0xffffffffu, mxa, 2));
            mxb = fmaxf(mxb, __shfl_xor_sync(0xffffffffu, mxb, 1));
            mxb = fmaxf(mxb, __shfl_xor_sync(0xffffffffu, mxb, 2));
            float mna = fmaxf(m_a, mxa), mnb = fmaxf(m_b, mxb);
            float alpha_a = exp2s((m_a - mna) * SC);
            float alpha_b = exp2s((m_b - mnb) * SC);
            m_a = mna; m_b = mnb;

            float suma = 0.0f, sumb = 0.0f;
#pragma unroll
            for (int j = 0; j < 8; ++j) {
                sa[j][0] = exp2s((sa[j][0] - mna) * SC);
                sa[j][1] = exp2s((sa[j][1] - mna) * SC);
                sa[j][2] = exp2s((sa[j][2] - mnb) * SC);
                sa[j][3] = exp2s((sa[j][3] - mnb) * SC);
                suma += sa[j][0] + sa[j][1];
                sumb += sa[j][2] + sa[j][3];
            }
            suma += __shfl_xor_sync(0xffffffffu, suma, 1);
            suma += __shfl_xor_sync(0xffffffffu, suma, 2);
            sumb += __shfl_xor_sync(0xffffffffu, sumb, 1);
            sumb += __shfl_xor_sync(0xffffffffu, sumb, 2);
            l_a = l_a * alpha_a + suma;
            l_b = l_b * alpha_b + sumb;
#pragma unroll
            for (int j = 0; j < 16; ++j) {
                O[j][0] *= alpha_a; O[j][1] *= alpha_a;
                O[j][2] *= alpha_b; O[j][3] *= alpha_b;
            }

            const int rB = rA + 8;
            const int wb = (lane & 3) * 4;
#pragma unroll
            for (int j = 0; j < 8; ++j) {
                uint32_t hA = packbf(sa[j][0], sa[j][1]);
                uint32_t hB = packbf(sa[j][2], sa[j][3]);
                float2 fA = __bfloat1622float2(*(__nv_bfloat162*)&hA);
                float2 fB = __bfloat1622float2(*(__nv_bfloat162*)&hB);
                uint32_t lA = packbf(sa[j][0] - fA.x, sa[j][1] - fA.y);
                uint32_t lB = packbf(sa[j][2] - fB.x, sa[j][3] - fB.y);
                *(uint32_t*)(smc + AT_PH + rA*128 + ((j ^ (rA & 7)) * 16) + wb) = hA;
                *(uint32_t*)(smc + AT_PH + rB*128 + ((j ^ (rB & 7)) * 16) + wb) = hB;
                *(uint32_t*)(smc + AT_PL + rA*128 + ((j ^ (rA & 7)) * 16) + wb) = lA;
                *(uint32_t*)(smc + AT_PL + rB*128 + ((j ^ (rB & 7)) * 16) + wb) = lB;
            }
            __syncwarp();

            uint32_t aPh[4][4], aPl[4][4];
#pragma unroll
            for (int k2 = 0; k2 < 4; ++k2) {
                int ch = k2 * 2 + p_ch;
                uint32_t offH = AT_PH + (uint32_t)(p_row*128 + ((ch ^ (p_row & 7)) * 16));
                uint32_t offL = AT_PL + (uint32_t)(p_row*128 + ((ch ^ (p_row & 7)) * 16));
                ldsm_x4(aPh[k2][0], aPh[k2][1], aPh[k2][2], aPh[k2][3], sb + offH);
                ldsm_x4(aPl[k2][0], aPl[k2][1], aPl[k2][2], aPl[k2][3], sb + offL);
            }

#pragma unroll
            for (int g = 0; g < 8; ++g) {
#pragma unroll
                for (int k2 = 0; k2 < 4; ++k2) {
                    uint32_t b[4];
                    ldsm_x4_t(b[0], b[1], b[2], b[3],
                              st + 32768u + swz256(k2 * 16 + vt_row, g * 32 + vt_cb)); // Vh
                    mma16816(O[2*g],   aPh[k2], b);
                    mma16816(O[2*g+1], aPh[k2], b + 2);
                    mma16816(O[2*g],   aPl[k2], b);
                    mma16816(O[2*g+1], aPl[k2], b + 2);
                    ldsm_x4_t(b[0], b[1], b[2], b[3],
                              st + 49152u + swz256(k2 * 16 + vt_row, g * 32 + vt_cb)); // Vl
                    mma16816(O[2*g],   aPh[k2], b);
                    mma16816(O[2*g+1], aPh[k2], b + 2);
                }
            }
        }

        __syncthreads();
        if (kt + 2 < nkt) issue_kv(kt + 2);
        else CP_COMMIT();
    }

    const int b = bh >> 4, h = bh & 15;
    const float inva = 1.0f / l_a, invb = 1.0f / l_b;
    float* rowA = ctx + ((size_t)(b * SEQ + qa)) * EMB + h * HD;
    float* rowB = ctx + ((size_t)(b * SEQ + qb)) * EMB + h * HD;
#pragma unroll
    for (int j = 0; j < 16; ++j) {
        int dcol = j * 8 + (lane & 3) * 2;
        *(float2*)(rowA + dcol) = make_float2(O[j][0] * inva, O[j][1] * inva);
        *(float2*)(rowB + dcol) = make_float2(O[j][2] * invb, O[j][3] * invb);
    }
}

// =================================================================================
extern "C" void kernel_launch(void* const* d_in, const int* in_sizes, int n_in,
                              void* d_out, int out_size)
{
    const float* query = (const float*)d_in[0];
    const float* key   = (const float*)d_in[1];
    const float* value = (const float*)d_in[2];
    const float* cosT  = (const float*)d_in[4];
    const float* sinT  = (const float*)d_in[5];
    const float* Wq    = (const float*)d_in[6];
    const float* Wk    = (const float*)d_in[7];
    const float* Wv    = (const float*)d_in[8];
    const float* Wo    = (const float*)d_in[9];

    float *pQ, *pK, *pV, *pC;
    __nv_bfloat16 *pXh, *pXl, *pWh, *pWl, *pKh, *pKl, *pVh, *pVl;
    cudaGetSymbolAddress((void**)&pQ,  g_Q);
    cudaGetSymbolAddress((void**)&pK,  g_K);
    cudaGetSymbolAddress((void**)&pV,  g_V);
    cudaGetSymbolAddress((void**)&pC,  g_ctx);
    cudaGetSymbolAddress((void**)&pXh, g_Xh);
    cudaGetSymbolAddress((void**)&pXl, g_Xl);
    cudaGetSymbolAddress((void**)&pWh, g_Wh);
    cudaGetSymbolAddress((void**)&pWl, g_Wl);
    cudaGetSymbolAddress((void**)&pKh, g_Kh);
    cudaGetSymbolAddress((void**)&pKl, g_Kl);
    cudaGetSymbolAddress((void**)&pVh, g_Vh);
    cudaGetSymbolAddress((void**)&pVl, g_Vl);

    cudaFuncSetAttribute(gemm_split_mma, cudaFuncAttributeMaxDynamicSharedMemorySize,
                         GEMM_SMEM);
    cudaFuncSetAttribute(attn_tc2, cudaFuncAttributeMaxDynamicSharedMemorySize,
                         AT2_SMEM);

    const int nX4 = MROWS * EMB / 4;
    const int nW4 = EMB * EMB / 4;
    dim3 gGemm(EMB / GBN, MROWS / GBM);   // (8, 32)

    // projections
    split_bf16<<<nX4/256, 256>>>(query, pXh, pXl, nX4);
    split_bf16<<<nW4/256, 256>>>(Wq, pWh, pWl, nW4);
    gemm_split_mma<<<gGemm, 512, GEMM_SMEM>>>(pXh, pXl, pWh, pWl, pQ, 0);
    split_bf16<<<nX4/256, 256>>>(key, pXh, pXl, nX4);
    split_bf16<<<nW4/256, 256>>>(Wk, pWh, pWl, nW4);
    gemm_split_mma<<<gGemm, 512, GEMM_SMEM>>>(pXh, pXl, pWh, pWl, pK, 0);
    split_bf16<<<nX4/256, 256>>>(value, pXh, pXl, nX4);
    split_bf16<<<nW4/256, 256>>>(Wv, pWh, pWl, nW4);
    gemm_split_mma<<<gGemm, 512, GEMM_SMEM>>>(pXh, pXl, pWh, pWl, pV, 0);

    // RoPE (fp32, in place), then split attention operands (correctly-sized buffers)
    rope_kernel<<<(64*1024*64)/256, 256>>>(pQ, pK, cosT, sinT);
    split_bf16<<<nX4/256, 256>>>(pQ, pXh, pXl, nX4);
    split_bf16<<<nX4/256, 256>>>(pK, pKh, pKl, nX4);
    split_bf16<<<nX4/256, 256>>>(pV, pVh, pVl, nX4);

    // tensor-core flash attention -> fp32 ctx
    attn_tc2<<<dim3(8, 64), 256, AT2_SMEM>>>(pXh, pXl, pKh, pKl, pVh, pVl, pC);

    // output projection
    split_bf16<<<nX4/256, 256>>>(pC, pXh, pXl, nX4);
    split_bf16<<<nW4/256, 256>>>(Wo, pWh, pWl, nW4);
    gemm_split_mma<<<gGemm, 512, GEMM_SMEM>>>(pXh, pXl, pWh, pWl, (float*)d_out, 1);
}

// round 8
// speedup vs baseline: 1.4082x; 1.0049x over previous
#include <cuda_runtime.h>
#include <cuda_bf16.h>
#include <math.h>
#include <stdint.h>

#define BATCH 4
#define SEQ   1024
#define EMB   2048
#define NH    16
#define HD    128
#define MROWS (BATCH*SEQ)   /* 4096 */

// ---------------- scratch (device globals; no allocation allowed) ----------------
__device__ float g_Q[(size_t)MROWS*EMB];      // [B,H,S,D] fp32 (pre-RoPE)
__device__ float g_K[(size_t)MROWS*EMB];
__device__ __nv_bfloat16 g_Xh[(size_t)MROWS*EMB];   // X splits / Qh after rope_split
__device__ __nv_bfloat16 g_Xl[(size_t)MROWS*EMB];
__device__ __nv_bfloat16 g_Wh[(size_t)EMB*EMB];
__device__ __nv_bfloat16 g_Wl[(size_t)EMB*EMB];
__device__ __nv_bfloat16 g_Kh[(size_t)MROWS*EMB];
__device__ __nv_bfloat16 g_Kl[(size_t)MROWS*EMB];
__device__ __nv_bfloat16 g_Vh[(size_t)MROWS*EMB];
__device__ __nv_bfloat16 g_Vl[(size_t)MROWS*EMB];
__device__ __nv_bfloat16 g_Ch[(size_t)MROWS*EMB];   // ctx splits [B,S,E]
__device__ __nv_bfloat16 g_Cl[(size_t)MROWS*EMB];

// ======================= portable PTX helpers (sm_80+) ===========================
__device__ __forceinline__ uint32_t smem_u32(const void* p) {
    uint32_t a;
    asm("{ .reg .u64 t; cvta.to.shared.u64 t, %1; cvt.u32.u64 %0, t; }" : "=r"(a) : "l"(p));
    return a;
}
#define CP_ASYNC16(dst, src) \
    asm volatile("cp.async.cg.shared.global [%0], [%1], 16;" :: "r"(dst), "l"(src) : "memory")
#define CP_COMMIT()   asm volatile("cp.async.commit_group;" ::: "memory")
#define CP_WAIT1()    asm volatile("cp.async.wait_group 1;" ::: "memory")
#define CP_WAIT3()    asm volatile("cp.async.wait_group 3;" ::: "memory")

__device__ __forceinline__ void ldsm_x4(uint32_t& r0, uint32_t& r1, uint32_t& r2,
                                        uint32_t& r3, uint32_t addr) {
    asm volatile("ldmatrix.sync.aligned.m8n8.x4.shared.b16 {%0,%1,%2,%3}, [%4];"
                 : "=r"(r0), "=r"(r1), "=r"(r2), "=r"(r3) : "r"(addr));
}
__device__ __forceinline__ void ldsm_x4_t(uint32_t& r0, uint32_t& r1, uint32_t& r2,
                                          uint32_t& r3, uint32_t addr) {
    asm volatile("ldmatrix.sync.aligned.m8n8.x4.trans.shared.b16 {%0,%1,%2,%3}, [%4];"
                 : "=r"(r0), "=r"(r1), "=r"(r2), "=r"(r3) : "r"(addr));
}
__device__ __forceinline__ void mma16816(float* d, const uint32_t* a, const uint32_t* b) {
    asm volatile("mma.sync.aligned.m16n8k16.row.col.f32.bf16.bf16.f32 "
                 "{%0,%1,%2,%3}, {%4,%5,%6,%7}, {%8,%9}, {%0,%1,%2,%3};"
                 : "+f"(d[0]), "+f"(d[1]), "+f"(d[2]), "+f"(d[3])
                 : "r"(a[0]), "r"(a[1]), "r"(a[2]), "r"(a[3]), "r"(b[0]), "r"(b[1]));
}
__device__ __forceinline__ uint32_t swz64(int row, int colByte) {
    return (uint32_t)(row * 64 + ((((colByte >> 4) ^ (row >> 1)) & 3) * 16));
}
__device__ __forceinline__ uint32_t swz256(int row, int cb) {
    int ch = cb >> 4;
    int sw = (ch & 8) | ((ch ^ row) & 7);
    return (uint32_t)(row * 256 + sw * 16);
}
__device__ __forceinline__ uint32_t packbf(float lo, float hi) {
    __nv_bfloat162 t = __floats2bfloat162_rn(lo, hi);
    return *(uint32_t*)&t;
}
__device__ __forceinline__ float exp2s(float x) {
    x = fmaxf(x, -126.0f);
    int i = __float2int_rn(x);
    float f = x - (float)i;
    float p = 0.00961812911f;
    p = fmaf(p, f, 0.0555041087f);
    p = fmaf(p, f, 0.240226507f);
    p = fmaf(p, f, 0.693147182f);
    p = fmaf(p, f, 1.0f);
    return p * __int_as_float((i + 127) << 23);
}

// ======================= split fp32 -> bf16 hi/lo ================================
__global__ __launch_bounds__(256)
void split_bf16(const float* __restrict__ X, __nv_bfloat16* __restrict__ Hi,
                __nv_bfloat16* __restrict__ Lo, int n4)
{
    int i = blockIdx.x * 256 + threadIdx.x;
    if (i >= n4) return;
    float4 v = ((const float4*)X)[i];
    __nv_bfloat16 h0 = __float2bfloat16(v.x);
    __nv_bfloat16 h1 = __float2bfloat16(v.y);
    __nv_bfloat16 h2 = __float2bfloat16(v.z);
    __nv_bfloat16 h3 = __float2bfloat16(v.w);
    __nv_bfloat16 l0 = __float2bfloat16(v.x - __bfloat162float(h0));
    __nv_bfloat16 l1 = __float2bfloat16(v.y - __bfloat162float(h1));
    __nv_bfloat16 l2 = __float2bfloat16(v.z - __bfloat162float(h2));
    __nv_bfloat16 l3 = __float2bfloat16(v.w - __bfloat162float(h3));
    __nv_bfloat162* H2 = (__nv_bfloat162*)Hi;
    __nv_bfloat162* L2 = (__nv_bfloat162*)Lo;
    H2[2*i]   = __nv_bfloat162(h0, h1);
    H2[2*i+1] = __nv_bfloat162(h2, h3);
    L2[2*i]   = __nv_bfloat162(l0, l1);
    L2[2*i+1] = __nv_bfloat162(l2, l3);
}

// ======================= mma.sync split-bf16 GEMM (4-stage) ======================
// mode 0: fp32 scatter to [B,H,S,D]; mode 1: fp32 [M,EMB]; mode 2: bf16 hi/lo
// split scatter to [B,H,S,D] (Yh/Yl).
#define GBM 128
#define GBN 256
#define GBK 32
#define OFF_AH 0
#define OFF_AL 8192
#define OFF_BH 16384
#define OFF_BL 32768
#define STAGE_BYTES 49152
#define GSTAGES 4
#define GEMM_SMEM (GSTAGES * STAGE_BYTES)   /* 196608 */

__global__ __launch_bounds__(512, 1)
void gemm_split_mma(const __nv_bfloat16* __restrict__ Ah, const __nv_bfloat16* __restrict__ Al,
                    const __nv_bfloat16* __restrict__ Bh, const __nv_bfloat16* __restrict__ Bl,
                    float* __restrict__ Y,
                    __nv_bfloat16* __restrict__ Yh, __nv_bfloat16* __restrict__ Yl,
                    int mode)
{
    extern __shared__ __align__(128) char smc[];
    const uint32_t sb = smem_u32(smc);
    const int tid = threadIdx.x, lane = tid & 31, wid = tid >> 5;
    const int m0 = blockIdx.y * GBM, n0 = blockIdx.x * GBN;
    const int warp_m = wid & 3;
    const int warp_n = wid >> 2;

    float acc[2][8][4];
#pragma unroll
    for (int i = 0; i < 2; ++i)
#pragma unroll
        for (int j = 0; j < 8; ++j)
#pragma unroll
            for (int r = 0; r < 4; ++r) acc[i][j][r] = 0.0f;

    auto issue_stage = [&](int c) {
        const uint32_t st = sb + (uint32_t)(c % GSTAGES) * STAGE_BYTES;
        const int kc = c * GBK;
#pragma unroll
        for (int u = 0; u < 6; ++u) {
            int f = tid + u * 512;
            uint32_t dst; const __nv_bfloat16* gp;
            if (f < 1024) {
                int rel = f & 511;
                int row = rel >> 2, ch = rel & 3;
                const __nv_bfloat16* base = (f < 512) ? Ah : Al;
                gp  = base + (size_t)(m0 + row) * EMB + kc + ch * 8;
                dst = st + ((f < 512) ? OFF_AH : OFF_AL) + swz64(row, ch * 16);
            } else {
                int rel = (f - 1024) & 1023;
                int row = rel >> 2, ch = rel & 3;
                const __nv_bfloat16* base = (f < 2048) ? Bh : Bl;
                gp  = base + (size_t)(n0 + row) * EMB + kc + ch * 8;
                dst = st + ((f < 2048) ? OFF_BH : OFF_BL) + swz64(row, ch * 16);
            }
            CP_ASYNC16(dst, gp);
        }
        CP_COMMIT();
    };

    issue_stage(0); issue_stage(1); issue_stage(2); issue_stage(3);

    const int a_row = warp_m * 32 + ((lane >> 3) & 1) * 8 + (lane & 7);
    const int a_cb  = (lane >> 4) * 16;
    const int b_row = warp_n * 64 + ((lane >> 4) & 1) * 8 + (lane & 7);
    const int b_cb  = ((lane >> 3) & 1) * 16;

    const int NC = EMB / GBK;   // 64
    for (int c = 0; c < NC; ++c) {
        CP_WAIT3();
        __syncthreads();
        const uint32_t st = sb + (uint32_t)(c % GSTAGES) * STAGE_BYTES;

#pragma unroll
        for (int ks = 0; ks < 2; ++ks) {
            const int cb = ks * 32;
            uint32_t a[2][2][4];
#pragma unroll
            for (int i = 0; i < 2; ++i) {
                ldsm_x4(a[0][i][0], a[0][i][1], a[0][i][2], a[0][i][3],
                        st + OFF_AH + swz64(a_row + i * 16, a_cb + cb));
                ldsm_x4(a[1][i][0], a[1][i][1], a[1][i][2], a[1][i][3],
                        st + OFF_AL + swz64(a_row + i * 16, a_cb + cb));
            }
            uint32_t b[8][2];
#pragma unroll
            for (int q = 0; q < 4; ++q)
                ldsm_x4(b[2*q][0], b[2*q][1], b[2*q+1][0], b[2*q+1][1],
                        st + OFF_BH + swz64(b_row + q * 16, b_cb + cb));
#pragma unroll
            for (int i = 0; i < 2; ++i)
#pragma unroll
                for (int j = 0; j < 8; ++j) {
                    mma16816(acc[i][j], a[0][i], b[j]);
                    mma16816(acc[i][j], a[1][i], b[j]);
                }
#pragma unroll
            for (int q = 0; q < 4; ++q)
                ldsm_x4(b[2*q][0], b[2*q][1], b[2*q+1][0], b[2*q+1][1],
                        st + OFF_BL + swz64(b_row + q * 16, b_cb + cb));
#pragma unroll
            for (int i = 0; i < 2; ++i)
#pragma unroll
                for (int j = 0; j < 8; ++j)
                    mma16816(acc[i][j], a[0][i], b[j]);
        }

        __syncthreads();
        if (c + GSTAGES < NC) issue_stage(c + GSTAGES);
        else CP_COMMIT();
    }

    const int r0q = lane >> 2, c0q = (lane & 3) * 2;
#pragma unroll
    for (int i = 0; i < 2; ++i) {
#pragma unroll
        for (int j = 0; j < 8; ++j) {
            int mrow0 = m0 + warp_m * 32 + i * 16 + r0q;
            int ncol  = n0 + warp_n * 64 + j * 8 + c0q;
            if (mode == 2) {
                int h = ncol >> 7, dc = ncol & 127;
                int b0 = mrow0 >> 10, s0 = mrow0 & 1023;
                int b1 = (mrow0 + 8) >> 10, s1 = (mrow0 + 8) & 1023;
                size_t o0 = (((size_t)(b0 * NH + h)) * SEQ + s0) * HD + dc;
                size_t o1 = (((size_t)(b1 * NH + h)) * SEQ + s1) * HD + dc;
                uint32_t h0 = packbf(acc[i][j][0], acc[i][j][1]);
                uint32_t h1 = packbf(acc[i][j][2], acc[i][j][3]);
                float2 f0 = __bfloat1622float2(*(__nv_bfloat162*)&h0);
                float2 f1 = __bfloat1622float2(*(__nv_bfloat162*)&h1);
                uint32_t l0 = packbf(acc[i][j][0] - f0.x, acc[i][j][1] - f0.y);
                uint32_t l1 = packbf(acc[i][j][2] - f1.x, acc[i][j][3] - f1.y);
                *(uint32_t*)(Yh + o0) = h0;
                *(uint32_t*)(Yh + o1) = h1;
                *(uint32_t*)(Yl + o0) = l0;
                *(uint32_t*)(Yl + o1) = l1;
            } else if (mode == 0) {
                int h = ncol >> 7, dc = ncol & 127;
                int b0 = mrow0 >> 10, s0 = mrow0 & 1023;
                int b1 = (mrow0 + 8) >> 10, s1 = (mrow0 + 8) & 1023;
                float* p0 = Y + (((size_t)(b0 * NH + h)) * SEQ + s0) * HD + dc;
                float* p1 = Y + (((size_t)(b1 * NH + h)) * SEQ + s1) * HD + dc;
                *(float2*)p0 = make_float2(acc[i][j][0], acc[i][j][1]);
                *(float2*)p1 = make_float2(acc[i][j][2], acc[i][j][3]);
            } else {
                float* p0 = Y + (size_t)mrow0 * EMB + ncol;
                float* p1 = Y + (size_t)(mrow0 + 8) * EMB + ncol;
                *(float2*)p0 = make_float2(acc[i][j][0], acc[i][j][1]);
                *(float2*)p1 = make_float2(acc[i][j][2], acc[i][j][3]);
            }
        }
    }
}

// =================================================================================
// Fused RoPE + bf16 hi/lo split (unscaled; attn applies scale inside exp2).
// =================================================================================
__global__ __launch_bounds__(256)
void rope_split(const float* __restrict__ Q, const float* __restrict__ K,
                const float* __restrict__ cosT, const float* __restrict__ sinT,
                __nv_bfloat16* __restrict__ Qh, __nv_bfloat16* __restrict__ Ql,
                __nv_bfloat16* __restrict__ Kh, __nv_bfloat16* __restrict__ Kl)
{
    int idx = blockIdx.x * 256 + threadIdx.x;
    int d  = idx & 63;
    int s2 = (idx >> 6) & 1023;
    int bh = idx >> 16;
    size_t base = ((size_t)bh * SEQ + s2) * HD;
    float c  = cosT[s2*HD + d];
    float sn = sinT[s2*HD + d];

    float q1 = Q[base + d], q2 = Q[base + d + 64];
    float r1 = q1*c - q2*sn;
    float r2 = q2*c + q1*sn;
    __nv_bfloat16 h1 = __float2bfloat16(r1), h2 = __float2bfloat16(r2);
    Qh[base + d]      = h1;  Ql[base + d]      = __float2bfloat16(r1 - __bfloat162float(h1));
    Qh[base + d + 64] = h2;  Ql[base + d + 64] = __float2bfloat16(r2 - __bfloat162float(h2));

    float k1 = K[base + d], k2 = K[base + d + 64];
    float t1 = k1*c - k2*sn;
    float t2 = k2*c + k1*sn;
    __nv_bfloat16 g1 = __float2bfloat16(t1), g2 = __float2bfloat16(t2);
    Kh[base + d]      = g1;  Kl[base + d]      = __float2bfloat16(t1 - __bfloat162float(g1));
    Kh[base + d + 64] = g2;  Kl[base + d + 64] = __float2bfloat16(t2 - __bfloat162float(g2));
}

// =================================================================================
// Tensor-core flash attention (R7 proven), epilogue now writes ctx bf16 splits.
// =================================================================================
#define AT_QH 0u
#define AT_QL 32768u
#define AT_KV(s) (65536u + (uint32_t)(s) * 65536u)
#define AT_PH 196608u
#define AT_PL 212992u
#define AT2_SMEM 229376

__global__ __launch_bounds__(256, 1)
void attn_tc2(const __nv_bfloat16* __restrict__ Qh_g, const __nv_bfloat16* __restrict__ Ql_g,
              const __nv_bfloat16* __restrict__ Kh_g, const __nv_bfloat16* __restrict__ Kl_g,
              const __nv_bfloat16* __restrict__ Vh_g, const __nv_bfloat16* __restrict__ Vl_g,
              __nv_bfloat16* __restrict__ Ch, __nv_bfloat16* __restrict__ Cl)
{
    extern __shared__ __align__(128) char smc[];
    const uint32_t sb = smem_u32(smc);
    const int tid = threadIdx.x, lane = tid & 31, w = tid >> 5;
    const int qt = blockIdx.x, bh = blockIdx.y;
    const int q0 = qt * 128;
    const float SC = 0.12751743f;   // log2(e)/sqrt(128)

    {
        const size_t gbase = ((size_t)bh * SEQ + q0) * HD;
#pragma unroll
        for (int u = 0; u < 16; ++u) {
            int f = tid + u * 256;
            int rel = f & 2047;
            int row = rel >> 4, ch = rel & 15;
            const __nv_bfloat16* gp = ((f < 2048) ? Qh_g : Ql_g) + gbase + (size_t)row * HD + ch * 8;
            uint32_t dst = sb + ((f < 2048) ? AT_QH : AT_QL) + swz256(row, ch * 16);
            CP_ASYNC16(dst, gp);
        }
        CP_COMMIT();
    }

    auto issue_kv = [&](int kt) {
        const uint32_t st = sb + AT_KV(kt & 1);
        const size_t gbase = ((size_t)bh * SEQ + kt * 64) * HD;
#pragma unroll
        for (int u = 0; u < 16; ++u) {
            int f = tid + u * 256;
            int rel = f & 1023;
            int row = rel >> 4, ch = rel & 15;
            int arr = f >> 10;
            const __nv_bfloat16* gb = (arr == 0) ? Kh_g : (arr == 1) ? Kl_g
                                     : (arr == 2) ? Vh_g : Vl_g;
            const __nv_bfloat16* gp = gb + gbase + (size_t)row * HD + ch * 8;
            uint32_t dst = st + (uint32_t)arr * 16384u + swz256(row, ch * 16);
            CP_ASYNC16(dst, gp);
        }
        CP_COMMIT();
    };

    const int nkt = 2 * qt + 2;
    issue_kv(0);
    if (nkt > 1) issue_kv(1); else CP_COMMIT();

    const int rA = w * 16 + (lane >> 2);
    const int qa = q0 + rA, qb = qa + 8;
    float O[16][4];
#pragma unroll
    for (int j = 0; j < 16; ++j)
#pragma unroll
        for (int r = 0; r < 4; ++r) O[j][r] = 0.0f;
    float m_a = -1e30f, m_b = -1e30f, l_a = 0.0f, l_b = 0.0f;

    const int qa_row = w * 16 + ((lane >> 3) & 1) * 8 + (lane & 7);
    const int qa_cb  = (lane >> 4) * 16;
    const int kb_row = ((lane >> 4) & 1) * 8 + (lane & 7);
    const int kb_cb  = ((lane >> 3) & 1) * 16;
    const int vt_row = ((lane >> 3) & 1) * 8 + (lane & 7);
    const int vt_cb  = (lane >> 4) * 16;
    const int p_row = w * 16 + ((lane >> 3) & 1) * 8 + (lane & 7);
    const int p_ch  = (lane >> 4);

    for (int kt = 0; kt < nkt; ++kt) {
        CP_WAIT1();
        __syncthreads();
        const uint32_t st = sb + AT_KV(kt & 1);
        const bool skip = (kt * 64 > q0 + w * 16 + 15);

        if (!skip) {
            float sa[8][4];
#pragma unroll
            for (int j = 0; j < 8; ++j)
#pragma unroll
                for (int r = 0; r < 4; ++r) sa[j][r] = 0.0f;

#pragma unroll
            for (int kk = 0; kk < 8; ++kk) {
                const int cb = kk * 32;
                uint32_t aH[4], aL[4];
                ldsm_x4(aH[0], aH[1], aH[2], aH[3], sb + AT_QH + swz256(qa_row, qa_cb + cb));
                ldsm_x4(aL[0], aL[1], aL[2], aL[3], sb + AT_QL + swz256(qa_row, qa_cb + cb));
#pragma unroll
                for (int g = 0; g < 4; ++g) {
                    uint32_t b[4];
                    ldsm_x4(b[0], b[1], b[2], b[3],
                            st + swz256(g * 16 + kb_row, kb_cb + cb));          // Kh
                    mma16816(sa[2*g],   aH, b);
                    mma16816(sa[2*g+1], aH, b + 2);
                    mma16816(sa[2*g],   aL, b);
                    mma16816(sa[2*g+1], aL, b + 2);
                    ldsm_x4(b[0], b[1], b[2], b[3],
                            st + 16384u + swz256(g * 16 + kb_row, kb_cb + cb)); // Kl
                    mma16816(sa[2*g],   aH, b);
                    mma16816(sa[2*g+1], aH, b + 2);
                }
            }

            if (kt * 64 + 63 > q0 + w * 16) {
                const int colb = kt * 64 + (lane & 3) * 2;
#pragma unroll
                for (int j = 0; j < 8; ++j) {
                    int c0 = colb + j * 8, c1 = c0 + 1;
                    if (c0 > qa) sa[j][0] = -1e30f;
                    if (c1 > qa) sa[j][1] = -1e30f;
                    if (c0 > qb) sa[j][2] = -1e30f;
                    if (c1 > qb) sa[j][3] = -1e30f;
                }
            }

            float mxa = sa[0][0], mxb = sa[0][2];
#pragma unroll
            for (int j = 0; j < 8; ++j) {
                mxa = fmaxf(mxa, fmaxf(sa[j][0], sa[j][1]));
                mxb = fmaxf(mxb, fmaxf(sa[j][2], sa[j][3]));
            }
            mxa = fmaxf(mxa, __shfl_xor_sync(0xffffffffu, mxa, 1));
            mxa = fmaxf(mxa, __shfl_xor_sync(0xffffffffu, mxa, 2));
            mxb = fmaxf(mxb, __shfl_xor_sync(0xffffffffu, mxb, 1));
            mxb = fmaxf(mxb, __shfl_xor_sync(0xffffffffu, mxb, 2));
            float mna = fmaxf(m_a, mxa), mnb = fmaxf(m_b, mxb);
            float alpha_a = exp2s((m_a - mna) * SC);
            float alpha_b = exp2s((m_b - mnb) * SC);
            m_a = mna; m_b = mnb;

            float suma = 0.0f, sumb = 0.0f;
#pragma unroll
            for (int j = 0; j < 8; ++j) {
                sa[j][0] = exp2s((sa[j][0] - mna) * SC);
                sa[j][1] = exp2s((sa[j][1] - mna) * SC);
                sa[j][2] = exp2s((sa[j][2] - mnb) * SC);
                sa[j][3] = exp2s((sa[j][3] - mnb) * SC);
                suma += sa[j][0] + sa[j][1];
                sumb += sa[j][2] + sa[j][3];
            }
            suma += __shfl_xor_sync(0xffffffffu, suma, 1);
            suma += __shfl_xor_sync(0xffffffffu, suma, 2);
            sumb += __shfl_xor_sync(0xffffffffu, sumb, 1);
            sumb += __shfl_xor_sync(0xffffffffu, sumb, 2);
            l_a = l_a * alpha_a + suma;
            l_b = l_b * alpha_b + sumb;
#pragma unroll
            for (int j = 0; j < 16; ++j) {
                O[j][0] *= alpha_a; O[j][1] *= alpha_a;
                O[j][2] *= alpha_b; O[j][3] *= alpha_b;
            }

            const int rB = rA + 8;
            const int wb = (lane & 3) * 4;
#pragma unroll
            for (int j = 0; j < 8; ++j) {
                uint32_t hA = packbf(sa[j][0], sa[j][1]);
                uint32_t hB = packbf(sa[j][2], sa[j][3]);
                float2 fA = __bfloat1622float2(*(__nv_bfloat162*)&hA);
                float2 fB = __bfloat1622float2(*(__nv_bfloat162*)&hB);
                uint32_t lA = packbf(sa[j][0] - fA.x, sa[j][1] - fA.y);
                uint32_t lB = packbf(sa[j][2] - fB.x, sa[j][3] - fB.y);
                *(uint32_t*)(smc + AT_PH + rA*128 + ((j ^ (rA & 7)) * 16) + wb) = hA;
                *(uint32_t*)(smc + AT_PH + rB*128 + ((j ^ (rB & 7)) * 16) + wb) = hB;
                *(uint32_t*)(smc + AT_PL + rA*128 + ((j ^ (rA & 7)) * 16) + wb) = lA;
                *(uint32_t*)(smc + AT_PL + rB*128 + ((j ^ (rB & 7)) * 16) + wb) = lB;
            }
            __syncwarp();

            uint32_t aPh[4][4], aPl[4][4];
#pragma unroll
            for (int k2 = 0; k2 < 4; ++k2) {
                int ch = k2 * 2 + p_ch;
                uint32_t offH = AT_PH + (uint32_t)(p_row*128 + ((ch ^ (p_row & 7)) * 16));
                uint32_t offL = AT_PL + (uint32_t)(p_row*128 + ((ch ^ (p_row & 7)) * 16));
                ldsm_x4(aPh[k2][0], aPh[k2][1], aPh[k2][2], aPh[k2][3], sb + offH);
                ldsm_x4(aPl[k2][0], aPl[k2][1], aPl[k2][2], aPl[k2][3], sb + offL);
            }

#pragma unroll
            for (int g = 0; g < 8; ++g) {
#pragma unroll
                for (int k2 = 0; k2 < 4; ++k2) {
                    uint32_t b[4];
                    ldsm_x4_t(b[0], b[1], b[2], b[3],
                              st + 32768u + swz256(k2 * 16 + vt_row, g * 32 + vt_cb)); // Vh
                    mma16816(O[2*g],   aPh[k2], b);
                    mma16816(O[2*g+1], aPh[k2], b + 2);
                    mma16816(O[2*g],   aPl[k2], b);
                    mma16816(O[2*g+1], aPl[k2], b + 2);
                    ldsm_x4_t(b[0], b[1], b[2], b[3],
                              st + 49152u + swz256(k2 * 16 + vt_row, g * 32 + vt_cb)); // Vl
                    mma16816(O[2*g],   aPh[k2], b);
                    mma16816(O[2*g+1], aPh[k2], b + 2);
                }
            }
        }

        __syncthreads();
        if (kt + 2 < nkt) issue_kv(kt + 2);
        else CP_COMMIT();
    }

    // ---- epilogue: normalize, split to bf16 hi/lo, write ctx [B,S,E] ----
    const int b = bh >> 4, h = bh & 15;
    const float inva = 1.0f / l_a, invb = 1.0f / l_b;
    const size_t base_a = ((size_t)(b * SEQ + qa)) * EMB + h * HD;
    const size_t base_b = ((size_t)(b * SEQ + qb)) * EMB + h * HD;
#pragma unroll
    for (int j = 0; j < 16; ++j) {
        int dcol = j * 8 + (lane & 3) * 2;
        float oa0 = O[j][0] * inva, oa1 = O[j][1] * inva;
        float ob0 = O[j][2] * invb, ob1 = O[j][3] * invb;
        uint32_t ha = packbf(oa0, oa1);
        uint32_t hb = packbf(ob0, ob1);
        float2 fa = __bfloat1622float2(*(__nv_bfloat162*)&ha);
        float2 fb = __bfloat1622float2(*(__nv_bfloat162*)&hb);
        uint32_t la = packbf(oa0 - fa.x, oa1 - fa.y);
        uint32_t lb = packbf(ob0 - fb.x, ob1 - fb.y);
        *(uint32_t*)(Ch + base_a + dcol) = ha;
        *(uint32_t*)(Cl + base_a + dcol) = la;
        *(uint32_t*)(Ch + base_b + dcol) = hb;
        *(uint32_t*)(Cl + base_b + dcol) = lb;
    }
}

// =================================================================================
extern "C" void kernel_launch(void* const* d_in, const int* in_sizes, int n_in,
                              void* d_out, int out_size)
{
    const float* query = (const float*)d_in[0];
    const float* key   = (const float*)d_in[1];
    const float* value = (const float*)d_in[2];
    const float* cosT  = (const float*)d_in[4];
    const float* sinT  = (const float*)d_in[5];
    const float* Wq    = (const float*)d_in[6];
    const float* Wk    = (const float*)d_in[7];
    const float* Wv    = (const float*)d_in[8];
    const float* Wo    = (const float*)d_in[9];

    float *pQ, *pK;
    __nv_bfloat16 *pXh, *pXl, *pWh, *pWl, *pKh, *pKl, *pVh, *pVl, *pCh, *pCl;
    cudaGetSymbolAddress((void**)&pQ,  g_Q);
    cudaGetSymbolAddress((void**)&pK,  g_K);
    cudaGetSymbolAddress((void**)&pXh, g_Xh);
    cudaGetSymbolAddress((void**)&pXl, g_Xl);
    cudaGetSymbolAddress((void**)&pWh, g_Wh);
    cudaGetSymbolAddress((void**)&pWl, g_Wl);
    cudaGetSymbolAddress((void**)&pKh, g_Kh);
    cudaGetSymbolAddress((void**)&pKl, g_Kl);
    cudaGetSymbolAddress((void**)&pVh, g_Vh);
    cudaGetSymbolAddress((void**)&pVl, g_Vl);
    cudaGetSymbolAddress((void**)&pCh, g_Ch);
    cudaGetSymbolAddress((void**)&pCl, g_Cl);

    cudaFuncSetAttribute(gemm_split_mma, cudaFuncAttributeMaxDynamicSharedMemorySize,
                         GEMM_SMEM);
    cudaFuncSetAttribute(attn_tc2, cudaFuncAttributeMaxDynamicSharedMemorySize,
                         AT2_SMEM);

    const int nX4 = MROWS * EMB / 4;
    const int nW4 = EMB * EMB / 4;
    dim3 gGemm(EMB / GBN, MROWS / GBM);   // (8, 32)

    // Q projection -> fp32 [B,H,S,D]
    split_bf16<<<nX4/256, 256>>>(query, pXh, pXl, nX4);
    split_bf16<<<nW4/256, 256>>>(Wq, pWh, pWl, nW4);
    gemm_split_mma<<<gGemm, 512, GEMM_SMEM>>>(pXh, pXl, pWh, pWl, pQ, 0, 0, 0);
    // K projection -> fp32 [B,H,S,D]
    split_bf16<<<nX4/256, 256>>>(key, pXh, pXl, nX4);
    split_bf16<<<nW4/256, 256>>>(Wk, pWh, pWl, nW4);
    gemm_split_mma<<<gGemm, 512, GEMM_SMEM>>>(pXh, pXl, pWh, pWl, pK, 0, 0, 0);
    // V projection -> bf16 splits directly (mode 2)
    split_bf16<<<nX4/256, 256>>>(value, pXh, pXl, nX4);
    split_bf16<<<nW4/256, 256>>>(Wv, pWh, pWl, nW4);
    gemm_split_mma<<<gGemm, 512, GEMM_SMEM>>>(pXh, pXl, pWh, pWl, 0, pVh, pVl, 2);

    // fused RoPE + split (Q -> Xh/Xl, K -> Kh/Kl)
    rope_split<<<(64*1024*64)/256, 256>>>(pQ, pK, cosT, sinT, pXh, pXl, pKh, pKl);

    // tensor-core flash attention -> ctx bf16 splits
    attn_tc2<<<dim3(8, 64), 256, AT2_SMEM>>>(pXh, pXl, pKh, pKl, pVh, pVl, pCh, pCl);

    // output projection (consumes ctx splits)
    split_bf16<<<nW4/256, 256>>>(Wo, pWh, pWl, nW4);
    gemm_split_mma<<<gGemm, 512, GEMM_SMEM>>>(pCh, pCl, pWh, pWl, (float*)d_out, 0, 0, 1);
}

// round 9
// speedup vs baseline: 1.4766x; 1.0486x over previous
#include <cuda_runtime.h>
#include <cuda_bf16.h>
#include <math.h>
#include <stdint.h>

#define BATCH 4
#define SEQ   1024
#define EMB   2048
#define NH    16
#define HD    128
#define MROWS (BATCH*SEQ)   /* 4096 */

// ---------------- scratch (device globals; no allocation allowed) ----------------
__device__ float g_Qf[(size_t)MROWS*EMB];     // Q projection fp32 [B,H,S,D]
__device__ float g_Kf[(size_t)MROWS*EMB];     // K projection fp32 [B,H,S,D]
// activation splits: [0]=query->roped Q, [1]=key->roped K, [2]=value->ctx
__device__ __nv_bfloat16 g_AH[3][(size_t)MROWS*EMB];
__device__ __nv_bfloat16 g_AL[3][(size_t)MROWS*EMB];
// weight splits: [0]=Wq [1]=Wk [2]=Wv [3]=Wo
__device__ __nv_bfloat16 g_BH[4][(size_t)EMB*EMB];
__device__ __nv_bfloat16 g_BL[4][(size_t)EMB*EMB];
__device__ __nv_bfloat16 g_Vh[(size_t)MROWS*EMB];   // V splits [B,H,S,D]
__device__ __nv_bfloat16 g_Vl[(size_t)MROWS*EMB];

// ======================= portable PTX helpers (sm_80+) ===========================
__device__ __forceinline__ uint32_t smem_u32(const void* p) {
    uint32_t a;
    asm("{ .reg .u64 t; cvta.to.shared.u64 t, %1; cvt.u32.u64 %0, t; }" : "=r"(a) : "l"(p));
    return a;
}
#define CP_ASYNC16(dst, src) \
    asm volatile("cp.async.cg.shared.global [%0], [%1], 16;" :: "r"(dst), "l"(src) : "memory")
#define CP_COMMIT()   asm volatile("cp.async.commit_group;" ::: "memory")
#define CP_WAIT1()    asm volatile("cp.async.wait_group 1;" ::: "memory")
#define CP_WAIT2()    asm volatile("cp.async.wait_group 2;" ::: "memory")

__device__ __forceinline__ void ldsm_x4(uint32_t& r0, uint32_t& r1, uint32_t& r2,
                                        uint32_t& r3, uint32_t addr) {
    asm volatile("ldmatrix.sync.aligned.m8n8.x4.shared.b16 {%0,%1,%2,%3}, [%4];"
                 : "=r"(r0), "=r"(r1), "=r"(r2), "=r"(r3) : "r"(addr));
}
__device__ __forceinline__ void ldsm_x4_t(uint32_t& r0, uint32_t& r1, uint32_t& r2,
                                          uint32_t& r3, uint32_t addr) {
    asm volatile("ldmatrix.sync.aligned.m8n8.x4.trans.shared.b16 {%0,%1,%2,%3}, [%4];"
                 : "=r"(r0), "=r"(r1), "=r"(r2), "=r"(r3) : "r"(addr));
}
__device__ __forceinline__ void mma16816(float* d, const uint32_t* a, const uint32_t* b) {
    asm volatile("mma.sync.aligned.m16n8k16.row.col.f32.bf16.bf16.f32 "
                 "{%0,%1,%2,%3}, {%4,%5,%6,%7}, {%8,%9}, {%0,%1,%2,%3};"
                 : "+f"(d[0]), "+f"(d[1]), "+f"(d[2]), "+f"(d[3])
                 : "r"(a[0]), "r"(a[1]), "r"(a[2]), "r"(a[3]), "r"(b[0]), "r"(b[1]));
}
__device__ __forceinline__ uint32_t swz64(int row, int colByte) {
    return (uint32_t)(row * 64 + ((((colByte >> 4) ^ (row >> 1)) & 3) * 16));
}
__device__ __forceinline__ uint32_t swz256(int row, int cb) {
    int ch = cb >> 4;
    int sw = (ch & 8) | ((ch ^ row) & 7);
    return (uint32_t)(row * 256 + sw * 16);
}
__device__ __forceinline__ uint32_t packbf(float lo, float hi) {
    __nv_bfloat162 t = __floats2bfloat162_rn(lo, hi);
    return *(uint32_t*)&t;
}
__device__ __forceinline__ float exp2s(float x) {
    x = fmaxf(x, -126.0f);
    int i = __float2int_rn(x);
    float f = x - (float)i;
    float p = 0.00961812911f;
    p = fmaf(p, f, 0.0555041087f);
    p = fmaf(p, f, 0.240226507f);
    p = fmaf(p, f, 0.693147182f);
    p = fmaf(p, f, 1.0f);
    return p * __int_as_float((i + 127) << 23);
}

// ======================= batched split fp32 -> bf16 hi/lo ========================
// blockIdx.y selects one of up to 4 tensors (same element count n4 each).
__global__ __launch_bounds__(256)
void split_batch(const float* __restrict__ a0, const float* __restrict__ a1,
                 const float* __restrict__ a2, const float* __restrict__ a3,
                 __nv_bfloat16* __restrict__ h0, __nv_bfloat16* __restrict__ l0,
                 __nv_bfloat16* __restrict__ h1, __nv_bfloat16* __restrict__ l1,
                 __nv_bfloat16* __restrict__ h2, __nv_bfloat16* __restrict__ l2,
                 __nv_bfloat16* __restrict__ h3, __nv_bfloat16* __restrict__ l3,
                 int n4)
{
    int t = blockIdx.y;
    const float* X = (t == 0) ? a0 : (t == 1) ? a1 : (t == 2) ? a2 : a3;
    __nv_bfloat16* Hi = (t == 0) ? h0 : (t == 1) ? h1 : (t == 2) ? h2 : h3;
    __nv_bfloat16* Lo = (t == 0) ? l0 : (t == 1) ? l1 : (t == 2) ? l2 : l3;

    int i = blockIdx.x * 256 + threadIdx.x;
    if (i >= n4) return;
    float4 v = ((const float4*)X)[i];
    __nv_bfloat16 b0 = __float2bfloat16(v.x);
    __nv_bfloat16 b1 = __float2bfloat16(v.y);
    __nv_bfloat16 b2 = __float2bfloat16(v.z);
    __nv_bfloat16 b3 = __float2bfloat16(v.w);
    __nv_bfloat16 c0 = __float2bfloat16(v.x - __bfloat162float(b0));
    __nv_bfloat16 c1 = __float2bfloat16(v.y - __bfloat162float(b1));
    __nv_bfloat16 c2 = __float2bfloat16(v.z - __bfloat162float(b2));
    __nv_bfloat16 c3 = __float2bfloat16(v.w - __bfloat162float(b3));
    __nv_bfloat162* H2 = (__nv_bfloat162*)Hi;
    __nv_bfloat162* L2 = (__nv_bfloat162*)Lo;
    H2[2*i]   = __nv_bfloat162(b0, b1);
    H2[2*i+1] = __nv_bfloat162(b2, b3);
    L2[2*i]   = __nv_bfloat162(c0, c1);
    L2[2*i+1] = __nv_bfloat162(c2, c3);
}

// ======================= split-bf16 GEMM core (single-sync multistage) ==========
#define GBM 128
#define GBN 256
#define GBK 32
#define OFF_AH 0
#define OFF_AL 8192
#define OFF_BH 16384
#define OFF_BL 32768
#define STAGE_BYTES 49152
#define GSTAGES 4
#define GEMM_SMEM (GSTAGES * STAGE_BYTES)   /* 196608 */

__device__ __forceinline__ void gemm_issue_stage(
    const __nv_bfloat16* __restrict__ Ah, const __nv_bfloat16* __restrict__ Al,
    const __nv_bfloat16* __restrict__ Bh, const __nv_bfloat16* __restrict__ Bl,
    uint32_t sb, int tid, int m0, int n0, int c)
{
    const uint32_t st = sb + (uint32_t)(c % GSTAGES) * STAGE_BYTES;
    const int kc = c * GBK;
#pragma unroll
    for (int u = 0; u < 6; ++u) {
        int f = tid + u * 512;
        uint32_t dst; const __nv_bfloat16* gp;
        if (f < 1024) {
            int rel = f & 511;
            int row = rel >> 2, ch = rel & 3;
            const __nv_bfloat16* base = (f < 512) ? Ah : Al;
            gp  = base + (size_t)(m0 + row) * EMB + kc + ch * 8;
            dst = st + ((f < 512) ? OFF_AH : OFF_AL) + swz64(row, ch * 16);
        } else {
            int rel = (f - 1024) & 1023;
            int row = rel >> 2, ch = rel & 3;
            const __nv_bfloat16* base = (f < 2048) ? Bh : Bl;
            gp  = base + (size_t)(n0 + row) * EMB + kc + ch * 8;
            dst = st + ((f < 2048) ? OFF_BH : OFF_BL) + swz64(row, ch * 16);
        }
        CP_ASYNC16(dst, gp);
    }
    CP_COMMIT();
}

__device__ __forceinline__ void gemm_core(
    const __nv_bfloat16* __restrict__ Ah, const __nv_bfloat16* __restrict__ Al,
    const __nv_bfloat16* __restrict__ Bh, const __nv_bfloat16* __restrict__ Bl,
    uint32_t sb, int tid, int lane, int wid, int m0, int n0,
    float (&acc)[2][8][4])
{
#pragma unroll
    for (int i = 0; i < 2; ++i)
#pragma unroll
        for (int j = 0; j < 8; ++j)
#pragma unroll
            for (int r = 0; r < 4; ++r) acc[i][j][r] = 0.0f;

    const int warp_m = wid & 3;
    const int warp_n = wid >> 2;
    const int a_row = warp_m * 32 + ((lane >> 3) & 1) * 8 + (lane & 7);
    const int a_cb  = (lane >> 4) * 16;
    const int b_row = warp_n * 64 + ((lane >> 4) & 1) * 8 + (lane & 7);
    const int b_cb  = ((lane >> 3) & 1) * 16;

    // prologue: 3 stages in flight
    gemm_issue_stage(Ah, Al, Bh, Bl, sb, tid, m0, n0, 0);
    gemm_issue_stage(Ah, Al, Bh, Bl, sb, tid, m0, n0, 1);
    gemm_issue_stage(Ah, Al, Bh, Bl, sb, tid, m0, n0, 2);

    const int NC = EMB / GBK;   // 64
    for (int c = 0; c < NC; ++c) {
        CP_WAIT2();
        __syncthreads();
        // issue into stage (c+3)%4 == (c-1)%4 (freed by the sync above)
        if (c + 3 < NC) gemm_issue_stage(Ah, Al, Bh, Bl, sb, tid, m0, n0, c + 3);
        else CP_COMMIT();

        const uint32_t st = sb + (uint32_t)(c % GSTAGES) * STAGE_BYTES;
#pragma unroll
        for (int ks = 0; ks < 2; ++ks) {
            const int cb = ks * 32;
            uint32_t a[2][2][4];
#pragma unroll
            for (int i = 0; i < 2; ++i) {
                ldsm_x4(a[0][i][0], a[0][i][1], a[0][i][2], a[0][i][3],
                        st + OFF_AH + swz64(a_row + i * 16, a_cb + cb));
                ldsm_x4(a[1][i][0], a[1][i][1], a[1][i][2], a[1][i][3],
                        st + OFF_AL + swz64(a_row + i * 16, a_cb + cb));
            }
            uint32_t b[8][2];
#pragma unroll
            for (int q = 0; q < 4; ++q)
                ldsm_x4(b[2*q][0], b[2*q][1], b[2*q+1][0], b[2*q+1][1],
                        st + OFF_BH + swz64(b_row + q * 16, b_cb + cb));
#pragma unroll
            for (int i = 0; i < 2; ++i)
#pragma unroll
                for (int j = 0; j < 8; ++j) {
                    mma16816(acc[i][j], a[0][i], b[j]);
                    mma16816(acc[i][j], a[1][i], b[j]);
                }
#pragma unroll
            for (int q = 0; q < 4; ++q)
                ldsm_x4(b[2*q][0], b[2*q][1], b[2*q+1][0], b[2*q+1][1],
                        st + OFF_BL + swz64(b_row + q * 16, b_cb + cb));
#pragma unroll
            for (int i = 0; i < 2; ++i)
#pragma unroll
                for (int j = 0; j < 8; ++j)
                    mma16816(acc[i][j], a[0][i], b[j]);
        }
        __syncthreads();   // all warps done reading stage c%4 before next iter issues into it
    }
}

// ---- batched Q/K/V projection GEMM: blockIdx.z selects projection ----
__global__ __launch_bounds__(512, 1)
void gemm_qkv()
{
    extern __shared__ __align__(128) char smc[];
    const uint32_t sb = smem_u32(smc);
    const int tid = threadIdx.x, lane = tid & 31, wid = tid >> 5;
    const int m0 = blockIdx.y * GBM, n0 = blockIdx.x * GBN;
    const int z = blockIdx.z;

    float acc[2][8][4];
    gemm_core(g_AH[z], g_AL[z], g_BH[z], g_BL[z], sb, tid, lane, wid, m0, n0, acc);

    const int warp_m = wid & 3, warp_n = wid >> 2;
    const int r0q = lane >> 2, c0q = (lane & 3) * 2;
#pragma unroll
    for (int i = 0; i < 2; ++i) {
#pragma unroll
        for (int j = 0; j < 8; ++j) {
            int mrow0 = m0 + warp_m * 32 + i * 16 + r0q;
            int ncol  = n0 + warp_n * 64 + j * 8 + c0q;
            int h = ncol >> 7, dc = ncol & 127;
            int b0 = mrow0 >> 10, s0 = mrow0 & 1023;
            int b1 = (mrow0 + 8) >> 10, s1 = (mrow0 + 8) & 1023;
            size_t o0 = (((size_t)(b0 * NH + h)) * SEQ + s0) * HD + dc;
            size_t o1 = (((size_t)(b1 * NH + h)) * SEQ + s1) * HD + dc;
            if (z == 2) {   // V -> bf16 splits
                uint32_t h0 = packbf(acc[i][j][0], acc[i][j][1]);
                uint32_t h1 = packbf(acc[i][j][2], acc[i][j][3]);
                float2 f0 = __bfloat1622float2(*(__nv_bfloat162*)&h0);
                float2 f1 = __bfloat1622float2(*(__nv_bfloat162*)&h1);
                uint32_t l0 = packbf(acc[i][j][0] - f0.x, acc[i][j][1] - f0.y);
                uint32_t l1 = packbf(acc[i][j][2] - f1.x, acc[i][j][3] - f1.y);
                *(uint32_t*)(g_Vh + o0) = h0;
                *(uint32_t*)(g_Vh + o1) = h1;
                *(uint32_t*)(g_Vl + o0) = l0;
                *(uint32_t*)(g_Vl + o1) = l1;
            } else {
                float* Y = (z == 0) ? g_Qf : g_Kf;
                *(float2*)(Y + o0) = make_float2(acc[i][j][0], acc[i][j][1]);
                *(float2*)(Y + o1) = make_float2(acc[i][j][2], acc[i][j][3]);
            }
        }
    }
}

// ---- output projection GEMM: ctx splits @ Wo^T -> d_out fp32 [M,EMB] ----
__global__ __launch_bounds__(512, 1)
void gemm_out(float* __restrict__ Y)
{
    extern __shared__ __align__(128) char smc[];
    const uint32_t sb = smem_u32(smc);
    const int tid = threadIdx.x, lane = tid & 31, wid = tid >> 5;
    const int m0 = blockIdx.y * GBM, n0 = blockIdx.x * GBN;

    float acc[2][8][4];
    gemm_core(g_AH[2], g_AL[2], g_BH[3], g_BL[3], sb, tid, lane, wid, m0, n0, acc);

    const int warp_m = wid & 3, warp_n = wid >> 2;
    const int r0q = lane >> 2, c0q = (lane & 3) * 2;
#pragma unroll
    for (int i = 0; i < 2; ++i) {
#pragma unroll
        for (int j = 0; j < 8; ++j) {
            int mrow0 = m0 + warp_m * 32 + i * 16 + r0q;
            int ncol  = n0 + warp_n * 64 + j * 8 + c0q;
            *(float2*)(Y + (size_t)mrow0 * EMB + ncol) =
                make_float2(acc[i][j][0], acc[i][j][1]);
            *(float2*)(Y + (size_t)(mrow0 + 8) * EMB + ncol) =
                make_float2(acc[i][j][2], acc[i][j][3]);
        }
    }
}

// =================================================================================
// Fused RoPE + bf16 hi/lo split (unscaled; attn applies scale inside exp2).
// =================================================================================
__global__ __launch_bounds__(256)
void rope_split(const float* __restrict__ cosT, const float* __restrict__ sinT)
{
    int idx = blockIdx.x * 256 + threadIdx.x;
    int d  = idx & 63;
    int s2 = (idx >> 6) & 1023;
    int bh = idx >> 16;
    size_t base = ((size_t)bh * SEQ + s2) * HD;
    float c  = cosT[s2*HD + d];
    float sn = sinT[s2*HD + d];

    float q1 = g_Qf[base + d], q2 = g_Qf[base + d + 64];
    float r1 = q1*c - q2*sn;
    float r2 = q2*c + q1*sn;
    __nv_bfloat16 h1 = __float2bfloat16(r1), h2 = __float2bfloat16(r2);
    g_AH[0][base + d]      = h1;
    g_AL[0][base + d]      = __float2bfloat16(r1 - __bfloat162float(h1));
    g_AH[0][base + d + 64] = h2;
    g_AL[0][base + d + 64] = __float2bfloat16(r2 - __bfloat162float(h2));

    float k1 = g_Kf[base + d], k2 = g_Kf[base + d + 64];
    float t1 = k1*c - k2*sn;
    float t2 = k2*c + k1*sn;
    __nv_bfloat16 g1 = __float2bfloat16(t1), g2 = __float2bfloat16(t2);
    g_AH[1][base + d]      = g1;
    g_AL[1][base + d]      = __float2bfloat16(t1 - __bfloat162float(g1));
    g_AH[1][base + d + 64] = g2;
    g_AL[1][base + d + 64] = __float2bfloat16(t2 - __bfloat162float(g2));
}

// =================================================================================
// Tensor-core flash attention (R7/R8 proven). Writes ctx bf16 splits to g_AH[2]/g_AL[2].
// =================================================================================
#define AT_QH 0u
#define AT_QL 32768u
#define AT_KV(s) (65536u + (uint32_t)(s) * 65536u)
#define AT_PH 196608u
#define AT_PL 212992u
#define AT2_SMEM 229376

__global__ __launch_bounds__(256, 1)
void attn_tc2()
{
    extern __shared__ __align__(128) char smc[];
    const uint32_t sb = smem_u32(smc);
    const int tid = threadIdx.x, lane = tid & 31, w = tid >> 5;
    const int qt = blockIdx.x, bh = blockIdx.y;
    const int q0 = qt * 128;
    const float SC = 0.12751743f;   // log2(e)/sqrt(128)

    {
        const size_t gbase = ((size_t)bh * SEQ + q0) * HD;
#pragma unroll
        for (int u = 0; u < 16; ++u) {
            int f = tid + u * 256;
            int rel = f & 2047;
            int row = rel >> 4, ch = rel & 15;
            const __nv_bfloat16* gp = ((f < 2048) ? g_AH[0] : g_AL[0])
                                      + gbase + (size_t)row * HD + ch * 8;
            uint32_t dst = sb + ((f < 2048) ? AT_QH : AT_QL) + swz256(row, ch * 16);
            CP_ASYNC16(dst, gp);
        }
        CP_COMMIT();
    }

    auto issue_kv = [&](int kt) {
        const uint32_t st = sb + AT_KV(kt & 1);
        const size_t gbase = ((size_t)bh * SEQ + kt * 64) * HD;
#pragma unroll
        for (int u = 0; u < 16; ++u) {
            int f = tid + u * 256;
            int rel = f & 1023;
            int row = rel >> 4, ch = rel & 15;
            int arr = f >> 10;
            const __nv_bfloat16* gb = (arr == 0) ? g_AH[1] : (arr == 1) ? g_AL[1]
                                     : (arr == 2) ? g_Vh : g_Vl;
            const __nv_bfloat16* gp = gb + gbase + (size_t)row * HD + ch * 8;
            uint32_t dst = st + (uint32_t)arr * 16384u + swz256(row, ch * 16);
            CP_ASYNC16(dst, gp);
        }
        CP_COMMIT();
    };

    const int nkt = 2 * qt + 2;
    issue_kv(0);
    if (nkt > 1) issue_kv(1); else CP_COMMIT();

    const int rA = w * 16 + (lane >> 2);
    const int qa = q0 + rA, qb = qa + 8;
    float O[16][4];
#pragma unroll
    for (int j = 0; j < 16; ++j)
#pragma unroll
        for (int r = 0; r < 4; ++r) O[j][r] = 0.0f;
    float m_a = -1e30f, m_b = -1e30f, l_a = 0.0f, l_b = 0.0f;

    const int qa_row = w * 16 + ((lane >> 3) & 1) * 8 + (lane & 7);
    const int qa_cb  = (lane >> 4) * 16;
    const int kb_row = ((lane >> 4) & 1) * 8 + (lane & 7);
    const int kb_cb  = ((lane >> 3) & 1) * 16;
    const int vt_row = ((lane >> 3) & 1) * 8 + (lane & 7);
    const int vt_cb  = (lane >> 4) * 16;
    const int p_row = w * 16 + ((lane >> 3) & 1) * 8 + (lane & 7);
    const int p_ch  = (lane >> 4);

    for (int kt = 0; kt < nkt; ++kt) {
        CP_WAIT1();
        __syncthreads();
        const uint32_t st = sb + AT_KV(kt & 1);
        const bool skip = (kt * 64 > q0 + w * 16 + 15);

        if (!skip) {
            float sa[8][4];
#pragma unroll
            for (int j = 0; j < 8; ++j)
#pragma unroll
                for (int r = 0; r < 4; ++r) sa[j][r] = 0.0f;

#pragma unroll
            for (int kk = 0; kk < 8; ++kk) {
                const int cb = kk * 32;
                uint32_t aH[4], aL[4];
                ldsm_x4(aH[0], aH[1], aH[2], aH[3], sb + AT_QH + swz256(qa_row, qa_cb + cb));
                ldsm_x4(aL[0], aL[1], aL[2], aL[3], sb + AT_QL + swz256(qa_row, qa_cb + cb));
#pragma unroll
                for (int g = 0; g < 4; ++g) {
                    uint32_t b[4];
                    ldsm_x4(b[0], b[1], b[2], b[3],
                            st + swz256(g * 16 + kb_row, kb_cb + cb));          // Kh
                    mma16816(sa[2*g],   aH, b);
                    mma16816(sa[2*g+1], aH, b + 2);
                    mma16816(sa[2*g],   aL, b);
                    mma16816(sa[2*g+1], aL, b + 2);
                    ldsm_x4(b[0], b[1], b[2], b[3],
                            st + 16384u + swz256(g * 16 + kb_row, kb_cb + cb)); // Kl
                    mma16816(sa[2*g],   aH, b);
                    mma16816(sa[2*g+1], aH, b + 2);
                }
            }

            if (kt * 64 + 63 > q0 + w * 16) {
                const int colb = kt * 64 + (lane & 3) * 2;
#pragma unroll
                for (int j = 0; j < 8; ++j) {
                    int c0 = colb + j * 8, c1 = c0 + 1;
                    if (c0 > qa) sa[j][0] = -1e30f;
                    if (c1 > qa) sa[j][1] = -1e30f;
                    if (c0 > qb) sa[j][2] = -1e30f;
                    if (c1 > qb) sa[j][3] = -1e30f;
                }
            }

            float mxa = sa[0][0], mxb = sa[0][2];
#pragma unroll
            for (int j = 0; j < 8; ++j) {
                mxa = fmaxf(mxa, fmaxf(sa[j][0], sa[j][1]));
                mxb = fmaxf(mxb, fmaxf(sa[j][2], sa[j][3]));
            }
            mxa = fmaxf(mxa, __shfl_xor_sync(0xffffffffu, mxa, 1));
            mxa = fmaxf(mxa, __shfl_xor_sync(0xffffffffu, mxa, 2));
            mxb = fmaxf(mxb, __shfl_xor_sync(0xffffffffu, mxb, 1));
            mxb = fmaxf(mxb, __shfl_xor_sync(0xffffffffu, mxb, 2));
            float mna = fmaxf(m_a, mxa), mnb = fmaxf(m_b, mxb);
            float alpha_a = exp2s((m_a - mna) * SC);
            float alpha_b = exp2s((m_b - mnb) * SC);
            m_a = mna; m_b = mnb;

            float suma = 0.0f, sumb = 0.0f;
#pragma unroll
            for (int j = 0; j < 8; ++j) {
                sa[j][0] = exp2s((sa[j][0] - mna) * SC);
                sa[j][1] = exp2s((sa[j][1] - mna) * SC);
                sa[j][2] = exp2s((sa[j][2] - mnb) * SC);
                sa[j][3] = exp2s((sa[j][3] - mnb) * SC);
                suma += sa[j][0] + sa[j][1];
                sumb += sa[j][2] + sa[j][3];
            }
            suma += __shfl_xor_sync(0xffffffffu, suma, 1);
            suma += __shfl_xor_sync(0xffffffffu, suma, 2);
            sumb += __shfl_xor_sync(0xffffffffu, sumb, 1);
            sumb += __shfl_xor_sync(0xffffffffu, sumb, 2);
            l_a = l_a * alpha_a + suma;
            l_b = l_b * alpha_b + sumb;
#pragma unroll
            for (int j = 0; j < 16; ++j) {
                O[j][0] *= alpha_a; O[j][1] *= alpha_a;
                O[j][2] *= alpha_b; O[j][3] *= alpha_b;
            }

            const int rB = rA + 8;
            const int wb = (lane & 3) * 4;
#pragma unroll
            for (int j = 0; j < 8; ++j) {
                uint32_t hA = packbf(sa[j][0], sa[j][1]);
                uint32_t hB = packbf(sa[j][2], sa[j][3]);
                float2 fA = __bfloat1622float2(*(__nv_bfloat162*)&hA);
                float2 fB = __bfloat1622float2(*(__nv_bfloat162*)&hB);
                uint32_t lA = packbf(sa[j][0] - fA.x, sa[j][1] - fA.y);
                uint32_t lB = packbf(sa[j][2] - fB.x, sa[j][3] - fB.y);
                *(uint32_t*)(smc + AT_PH + rA*128 + ((j ^ (rA & 7)) * 16) + wb) = hA;
                *(uint32_t*)(smc + AT_PH + rB*128 + ((j ^ (rB & 7)) * 16) + wb) = hB;
                *(uint32_t*)(smc + AT_PL + rA*128 + ((j ^ (rA & 7)) * 16) + wb) = lA;
                *(uint32_t*)(smc + AT_PL + rB*128 + ((j ^ (rB & 7)) * 16) + wb) = lB;
            }
            __syncwarp();

            uint32_t aPh[4][4], aPl[4][4];
#pragma unroll
            for (int k2 = 0; k2 < 4; ++k2) {
                int ch = k2 * 2 + p_ch;
                uint32_t offH = AT_PH + (uint32_t)(p_row*128 + ((ch ^ (p_row & 7)) * 16));
                uint32_t offL = AT_PL + (uint32_t)(p_row*128 + ((ch ^ (p_row & 7)) * 16));
                ldsm_x4(aPh[k2][0], aPh[k2][1], aPh[k2][2], aPh[k2][3], sb + offH);
                ldsm_x4(aPl[k2][0], aPl[k2][1], aPl[k2][2], aPl[k2][3], sb + offL);
            }

#pragma unroll
            for (int g = 0; g < 8; ++g) {
#pragma unroll
                for (int k2 = 0; k2 < 4; ++k2) {
                    uint32_t b[4];
                    ldsm_x4_t(b[0], b[1], b[2], b[3],
                              st + 32768u + swz256(k2 * 16 + vt_row, g * 32 + vt_cb)); // Vh
                    mma16816(O[2*g],   aPh[k2], b);
                    mma16816(O[2*g+1], aPh[k2], b + 2);
                    mma16816(O[2*g],   aPl[k2], b);
                    mma16816(O[2*g+1], aPl[k2], b + 2);
                    ldsm_x4_t(b[0], b[1], b[2], b[3],
                              st + 49152u + swz256(k2 * 16 + vt_row, g * 32 + vt_cb)); // Vl
                    mma16816(O[2*g],   aPh[k2], b);
                    mma16816(O[2*g+1], aPh[k2], b + 2);
                }
            }
        }

        __syncthreads();
        if (kt + 2 < nkt) issue_kv(kt + 2);
        else CP_COMMIT();
    }

    // ---- epilogue: normalize, split to bf16 hi/lo, write ctx [B,S,E] ----
    const int b = bh >> 4, h = bh & 15;
    const float inva = 1.0f / l_a, invb = 1.0f / l_b;
    const size_t base_a = ((size_t)(b * SEQ + qa)) * EMB + h * HD;
    const size_t base_b = ((size_t)(b * SEQ + qb)) * EMB + h * HD;
#pragma unroll
    for (int j = 0; j < 16; ++j) {
        int dcol = j * 8 + (lane & 3) * 2;
        float oa0 = O[j][0] * inva, oa1 = O[j][1] * inva;
        float ob0 = O[j][2] * invb, ob1 = O[j][3] * invb;
        uint32_t ha = packbf(oa0, oa1);
        uint32_t hb = packbf(ob0, ob1);
        float2 fa = __bfloat1622float2(*(__nv_bfloat162*)&ha);
        float2 fb = __bfloat1622float2(*(__nv_bfloat162*)&hb);
        uint32_t la = packbf(oa0 - fa.x, oa1 - fa.y);
        uint32_t lb = packbf(ob0 - fb.x, ob1 - fb.y);
        *(uint32_t*)(g_AH[2] + base_a + dcol) = ha;
        *(uint32_t*)(g_AL[2] + base_a + dcol) = la;
        *(uint32_t*)(g_AH[2] + base_b + dcol) = hb;
        *(uint32_t*)(g_AL[2] + base_b + dcol) = lb;
    }
}

// =================================================================================
extern "C" void kernel_launch(void* const* d_in, const int* in_sizes, int n_in,
                              void* d_out, int out_size)
{
    const float* query = (const float*)d_in[0];
    const float* key   = (const float*)d_in[1];
    const float* value = (const float*)d_in[2];
    const float* cosT  = (const float*)d_in[4];
    const float* sinT  = (const float*)d_in[5];
    const float* Wq    = (const float*)d_in[6];
    const float* Wk    = (const float*)d_in[7];
    const float* Wv    = (const float*)d_in[8];
    const float* Wo    = (const float*)d_in[9];

    __nv_bfloat16 *pAH0, *pAL0, *pAH1, *pAL1, *pAH2, *pAL2;
    __nv_bfloat16 *pBH0, *pBL0, *pBH1, *pBL1, *pBH2, *pBL2, *pBH3, *pBL3;
    cudaGetSymbolAddress((void**)&pAH0, g_AH);
    cudaGetSymbolAddress((void**)&pAL0, g_AL);
    cudaGetSymbolAddress((void**)&pBH0, g_BH);
    cudaGetSymbolAddress((void**)&pBL0, g_BL);
    const size_t NA = (size_t)MROWS * EMB;
    const size_t NB = (size_t)EMB * EMB;
    pAH1 = pAH0 + NA; pAH2 = pAH0 + 2 * NA;
    pAL1 = pAL0 + NA; pAL2 = pAL0 + 2 * NA;
    pBH1 = pBH0 + NB; pBH2 = pBH0 + 2 * NB; pBH3 = pBH0 + 3 * NB;
    pBL1 = pBL0 + NB; pBL2 = pBL0 + 2 * NB; pBL3 = pBL0 + 3 * NB;

    cudaFuncSetAttribute(gemm_qkv, cudaFuncAttributeMaxDynamicSharedMemorySize, GEMM_SMEM);
    cudaFuncSetAttribute(gemm_out, cudaFuncAttributeMaxDynamicSharedMemorySize, GEMM_SMEM);
    cudaFuncSetAttribute(attn_tc2, cudaFuncAttributeMaxDynamicSharedMemorySize, AT2_SMEM);

    const int nX4 = MROWS * EMB / 4;
    const int nW4 = EMB * EMB / 4;

    // batched input splits: query/key/value -> g_AH/AL[0..2]
    split_batch<<<dim3(nX4 / 256, 3), 256>>>(
        query, key, value, query,
        pAH0, pAL0, pAH1, pAL1, pAH2, pAL2, pAH0, pAL0, nX4);
    // batched weight splits: Wq/Wk/Wv/Wo -> g_BH/BL[0..3]
    split_batch<<<dim3(nW4 / 256, 4), 256>>>(
        Wq, Wk, Wv, Wo,
        pBH0, pBL0, pBH1, pBL1, pBH2, pBL2, pBH3, pBL3, nW4);

    // batched Q/K/V projections (z = 0,1,2)
    gemm_qkv<<<dim3(EMB / GBN, MROWS / GBM, 3), 512, GEMM_SMEM>>>();

    // fused RoPE + split (Q -> g_AH/AL[0], K -> g_AH/AL[1])
    rope_split<<<(64*1024*64)/256, 256>>>(cosT, sinT);

    // tensor-core flash attention -> ctx splits in g_AH/AL[2]
    attn_tc2<<<dim3(8, 64), 256, AT2_SMEM>>>();

    // output projection
    gemm_out<<<dim3(EMB / GBN, MROWS / GBM), 512, GEMM_SMEM>>>((float*)d_out);
}

// round 10
// speedup vs baseline: 1.5066x; 1.0203x over previous
#include <cuda_runtime.h>
#include <cuda_bf16.h>
#include <math.h>
#include <stdint.h>

#define BATCH 4
#define SEQ   1024
#define EMB   2048
#define NH    16
#define HD    128
#define MROWS (BATCH*SEQ)   /* 4096 */

// ---------------- scratch (device globals; no allocation allowed) ----------------
__device__ float g_Qf[(size_t)MROWS*EMB];     // Q projection fp32 [B,H,S,D]
__device__ float g_Kf[(size_t)MROWS*EMB];     // K projection fp32 [B,H,S,D]
// activation splits: [0]=query->roped Q, [1]=key->roped K, [2]=value->ctx
__device__ __nv_bfloat16 g_AH[3][(size_t)MROWS*EMB];
__device__ __nv_bfloat16 g_AL[3][(size_t)MROWS*EMB];
// weight splits: [0]=Wq [1]=Wk [2]=Wv [3]=Wo
__device__ __nv_bfloat16 g_BH[4][(size_t)EMB*EMB];
__device__ __nv_bfloat16 g_BL[4][(size_t)EMB*EMB];
__device__ __nv_bfloat16 g_Vh[(size_t)MROWS*EMB];   // V splits [B,H,S,D]
__device__ __nv_bfloat16 g_Vl[(size_t)MROWS*EMB];

// ======================= portable PTX helpers (sm_80+) ===========================
__device__ __forceinline__ uint32_t smem_u32(const void* p) {
    uint32_t a;
    asm("{ .reg .u64 t; cvta.to.shared.u64 t, %1; cvt.u32.u64 %0, t; }" : "=r"(a) : "l"(p));
    return a;
}
#define CP_ASYNC16(dst, src) \
    asm volatile("cp.async.cg.shared.global [%0], [%1], 16;" :: "r"(dst), "l"(src) : "memory")
#define CP_COMMIT()   asm volatile("cp.async.commit_group;" ::: "memory")
#define CP_WAIT1()    asm volatile("cp.async.wait_group 1;" ::: "memory")
#define CP_WAIT2()    asm volatile("cp.async.wait_group 2;" ::: "memory")

__device__ __forceinline__ void ldsm_x4(uint32_t& r0, uint32_t& r1, uint32_t& r2,
                                        uint32_t& r3, uint32_t addr) {
    asm volatile("ldmatrix.sync.aligned.m8n8.x4.shared.b16 {%0,%1,%2,%3}, [%4];"
                 : "=r"(r0), "=r"(r1), "=r"(r2), "=r"(r3) : "r"(addr));
}
__device__ __forceinline__ void ldsm_x4_t(uint32_t& r0, uint32_t& r1, uint32_t& r2,
                                          uint32_t& r3, uint32_t addr) {
    asm volatile("ldmatrix.sync.aligned.m8n8.x4.trans.shared.b16 {%0,%1,%2,%3}, [%4];"
                 : "=r"(r0), "=r"(r1), "=r"(r2), "=r"(r3) : "r"(addr));
}
__device__ __forceinline__ void mma16816(float* d, const uint32_t* a, const uint32_t* b) {
    asm volatile("mma.sync.aligned.m16n8k16.row.col.f32.bf16.bf16.f32 "
                 "{%0,%1,%2,%3}, {%4,%5,%6,%7}, {%8,%9}, {%0,%1,%2,%3};"
                 : "+f"(d[0]), "+f"(d[1]), "+f"(d[2]), "+f"(d[3])
                 : "r"(a[0]), "r"(a[1]), "r"(a[2]), "r"(a[3]), "r"(b[0]), "r"(b[1]));
}
__device__ __forceinline__ uint32_t swz64(int row, int colByte) {
    return (uint32_t)(row * 64 + ((((colByte >> 4) ^ (row >> 1)) & 3) * 16));
}
__device__ __forceinline__ uint32_t swz256(int row, int cb) {
    int ch = cb >> 4;
    int sw = (ch & 8) | ((ch ^ row) & 7);
    return (uint32_t)(row * 256 + sw * 16);
}
__device__ __forceinline__ uint32_t packbf(float lo, float hi) {
    __nv_bfloat162 t = __floats2bfloat162_rn(lo, hi);
    return *(uint32_t*)&t;
}
__device__ __forceinline__ float exp2s(float x) {
    x = fmaxf(x, -126.0f);
    int i = __float2int_rn(x);
    float f = x - (float)i;
    float p = 0.00961812911f;
    p = fmaf(p, f, 0.0555041087f);
    p = fmaf(p, f, 0.240226507f);
    p = fmaf(p, f, 0.693147182f);
    p = fmaf(p, f, 1.0f);
    return p * __int_as_float((i + 127) << 23);
}

// ======================= batched split fp32 -> bf16 hi/lo ========================
__global__ __launch_bounds__(256)
void split_batch(const float* __restrict__ a0, const float* __restrict__ a1,
                 const float* __restrict__ a2, const float* __restrict__ a3,
                 __nv_bfloat16* __restrict__ h0, __nv_bfloat16* __restrict__ l0,
                 __nv_bfloat16* __restrict__ h1, __nv_bfloat16* __restrict__ l1,
                 __nv_bfloat16* __restrict__ h2, __nv_bfloat16* __restrict__ l2,
                 __nv_bfloat16* __restrict__ h3, __nv_bfloat16* __restrict__ l3,
                 int n4)
{
    int t = blockIdx.y;
    const float* X = (t == 0) ? a0 : (t == 1) ? a1 : (t == 2) ? a2 : a3;
    __nv_bfloat16* Hi = (t == 0) ? h0 : (t == 1) ? h1 : (t == 2) ? h2 : h3;
    __nv_bfloat16* Lo = (t == 0) ? l0 : (t == 1) ? l1 : (t == 2) ? l2 : l3;

    int i = blockIdx.x * 256 + threadIdx.x;
    if (i >= n4) return;
    float4 v = ((const float4*)X)[i];
    __nv_bfloat16 b0 = __float2bfloat16(v.x);
    __nv_bfloat16 b1 = __float2bfloat16(v.y);
    __nv_bfloat16 b2 = __float2bfloat16(v.z);
    __nv_bfloat16 b3 = __float2bfloat16(v.w);
    __nv_bfloat16 c0 = __float2bfloat16(v.x - __bfloat162float(b0));
    __nv_bfloat16 c1 = __float2bfloat16(v.y - __bfloat162float(b1));
    __nv_bfloat16 c2 = __float2bfloat16(v.z - __bfloat162float(b2));
    __nv_bfloat16 c3 = __float2bfloat16(v.w - __bfloat162float(b3));
    __nv_bfloat162* H2 = (__nv_bfloat162*)Hi;
    __nv_bfloat162* L2 = (__nv_bfloat162*)Lo;
    H2[2*i]   = __nv_bfloat162(b0, b1);
    H2[2*i+1] = __nv_bfloat162(b2, b3);
    L2[2*i]   = __nv_bfloat162(c0, c1);
    L2[2*i+1] = __nv_bfloat162(c2, c3);
}

// ======================= split-bf16 GEMM core (one sync per chunk) ==============
#define GBM 128
#define GBN 256
#define GBK 32
#define OFF_AH 0
#define OFF_AL 8192
#define OFF_BH 16384
#define OFF_BL 32768
#define STAGE_BYTES 49152
#define GSTAGES 4
#define GEMM_SMEM (GSTAGES * STAGE_BYTES)   /* 196608 */

__device__ __forceinline__ void gemm_issue_stage(
    const __nv_bfloat16* __restrict__ Ah, const __nv_bfloat16* __restrict__ Al,
    const __nv_bfloat16* __restrict__ Bh, const __nv_bfloat16* __restrict__ Bl,
    uint32_t sb, int tid, int m0, int n0, int c)
{
    const uint32_t st = sb + (uint32_t)(c % GSTAGES) * STAGE_BYTES;
    const int kc = c * GBK;
#pragma unroll
    for (int u = 0; u < 6; ++u) {
        int f = tid + u * 512;
        uint32_t dst; const __nv_bfloat16* gp;
        if (f < 1024) {
            int rel = f & 511;
            int row = rel >> 2, ch = rel & 3;
            const __nv_bfloat16* base = (f < 512) ? Ah : Al;
            gp  = base + (size_t)(m0 + row) * EMB + kc + ch * 8;
            dst = st + ((f < 512) ? OFF_AH : OFF_AL) + swz64(row, ch * 16);
        } else {
            int rel = (f - 1024) & 1023;
            int row = rel >> 2, ch = rel & 3;
            const __nv_bfloat16* base = (f < 2048) ? Bh : Bl;
            gp  = base + (size_t)(n0 + row) * EMB + kc + ch * 8;
            dst = st + ((f < 2048) ? OFF_BH : OFF_BL) + swz64(row, ch * 16);
        }
        CP_ASYNC16(dst, gp);
    }
    CP_COMMIT();
}

__device__ __forceinline__ void gemm_core(
    const __nv_bfloat16* __restrict__ Ah, const __nv_bfloat16* __restrict__ Al,
    const __nv_bfloat16* __restrict__ Bh, const __nv_bfloat16* __restrict__ Bl,
    uint32_t sb, int tid, int lane, int wid, int m0, int n0,
    float (&acc)[2][8][4])
{
#pragma unroll
    for (int i = 0; i < 2; ++i)
#pragma unroll
        for (int j = 0; j < 8; ++j)
#pragma unroll
            for (int r = 0; r < 4; ++r) acc[i][j][r] = 0.0f;

    const int warp_m = wid & 3;
    const int warp_n = wid >> 2;
    const int a_row = warp_m * 32 + ((lane >> 3) & 1) * 8 + (lane & 7);
    const int a_cb  = (lane >> 4) * 16;
    const int b_row = warp_n * 64 + ((lane >> 4) & 1) * 8 + (lane & 7);
    const int b_cb  = ((lane >> 3) & 1) * 16;

    gemm_issue_stage(Ah, Al, Bh, Bl, sb, tid, m0, n0, 0);
    gemm_issue_stage(Ah, Al, Bh, Bl, sb, tid, m0, n0, 1);
    gemm_issue_stage(Ah, Al, Bh, Bl, sb, tid, m0, n0, 2);

    const int NC = EMB / GBK;   // 64
    for (int c = 0; c < NC; ++c) {
        CP_WAIT2();
        __syncthreads();   // stage c fully written AND all warps done reading stage (c-1)
        if (c + 3 < NC) gemm_issue_stage(Ah, Al, Bh, Bl, sb, tid, m0, n0, c + 3);
        else CP_COMMIT();

        const uint32_t st = sb + (uint32_t)(c % GSTAGES) * STAGE_BYTES;
#pragma unroll
        for (int ks = 0; ks < 2; ++ks) {
            const int cb = ks * 32;
            uint32_t a[2][2][4];
#pragma unroll
            for (int i = 0; i < 2; ++i) {
                ldsm_x4(a[0][i][0], a[0][i][1], a[0][i][2], a[0][i][3],
                        st + OFF_AH + swz64(a_row + i * 16, a_cb + cb));
                ldsm_x4(a[1][i][0], a[1][i][1], a[1][i][2], a[1][i][3],
                        st + OFF_AL + swz64(a_row + i * 16, a_cb + cb));
            }
            uint32_t b[8][2];
#pragma unroll
            for (int q = 0; q < 4; ++q)
                ldsm_x4(b[2*q][0], b[2*q][1], b[2*q+1][0], b[2*q+1][1],
                        st + OFF_BH + swz64(b_row + q * 16, b_cb + cb));
#pragma unroll
            for (int i = 0; i < 2; ++i)
#pragma unroll
                for (int j = 0; j < 8; ++j) {
                    mma16816(acc[i][j], a[0][i], b[j]);
                    mma16816(acc[i][j], a[1][i], b[j]);
                }
#pragma unroll
            for (int q = 0; q < 4; ++q)
                ldsm_x4(b[2*q][0], b[2*q][1], b[2*q+1][0], b[2*q+1][1],
                        st + OFF_BL + swz64(b_row + q * 16, b_cb + cb));
#pragma unroll
            for (int i = 0; i < 2; ++i)
#pragma unroll
                for (int j = 0; j < 8; ++j)
                    mma16816(acc[i][j], a[0][i], b[j]);
        }
        // no trailing sync: next iteration's leading sync provides the WAR guard
    }
}

// ---- batched Q/K/V projection GEMM: blockIdx.z selects projection ----
__global__ __launch_bounds__(512, 1)
void gemm_qkv()
{
    extern __shared__ __align__(128) char smc[];
    const uint32_t sb = smem_u32(smc);
    const int tid = threadIdx.x, lane = tid & 31, wid = tid >> 5;
    const int m0 = blockIdx.y * GBM, n0 = blockIdx.x * GBN;
    const int z = blockIdx.z;

    float acc[2][8][4];
    gemm_core(g_AH[z], g_AL[z], g_BH[z], g_BL[z], sb, tid, lane, wid, m0, n0, acc);

    const int warp_m = wid & 3, warp_n = wid >> 2;
    const int r0q = lane >> 2, c0q = (lane & 3) * 2;
#pragma unroll
    for (int i = 0; i < 2; ++i) {
#pragma unroll
        for (int j = 0; j < 8; ++j) {
            int mrow0 = m0 + warp_m * 32 + i * 16 + r0q;
            int ncol  = n0 + warp_n * 64 + j * 8 + c0q;
            int h = ncol >> 7, dc = ncol & 127;
            int b0 = mrow0 >> 10, s0 = mrow0 & 1023;
            int b1 = (mrow0 + 8) >> 10, s1 = (mrow0 + 8) & 1023;
            size_t o0 = (((size_t)(b0 * NH + h)) * SEQ + s0) * HD + dc;
            size_t o1 = (((size_t)(b1 * NH + h)) * SEQ + s1) * HD + dc;
            if (z == 2) {   // V -> bf16 splits
                uint32_t h0 = packbf(acc[i][j][0], acc[i][j][1]);
                uint32_t h1 = packbf(acc[i][j][2], acc[i][j][3]);
                float2 f0 = __bfloat1622float2(*(__nv_bfloat162*)&h0);
                float2 f1 = __bfloat1622float2(*(__nv_bfloat162*)&h1);
                uint32_t l0 = packbf(acc[i][j][0] - f0.x, acc[i][j][1] - f0.y);
                uint32_t l1 = packbf(acc[i][j][2] - f1.x, acc[i][j][3] - f1.y);
                *(uint32_t*)(g_Vh + o0) = h0;
                *(uint32_t*)(g_Vh + o1) = h1;
                *(uint32_t*)(g_Vl + o0) = l0;
                *(uint32_t*)(g_Vl + o1) = l1;
            } else {
                float* Y = (z == 0) ? g_Qf : g_Kf;
                *(float2*)(Y + o0) = make_float2(acc[i][j][0], acc[i][j][1]);
                *(float2*)(Y + o1) = make_float2(acc[i][j][2], acc[i][j][3]);
            }
        }
    }
}

// ---- output projection GEMM ----
__global__ __launch_bounds__(512, 1)
void gemm_out(float* __restrict__ Y)
{
    extern __shared__ __align__(128) char smc[];
    const uint32_t sb = smem_u32(smc);
    const int tid = threadIdx.x, lane = tid & 31, wid = tid >> 5;
    const int m0 = blockIdx.y * GBM, n0 = blockIdx.x * GBN;

    float acc[2][8][4];
    gemm_core(g_AH[2], g_AL[2], g_BH[3], g_BL[3], sb, tid, lane, wid, m0, n0, acc);

    const int warp_m = wid & 3, warp_n = wid >> 2;
    const int r0q = lane >> 2, c0q = (lane & 3) * 2;
#pragma unroll
    for (int i = 0; i < 2; ++i) {
#pragma unroll
        for (int j = 0; j < 8; ++j) {
            int mrow0 = m0 + warp_m * 32 + i * 16 + r0q;
            int ncol  = n0 + warp_n * 64 + j * 8 + c0q;
            *(float2*)(Y + (size_t)mrow0 * EMB + ncol) =
                make_float2(acc[i][j][0], acc[i][j][1]);
            *(float2*)(Y + (size_t)(mrow0 + 8) * EMB + ncol) =
                make_float2(acc[i][j][2], acc[i][j][3]);
        }
    }
}

// =================================================================================
// Fused RoPE + bf16 hi/lo split, float2-vectorized (2 d-values per thread).
// =================================================================================
__global__ __launch_bounds__(256)
void rope_split(const float* __restrict__ cosT, const float* __restrict__ sinT)
{
    int idx = blockIdx.x * 256 + threadIdx.x;    // total BH*S*32
    int f  = idx & 31;            // 32 threads per (bh,s2); d0 = 2f
    int s2 = (idx >> 5) & 1023;
    int bh = idx >> 15;
    int d0 = f * 2;
    size_t base = ((size_t)bh * SEQ + s2) * HD;
    float2 c  = *(const float2*)(cosT + s2*HD + d0);
    float2 sn = *(const float2*)(sinT + s2*HD + d0);

    float2 q1 = *(const float2*)(g_Qf + base + d0);
    float2 q2 = *(const float2*)(g_Qf + base + d0 + 64);
    float r1x = q1.x*c.x - q2.x*sn.x, r1y = q1.y*c.y - q2.y*sn.y;
    float r2x = q2.x*c.x + q1.x*sn.x, r2y = q2.y*c.y + q1.y*sn.y;
    uint32_t h1 = packbf(r1x, r1y), h2 = packbf(r2x, r2y);
    float2 f1 = __bfloat1622float2(*(__nv_bfloat162*)&h1);
    float2 f2 = __bfloat1622float2(*(__nv_bfloat162*)&h2);
    *(uint32_t*)(g_AH[0] + base + d0)      = h1;
    *(uint32_t*)(g_AL[0] + base + d0)      = packbf(r1x - f1.x, r1y - f1.y);
    *(uint32_t*)(g_AH[0] + base + d0 + 64) = h2;
    *(uint32_t*)(g_AL[0] + base + d0 + 64) = packbf(r2x - f2.x, r2y - f2.y);

    float2 k1 = *(const float2*)(g_Kf + base + d0);
    float2 k2 = *(const float2*)(g_Kf + base + d0 + 64);
    float t1x = k1.x*c.x - k2.x*sn.x, t1y = k1.y*c.y - k2.y*sn.y;
    float t2x = k2.x*c.x + k1.x*sn.x, t2y = k2.y*c.y + k1.y*sn.y;
    uint32_t g1 = packbf(t1x, t1y), g2 = packbf(t2x, t2y);
    float2 e1 = __bfloat1622float2(*(__nv_bfloat162*)&g1);
    float2 e2 = __bfloat1622float2(*(__nv_bfloat162*)&g2);
    *(uint32_t*)(g_AH[1] + base + d0)      = g1;
    *(uint32_t*)(g_AL[1] + base + d0)      = packbf(t1x - e1.x, t1y - e1.y);
    *(uint32_t*)(g_AH[1] + base + d0 + 64) = g2;
    *(uint32_t*)(g_AL[1] + base + d0 + 64) = packbf(t2x - e2.x, t2y - e2.y);
}

// =================================================================================
// Tensor-core flash attention (R7-R9 proven). qt remapped descending (big first).
// =================================================================================
#define AT_QH 0u
#define AT_QL 32768u
#define AT_KV(s) (65536u + (uint32_t)(s) * 65536u)
#define AT_PH 196608u
#define AT_PL 212992u
#define AT2_SMEM 229376

__global__ __launch_bounds__(256, 1)
void attn_tc2()
{
    extern __shared__ __align__(128) char smc[];
    const uint32_t sb = smem_u32(smc);
    const int tid = threadIdx.x, lane = tid & 31, w = tid >> 5;
    const int qt = 7 - blockIdx.x;          // heaviest tiles first
    const int bh = blockIdx.y;
    const int q0 = qt * 128;
    const float SC = 0.12751743f;   // log2(e)/sqrt(128)

    {
        const size_t gbase = ((size_t)bh * SEQ + q0) * HD;
#pragma unroll
        for (int u = 0; u < 16; ++u) {
            int f = tid + u * 256;
            int rel = f & 2047;
            int row = rel >> 4, ch = rel & 15;
            const __nv_bfloat16* gp = ((f < 2048) ? g_AH[0] : g_AL[0])
                                      + gbase + (size_t)row * HD + ch * 8;
            uint32_t dst = sb + ((f < 2048) ? AT_QH : AT_QL) + swz256(row, ch * 16);
            CP_ASYNC16(dst, gp);
        }
        CP_COMMIT();
    }

    auto issue_kv = [&](int kt) {
        const uint32_t st = sb + AT_KV(kt & 1);
        const size_t gbase = ((size_t)bh * SEQ + kt * 64) * HD;
#pragma unroll
        for (int u = 0; u < 16; ++u) {
            int f = tid + u * 256;
            int rel = f & 1023;
            int row = rel >> 4, ch = rel & 15;
            int arr = f >> 10;
            const __nv_bfloat16* gb = (arr == 0) ? g_AH[1] : (arr == 1) ? g_AL[1]
                                     : (arr == 2) ? g_Vh : g_Vl;
            const __nv_bfloat16* gp = gb + gbase + (size_t)row * HD + ch * 8;
            uint32_t dst = st + (uint32_t)arr * 16384u + swz256(row, ch * 16);
            CP_ASYNC16(dst, gp);
        }
        CP_COMMIT();
    };

    const int nkt = 2 * qt + 2;
    issue_kv(0);
    if (nkt > 1) issue_kv(1); else CP_COMMIT();

    const int rA = w * 16 + (lane >> 2);
    const int qa = q0 + rA, qb = qa + 8;
    float O[16][4];
#pragma unroll
    for (int j = 0; j < 16; ++j)
#pragma unroll
        for (int r = 0; r < 4; ++r) O[j][r] = 0.0f;
    float m_a = -1e30f, m_b = -1e30f, l_a = 0.0f, l_b = 0.0f;

    const int qa_row = w * 16 + ((lane >> 3) & 1) * 8 + (lane & 7);
    const int qa_cb  = (lane >> 4) * 16;
    const int kb_row = ((lane >> 4) & 1) * 8 + (lane & 7);
    const int kb_cb  = ((lane >> 3) & 1) * 16;
    const int vt_row = ((lane >> 3) & 1) * 8 + (lane & 7);
    const int vt_cb  = (lane >> 4) * 16;
    const int p_row = w * 16 + ((lane >> 3) & 1) * 8 + (lane & 7);
    const int p_ch  = (lane >> 4);

    for (int kt = 0; kt < nkt; ++kt) {
        CP_WAIT1();
        __syncthreads();
        const uint32_t st = sb + AT_KV(kt & 1);
        const bool skip = (kt * 64 > q0 + w * 16 + 15);

        if (!skip) {
            float sa[8][4];
#pragma unroll
            for (int j = 0; j < 8; ++j)
#pragma unroll
                for (int r = 0; r < 4; ++r) sa[j][r] = 0.0f;

#pragma unroll
            for (int kk = 0; kk < 8; ++kk) {
                const int cb = kk * 32;
                uint32_t aH[4], aL[4];
                ldsm_x4(aH[0], aH[1], aH[2], aH[3], sb + AT_QH + swz256(qa_row, qa_cb + cb));
                ldsm_x4(aL[0], aL[1], aL[2], aL[3], sb + AT_QL + swz256(qa_row, qa_cb + cb));
#pragma unroll
                for (int g = 0; g < 4; ++g) {
                    uint32_t b[4];
                    ldsm_x4(b[0], b[1], b[2], b[3],
                            st + swz256(g * 16 + kb_row, kb_cb + cb));          // Kh
                    mma16816(sa[2*g],   aH, b);
                    mma16816(sa[2*g+1], aH, b + 2);
                    mma16816(sa[2*g],   aL, b);
                    mma16816(sa[2*g+1], aL, b + 2);
                    ldsm_x4(b[0], b[1], b[2], b[3],
                            st + 16384u + swz256(g * 16 + kb_row, kb_cb + cb)); // Kl
                    mma16816(sa[2*g],   aH, b);
                    mma16816(sa[2*g+1], aH, b + 2);
                }
            }

            if (kt * 64 + 63 > q0 + w * 16) {
                const int colb = kt * 64 + (lane & 3) * 2;
#pragma unroll
                for (int j = 0; j < 8; ++j) {
                    int c0 = colb + j * 8, c1 = c0 + 1;
                    if (c0 > qa) sa[j][0] = -1e30f;
                    if (c1 > qa) sa[j][1] = -1e30f;
                    if (c0 > qb) sa[j][2] = -1e30f;
                    if (c1 > qb) sa[j][3] = -1e30f;
                }
            }

            float mxa = sa[0][0], mxb = sa[0][2];
#pragma unroll
            for (int j = 0; j < 8; ++j) {
                mxa = fmaxf(mxa, fmaxf(sa[j][0], sa[j][1]));
                mxb = fmaxf(mxb, fmaxf(sa[j][2], sa[j][3]));
            }
            mxa = fmaxf(mxa, __shfl_xor_sync(0xffffffffu, mxa, 1));
            mxa = fmaxf(mxa, __shfl_xor_sync(0xffffffffu, mxa, 2));
            mxb = fmaxf(mxb, __shfl_xor_sync(0xffffffffu, mxb, 1));
            mxb = fmaxf(mxb, __shfl_xor_sync(0xffffffffu, mxb, 2));
            float mna = fmaxf(m_a, mxa), mnb = fmaxf(m_b, mxb);
            float alpha_a = exp2s((m_a - mna) * SC);
            float alpha_b = exp2s((m_b - mnb) * SC);
            m_a = mna; m_b = mnb;

            float suma = 0.0f, sumb = 0.0f;
#pragma unroll
            for (int j = 0; j < 8; ++j) {
                sa[j][0] = exp2s((sa[j][0] - mna) * SC);
                sa[j][1] = exp2s((sa[j][1] - mna) * SC);
                sa[j][2] = exp2s((sa[j][2] - mnb) * SC);
                sa[j][3] = exp2s((sa[j][3] - mnb) * SC);
                suma += sa[j][0] + sa[j][1];
                sumb += sa[j][2] + sa[j][3];
            }
            suma += __shfl_xor_sync(0xffffffffu, suma, 1);
            suma += __shfl_xor_sync(0xffffffffu, suma, 2);
            sumb += __shfl_xor_sync(0xffffffffu, sumb, 1);
            sumb += __shfl_xor_sync(0xffffffffu, sumb, 2);
            l_a = l_a * alpha_a + suma;
            l_b = l_b * alpha_b + sumb;
#pragma unroll
            for (int j = 0; j < 16; ++j) {
                O[j][0] *= alpha_a; O[j][1] *= alpha_a;
                O[j][2] *= alpha_b; O[j][3] *= alpha_b;
            }

            const int rB = rA + 8;
            const int wb = (lane & 3) * 4;
#pragma unroll
            for (int j = 0; j < 8; ++j) {
                uint32_t hA = packbf(sa[j][0], sa[j][1]);
                uint32_t hB = packbf(sa[j][2], sa[j][3]);
                float2 fA = __bfloat1622float2(*(__nv_bfloat162*)&hA);
                float2 fB = __bfloat1622float2(*(__nv_bfloat162*)&hB);
                uint32_t lA = packbf(sa[j][0] - fA.x, sa[j][1] - fA.y);
                uint32_t lB = packbf(sa[j][2] - fB.x, sa[j][3] - fB.y);
                *(uint32_t*)(smc + AT_PH + rA*128 + ((j ^ (rA & 7)) * 16) + wb) = hA;
                *(uint32_t*)(smc + AT_PH + rB*128 + ((j ^ (rB & 7)) * 16) + wb) = hB;
                *(uint32_t*)(smc + AT_PL + rA*128 + ((j ^ (rA & 7)) * 16) + wb) = lA;
                *(uint32_t*)(smc + AT_PL + rB*128 + ((j ^ (rB & 7)) * 16) + wb) = lB;
            }
            __syncwarp();

            uint32_t aPh[4][4], aPl[4][4];
#pragma unroll
            for (int k2 = 0; k2 < 4; ++k2) {
                int ch = k2 * 2 + p_ch;
                uint32_t offH = AT_PH + (uint32_t)(p_row*128 + ((ch ^ (p_row & 7)) * 16));
                uint32_t offL = AT_PL + (uint32_t)(p_row*128 + ((ch ^ (p_row & 7)) * 16));
                ldsm_x4(aPh[k2][0], aPh[k2][1], aPh[k2][2], aPh[k2][3], sb + offH);
                ldsm_x4(aPl[k2][0], aPl[k2][1], aPl[k2][2], aPl[k2][3], sb + offL);
            }

#pragma unroll
            for (int g = 0; g < 8; ++g) {
#pragma unroll
                for (int k2 = 0; k2 < 4; ++k2) {
                    uint32_t b[4];
                    ldsm_x4_t(b[0], b[1], b[2], b[3],
                              st + 32768u + swz256(k2 * 16 + vt_row, g * 32 + vt_cb)); // Vh
                    mma16816(O[2*g],   aPh[k2], b);
                    mma16816(O[2*g+1], aPh[k2], b + 2);
                    mma16816(O[2*g],   aPl[k2], b);
                    mma16816(O[2*g+1], aPl[k2], b + 2);
                    ldsm_x4_t(b[0], b[1], b[2], b[3],
                              st + 49152u + swz256(k2 * 16 + vt_row, g * 32 + vt_cb)); // Vl
                    mma16816(O[2*g],   aPh[k2], b);
                    mma16816(O[2*g+1], aPh[k2], b + 2);
                }
            }
        }

        __syncthreads();
        if (kt + 2 < nkt) issue_kv(kt + 2);
        else CP_COMMIT();
    }

    const int b = bh >> 4, h = bh & 15;
    const float inva = 1.0f / l_a, invb = 1.0f / l_b;
    const size_t base_a = ((size_t)(b * SEQ + qa)) * EMB + h * HD;
    const size_t base_b = ((size_t)(b * SEQ + qb)) * EMB + h * HD;
#pragma unroll
    for (int j = 0; j < 16; ++j) {
        int dcol = j * 8 + (lane & 3) * 2;
        float oa0 = O[j][0] * inva, oa1 = O[j][1] * inva;
        float ob0 = O[j][2] * invb, ob1 = O[j][3] * invb;
        uint32_t ha = packbf(oa0, oa1);
        uint32_t hb = packbf(ob0, ob1);
        float2 fa = __bfloat1622float2(*(__nv_bfloat162*)&ha);
        float2 fb = __bfloat1622float2(*(__nv_bfloat162*)&hb);
        uint32_t la = packbf(oa0 - fa.x, oa1 - fa.y);
        uint32_t lb = packbf(ob0 - fb.x, ob1 - fb.y);
        *(uint32_t*)(g_AH[2] + base_a + dcol) = ha;
        *(uint32_t*)(g_AL[2] + base_a + dcol) = la;
        *(uint32_t*)(g_AH[2] + base_b + dcol) = hb;
        *(uint32_t*)(g_AL[2] + base_b + dcol) = lb;
    }
}

// =================================================================================
extern "C" void kernel_launch(void* const* d_in, const int* in_sizes, int n_in,
                              void* d_out, int out_size)
{
    const float* query = (const float*)d_in[0];
    const float* key   = (const float*)d_in[1];
    const float* value = (const float*)d_in[2];
    const float* cosT  = (const float*)d_in[4];
    const float* sinT  = (const float*)d_in[5];
    const float* Wq    = (const float*)d_in[6];
    const float* Wk    = (const float*)d_in[7];
    const float* Wv    = (const float*)d_in[8];
    const float* Wo    = (const float*)d_in[9];

    __nv_bfloat16 *pAH0, *pAL0, *pAH1, *pAL1, *pAH2, *pAL2;
    __nv_bfloat16 *pBH0, *pBL0, *pBH1, *pBL1, *pBH2, *pBL2, *pBH3, *pBL3;
    cudaGetSymbolAddress((void**)&pAH0, g_AH);
    cudaGetSymbolAddress((void**)&pAL0, g_AL);
    cudaGetSymbolAddress((void**)&pBH0, g_BH);
    cudaGetSymbolAddress((void**)&pBL0, g_BL);
    const size_t NA = (size_t)MROWS * EMB;
    const size_t NB = (size_t)EMB * EMB;
    pAH1 = pAH0 + NA; pAH2 = pAH0 + 2 * NA;
    pAL1 = pAL0 + NA; pAL2 = pAL0 + 2 * NA;
    pBH1 = pBH0 + NB; pBH2 = pBH0 + 2 * NB; pBH3 = pBH0 + 3 * NB;
    pBL1 = pBL0 + NB; pBL2 = pBL0 + 2 * NB; pBL3 = pBL0 + 3 * NB;

    cudaFuncSetAttribute(gemm_qkv, cudaFuncAttributeMaxDynamicSharedMemorySize, GEMM_SMEM);
    cudaFuncSetAttribute(gemm_out, cudaFuncAttributeMaxDynamicSharedMemorySize, GEMM_SMEM);
    cudaFuncSetAttribute(attn_tc2, cudaFuncAttributeMaxDynamicSharedMemorySize, AT2_SMEM);

    const int nX4 = MROWS * EMB / 4;
    const int nW4 = EMB * EMB / 4;

    split_batch<<<dim3(nX4 / 256, 3), 256>>>(
        query, key, value, query,
        pAH0, pAL0, pAH1, pAL1, pAH2, pAL2, pAH0, pAL0, nX4);
    split_batch<<<dim3(nW4 / 256, 4), 256>>>(
        Wq, Wk, Wv, Wo,
        pBH0, pBL0, pBH1, pBL1, pBH2, pBL2, pBH3, pBL3, nW4);

    gemm_qkv<<<dim3(EMB / GBN, MROWS / GBM, 3), 512, GEMM_SMEM>>>();

    rope_split<<<(64*1024*32)/256, 256>>>(cosT, sinT);

    attn_tc2<<<dim3(8, 64), 256, AT2_SMEM>>>();

    gemm_out<<<dim3(EMB / GBN, MROWS / GBM), 512, GEMM_SMEM>>>((float*)d_out);
}

// round 11
// speedup vs baseline: 1.5391x; 1.0216x over previous
#include <cuda_runtime.h>
#include <cuda_bf16.h>
#include <math.h>
#include <stdint.h>

#define BATCH 4
#define SEQ   1024
#define EMB   2048
#define NH    16
#define HD    128
#define MROWS (BATCH*SEQ)   /* 4096 */

// ---------------- scratch (device globals; no allocation allowed) ----------------
// activation input splits: [0]=query, [1]=key, [2]=value->ctx(later)
__device__ __nv_bfloat16 g_AH[3][(size_t)MROWS*EMB];
__device__ __nv_bfloat16 g_AL[3][(size_t)MROWS*EMB];
// weight splits: [0]=Wq [1]=Wk [2]=Wv [3]=Wo
__device__ __nv_bfloat16 g_BH[4][(size_t)EMB*EMB];
__device__ __nv_bfloat16 g_BL[4][(size_t)EMB*EMB];
// attention operand splits [B,H,S,D] (distinct from g_AH/AL to avoid RAW races
// with the in-kernel rope epilogue)
__device__ __nv_bfloat16 g_QH[(size_t)MROWS*EMB];
__device__ __nv_bfloat16 g_QL[(size_t)MROWS*EMB];
__device__ __nv_bfloat16 g_KH[(size_t)MROWS*EMB];
__device__ __nv_bfloat16 g_KL[(size_t)MROWS*EMB];
__device__ __nv_bfloat16 g_Vh[(size_t)MROWS*EMB];
__device__ __nv_bfloat16 g_Vl[(size_t)MROWS*EMB];

// ======================= portable PTX helpers (sm_80+) ===========================
__device__ __forceinline__ uint32_t smem_u32(const void* p) {
    uint32_t a;
    asm("{ .reg .u64 t; cvta.to.shared.u64 t, %1; cvt.u32.u64 %0, t; }" : "=r"(a) : "l"(p));
    return a;
}
#define CP_ASYNC16(dst, src) \
    asm volatile("cp.async.cg.shared.global [%0], [%1], 16;" :: "r"(dst), "l"(src) : "memory")
#define CP_COMMIT()   asm volatile("cp.async.commit_group;" ::: "memory")
#define CP_WAIT1()    asm volatile("cp.async.wait_group 1;" ::: "memory")
#define CP_WAIT2()    asm volatile("cp.async.wait_group 2;" ::: "memory")

__device__ __forceinline__ void ldsm_x4(uint32_t& r0, uint32_t& r1, uint32_t& r2,
                                        uint32_t& r3, uint32_t addr) {
    asm volatile("ldmatrix.sync.aligned.m8n8.x4.shared.b16 {%0,%1,%2,%3}, [%4];"
                 : "=r"(r0), "=r"(r1), "=r"(r2), "=r"(r3) : "r"(addr));
}
__device__ __forceinline__ void ldsm_x4_t(uint32_t& r0, uint32_t& r1, uint32_t& r2,
                                          uint32_t& r3, uint32_t addr) {
    asm volatile("ldmatrix.sync.aligned.m8n8.x4.trans.shared.b16 {%0,%1,%2,%3}, [%4];"
                 : "=r"(r0), "=r"(r1), "=r"(r2), "=r"(r3) : "r"(addr));
}
__device__ __forceinline__ void mma16816(float* d, const uint32_t* a, const uint32_t* b) {
    asm volatile("mma.sync.aligned.m16n8k16.row.col.f32.bf16.bf16.f32 "
                 "{%0,%1,%2,%3}, {%4,%5,%6,%7}, {%8,%9}, {%0,%1,%2,%3};"
                 : "+f"(d[0]), "+f"(d[1]), "+f"(d[2]), "+f"(d[3])
                 : "r"(a[0]), "r"(a[1]), "r"(a[2]), "r"(a[3]), "r"(b[0]), "r"(b[1]));
}
__device__ __forceinline__ uint32_t swz64(int row, int colByte) {
    return (uint32_t)(row * 64 + ((((colByte >> 4) ^ (row >> 1)) & 3) * 16));
}
__device__ __forceinline__ uint32_t swz256(int row, int cb) {
    int ch = cb >> 4;
    int sw = (ch & 8) | ((ch ^ row) & 7);
    return (uint32_t)(row * 256 + sw * 16);
}
__device__ __forceinline__ uint32_t packbf(float lo, float hi) {
    __nv_bfloat162 t = __floats2bfloat162_rn(lo, hi);
    return *(uint32_t*)&t;
}
__device__ __forceinline__ float exp2s(float x) {
    x = fmaxf(x, -126.0f);
    int i = __float2int_rn(x);
    float f = x - (float)i;
    float p = 0.00961812911f;
    p = fmaf(p, f, 0.0555041087f);
    p = fmaf(p, f, 0.240226507f);
    p = fmaf(p, f, 0.693147182f);
    p = fmaf(p, f, 1.0f);
    return p * __int_as_float((i + 127) << 23);
}

// ======================= batched split fp32 -> bf16 hi/lo ========================
__global__ __launch_bounds__(256)
void split_batch(const float* __restrict__ a0, const float* __restrict__ a1,
                 const float* __restrict__ a2, const float* __restrict__ a3,
                 __nv_bfloat16* __restrict__ h0, __nv_bfloat16* __restrict__ l0,
                 __nv_bfloat16* __restrict__ h1, __nv_bfloat16* __restrict__ l1,
                 __nv_bfloat16* __restrict__ h2, __nv_bfloat16* __restrict__ l2,
                 __nv_bfloat16* __restrict__ h3, __nv_bfloat16* __restrict__ l3,
                 int n4)
{
    int t = blockIdx.y;
    const float* X = (t == 0) ? a0 : (t == 1) ? a1 : (t == 2) ? a2 : a3;
    __nv_bfloat16* Hi = (t == 0) ? h0 : (t == 1) ? h1 : (t == 2) ? h2 : h3;
    __nv_bfloat16* Lo = (t == 0) ? l0 : (t == 1) ? l1 : (t == 2) ? l2 : l3;

    int i = blockIdx.x * 256 + threadIdx.x;
    if (i >= n4) return;
    float4 v = ((const float4*)X)[i];
    __nv_bfloat16 b0 = __float2bfloat16(v.x);
    __nv_bfloat16 b1 = __float2bfloat16(v.y);
    __nv_bfloat16 b2 = __float2bfloat16(v.z);
    __nv_bfloat16 b3 = __float2bfloat16(v.w);
    __nv_bfloat16 c0 = __float2bfloat16(v.x - __bfloat162float(b0));
    __nv_bfloat16 c1 = __float2bfloat16(v.y - __bfloat162float(b1));
    __nv_bfloat16 c2 = __float2bfloat16(v.z - __bfloat162float(b2));
    __nv_bfloat16 c3 = __float2bfloat16(v.w - __bfloat162float(b3));
    __nv_bfloat162* H2 = (__nv_bfloat162*)Hi;
    __nv_bfloat162* L2 = (__nv_bfloat162*)Lo;
    H2[2*i]   = __nv_bfloat162(b0, b1);
    H2[2*i+1] = __nv_bfloat162(b2, b3);
    L2[2*i]   = __nv_bfloat162(c0, c1);
    L2[2*i+1] = __nv_bfloat162(c2, c3);
}

// ======================= split-bf16 GEMM core (one sync per chunk) ==============
#define GBM 128
#define GBN 256
#define GBK 32
#define OFF_AH 0
#define OFF_AL 8192
#define OFF_BH 16384
#define OFF_BL 32768
#define STAGE_BYTES 49152
#define GSTAGES 4
#define GEMM_SMEM (GSTAGES * STAGE_BYTES)   /* 196608 */

__device__ __forceinline__ void gemm_issue_stage(
    const __nv_bfloat16* __restrict__ Ah, const __nv_bfloat16* __restrict__ Al,
    const __nv_bfloat16* __restrict__ Bh, const __nv_bfloat16* __restrict__ Bl,
    uint32_t sb, int tid, int m0, int n0, int c)
{
    const uint32_t st = sb + (uint32_t)(c % GSTAGES) * STAGE_BYTES;
    const int kc = c * GBK;
#pragma unroll
    for (int u = 0; u < 6; ++u) {
        int f = tid + u * 512;
        uint32_t dst; const __nv_bfloat16* gp;
        if (f < 1024) {
            int rel = f & 511;
            int row = rel >> 2, ch = rel & 3;
            const __nv_bfloat16* base = (f < 512) ? Ah : Al;
            gp  = base + (size_t)(m0 + row) * EMB + kc + ch * 8;
            dst = st + ((f < 512) ? OFF_AH : OFF_AL) + swz64(row, ch * 16);
        } else {
            int rel = (f - 1024) & 1023;
            int row = rel >> 2, ch = rel & 3;
            const __nv_bfloat16* base = (f < 2048) ? Bh : Bl;
            gp  = base + (size_t)(n0 + row) * EMB + kc + ch * 8;
            dst = st + ((f < 2048) ? OFF_BH : OFF_BL) + swz64(row, ch * 16);
        }
        CP_ASYNC16(dst, gp);
    }
    CP_COMMIT();
}

__device__ __forceinline__ void gemm_core(
    const __nv_bfloat16* __restrict__ Ah, const __nv_bfloat16* __restrict__ Al,
    const __nv_bfloat16* __restrict__ Bh, const __nv_bfloat16* __restrict__ Bl,
    uint32_t sb, int tid, int lane, int wid, int m0, int n0,
    float (&acc)[2][8][4])
{
#pragma unroll
    for (int i = 0; i < 2; ++i)
#pragma unroll
        for (int j = 0; j < 8; ++j)
#pragma unroll
            for (int r = 0; r < 4; ++r) acc[i][j][r] = 0.0f;

    const int warp_m = wid & 3;
    const int warp_n = wid >> 2;
    const int a_row = warp_m * 32 + ((lane >> 3) & 1) * 8 + (lane & 7);
    const int a_cb  = (lane >> 4) * 16;
    const int b_row = warp_n * 64 + ((lane >> 4) & 1) * 8 + (lane & 7);
    const int b_cb  = ((lane >> 3) & 1) * 16;

    gemm_issue_stage(Ah, Al, Bh, Bl, sb, tid, m0, n0, 0);
    gemm_issue_stage(Ah, Al, Bh, Bl, sb, tid, m0, n0, 1);
    gemm_issue_stage(Ah, Al, Bh, Bl, sb, tid, m0, n0, 2);

    const int NC = EMB / GBK;   // 64
    for (int c = 0; c < NC; ++c) {
        CP_WAIT2();
        __syncthreads();   // stage c fully written AND all warps done reading stage (c-1)
        if (c + 3 < NC) gemm_issue_stage(Ah, Al, Bh, Bl, sb, tid, m0, n0, c + 3);
        else CP_COMMIT();

        const uint32_t st = sb + (uint32_t)(c % GSTAGES) * STAGE_BYTES;
#pragma unroll
        for (int ks = 0; ks < 2; ++ks) {
            const int cb = ks * 32;
            uint32_t a[2][2][4];
#pragma unroll
            for (int i = 0; i < 2; ++i) {
                ldsm_x4(a[0][i][0], a[0][i][1], a[0][i][2], a[0][i][3],
                        st + OFF_AH + swz64(a_row + i * 16, a_cb + cb));
                ldsm_x4(a[1][i][0], a[1][i][1], a[1][i][2], a[1][i][3],
                        st + OFF_AL + swz64(a_row + i * 16, a_cb + cb));
            }
            uint32_t b[8][2];
#pragma unroll
            for (int q = 0; q < 4; ++q)
                ldsm_x4(b[2*q][0], b[2*q][1], b[2*q+1][0], b[2*q+1][1],
                        st + OFF_BH + swz64(b_row + q * 16, b_cb + cb));
#pragma unroll
            for (int i = 0; i < 2; ++i)
#pragma unroll
                for (int j = 0; j < 8; ++j) {
                    mma16816(acc[i][j], a[0][i], b[j]);
                    mma16816(acc[i][j], a[1][i], b[j]);
                }
#pragma unroll
            for (int q = 0; q < 4; ++q)
                ldsm_x4(b[2*q][0], b[2*q][1], b[2*q+1][0], b[2*q+1][1],
                        st + OFF_BL + swz64(b_row + q * 16, b_cb + cb));
#pragma unroll
            for (int i = 0; i < 2; ++i)
#pragma unroll
                for (int j = 0; j < 8; ++j)
                    mma16816(acc[i][j], a[0][i], b[j]);
        }
        // no trailing sync: next iteration's leading sync provides the WAR guard
    }
}

// ---- batched Q/K/V projection GEMM with fused RoPE+split epilogue -------------
// z=0: Q -> rope -> g_QH/QL ; z=1: K -> rope -> g_KH/KL ; z=2: V -> g_Vh/Vl
#define SPAD 260

__global__ __launch_bounds__(512, 1)
void gemm_qkv(const float* __restrict__ cosT, const float* __restrict__ sinT)
{
    extern __shared__ __align__(128) char smc[];
    const uint32_t sb = smem_u32(smc);
    const int tid = threadIdx.x, lane = tid & 31, wid = tid >> 5;
    const int m0 = blockIdx.y * GBM, n0 = blockIdx.x * GBN;
    const int z = blockIdx.z;

    float acc[2][8][4];
    gemm_core(g_AH[z], g_AL[z], g_BH[z], g_BL[z], sb, tid, lane, wid, m0, n0, acc);

    const int warp_m = wid & 3, warp_n = wid >> 2;
    const int r0q = lane >> 2, c0q = (lane & 3) * 2;

    if (z == 2) {
        // V: direct bf16 split scatter [B,H,S,D] (proven path)
#pragma unroll
        for (int i = 0; i < 2; ++i) {
#pragma unroll
            for (int j = 0; j < 8; ++j) {
                int mrow0 = m0 + warp_m * 32 + i * 16 + r0q;
                int ncol  = n0 + warp_n * 64 + j * 8 + c0q;
                int h = ncol >> 7, dc = ncol & 127;
                int b0 = mrow0 >> 10, s0 = mrow0 & 1023;
                int b1 = (mrow0 + 8) >> 10, s1 = (mrow0 + 8) & 1023;
                size_t o0 = (((size_t)(b0 * NH + h)) * SEQ + s0) * HD + dc;
                size_t o1 = (((size_t)(b1 * NH + h)) * SEQ + s1) * HD + dc;
                uint32_t h0 = packbf(acc[i][j][0], acc[i][j][1]);
                uint32_t h1 = packbf(acc[i][j][2], acc[i][j][3]);
                float2 f0 = __bfloat1622float2(*(__nv_bfloat162*)&h0);
                float2 f1 = __bfloat1622float2(*(__nv_bfloat162*)&h1);
                uint32_t l0 = packbf(acc[i][j][0] - f0.x, acc[i][j][1] - f0.y);
                uint32_t l1 = packbf(acc[i][j][2] - f1.x, acc[i][j][3] - f1.y);
                *(uint32_t*)(g_Vh + o0) = h0;
                *(uint32_t*)(g_Vh + o1) = h1;
                *(uint32_t*)(g_Vl + o0) = l0;
                *(uint32_t*)(g_Vl + o1) = l1;
            }
        }
    } else {
        // Q/K: stage fp32 tile in smem, apply RoPE + split, write [B,H,S,D]
        float* stile = (float*)smc;   // [128][SPAD] = 133120 B < GEMM_SMEM
        __syncthreads();              // all warps done with pipeline smem
#pragma unroll
        for (int i = 0; i < 2; ++i) {
#pragma unroll
            for (int j = 0; j < 8; ++j) {
                int lr0 = warp_m * 32 + i * 16 + r0q;
                int lc  = warp_n * 64 + j * 8 + c0q;
                stile[lr0 * SPAD + lc]           = acc[i][j][0];
                stile[lr0 * SPAD + lc + 1]       = acc[i][j][1];
                stile[(lr0 + 8) * SPAD + lc]     = acc[i][j][2];
                stile[(lr0 + 8) * SPAD + lc + 1] = acc[i][j][3];
            }
        }
        __syncthreads();

        __nv_bfloat16* H = (z == 0) ? g_QH : g_KH;
        __nv_bfloat16* L = (z == 0) ? g_QL : g_KL;
#pragma unroll
        for (int it = 0; it < 16; ++it) {
            int slot = tid + it * 512;        // 0..8191 = 2 heads x 128 rows x 32 dpairs
            int t  = slot & 31;
            int lr = (slot >> 5) & 127;
            int hh = slot >> 12;
            int d0 = t * 2;
            int gm = m0 + lr;
            int b  = gm >> 10, s = gm & 1023;
            float2 cc = *(const float2*)(cosT + s * HD + d0);
            float2 ss = *(const float2*)(sinT + s * HD + d0);
            const float* row = stile + lr * SPAD + hh * 128;
            float x1a = row[d0],      x1b = row[d0 + 1];
            float x2a = row[d0 + 64], x2b = row[d0 + 65];
            float r1a = x1a * cc.x - x2a * ss.x, r1b = x1b * cc.y - x2b * ss.y;
            float r2a = x2a * cc.x + x1a * ss.x, r2b = x2b * cc.y + x1b * ss.y;
            uint32_t h1 = packbf(r1a, r1b), h2 = packbf(r2a, r2b);
            float2 f1 = __bfloat1622float2(*(__nv_bfloat162*)&h1);
            float2 f2 = __bfloat1622float2(*(__nv_bfloat162*)&h2);
            uint32_t l1 = packbf(r1a - f1.x, r1b - f1.y);
            uint32_t l2 = packbf(r2a - f2.x, r2b - f2.y);
            int h = (n0 >> 7) + hh;
            size_t o = (((size_t)(b * NH + h)) * SEQ + s) * HD + d0;
            *(uint32_t*)(H + o)      = h1;
            *(uint32_t*)(L + o)      = l1;
            *(uint32_t*)(H + o + 64) = h2;
            *(uint32_t*)(L + o + 64) = l2;
        }
    }
}

// ---- output projection GEMM ----
__global__ __launch_bounds__(512, 1)
void gemm_out(float* __restrict__ Y)
{
    extern __shared__ __align__(128) char smc[];
    const uint32_t sb = smem_u32(smc);
    const int tid = threadIdx.x, lane = tid & 31, wid = tid >> 5;
    const int m0 = blockIdx.y * GBM, n0 = blockIdx.x * GBN;

    float acc[2][8][4];
    gemm_core(g_AH[2], g_AL[2], g_BH[3], g_BL[3], sb, tid, lane, wid, m0, n0, acc);

    const int warp_m = wid & 3, warp_n = wid >> 2;
    const int r0q = lane >> 2, c0q = (lane & 3) * 2;
#pragma unroll
    for (int i = 0; i < 2; ++i) {
#pragma unroll
        for (int j = 0; j < 8; ++j) {
            int mrow0 = m0 + warp_m * 32 + i * 16 + r0q;
            int ncol  = n0 + warp_n * 64 + j * 8 + c0q;
            *(float2*)(Y + (size_t)mrow0 * EMB + ncol) =
                make_float2(acc[i][j][0], acc[i][j][1]);
            *(float2*)(Y + (size_t)(mrow0 + 8) * EMB + ncol) =
                make_float2(acc[i][j][2], acc[i][j][3]);
        }
    }
}

// =================================================================================
// Tensor-core flash attention (R7-R10 proven). Reads g_QH/QL, g_KH/KL, g_Vh/Vl;
// writes ctx bf16 splits to g_AH[2]/g_AL[2]. qt descending (big tiles first).
// =================================================================================
#define AT_QH 0u
#define AT_QL 32768u
#define AT_KV(s) (65536u + (uint32_t)(s) * 65536u)
#define AT_PH 196608u
#define AT_PL 212992u
#define AT2_SMEM 229376

__global__ __launch_bounds__(256, 1)
void attn_tc2()
{
    extern __shared__ __align__(128) char smc[];
    const uint32_t sb = smem_u32(smc);
    const int tid = threadIdx.x, lane = tid & 31, w = tid >> 5;
    const int qt = 7 - blockIdx.x;
    const int bh = blockIdx.y;
    const int q0 = qt * 128;
    const float SC = 0.12751743f;   // log2(e)/sqrt(128)

    {
        const size_t gbase = ((size_t)bh * SEQ + q0) * HD;
#pragma unroll
        for (int u = 0; u < 16; ++u) {
            int f = tid + u * 256;
            int rel = f & 2047;
            int row = rel >> 4, ch = rel & 15;
            const __nv_bfloat16* gp = ((f < 2048) ? g_QH : g_QL)
                                      + gbase + (size_t)row * HD + ch * 8;
            uint32_t dst = sb + ((f < 2048) ? AT_QH : AT_QL) + swz256(row, ch * 16);
            CP_ASYNC16(dst, gp);
        }
        CP_COMMIT();
    }

    auto issue_kv = [&](int kt) {
        const uint32_t st = sb + AT_KV(kt & 1);
        const size_t gbase = ((size_t)bh * SEQ + kt * 64) * HD;
#pragma unroll
        for (int u = 0; u < 16; ++u) {
            int f = tid + u * 256;
            int rel = f & 1023;
            int row = rel >> 4, ch = rel & 15;
            int arr = f >> 10;
            const __nv_bfloat16* gb = (arr == 0) ? g_KH : (arr == 1) ? g_KL
                                     : (arr == 2) ? g_Vh : g_Vl;
            const __nv_bfloat16* gp = gb + gbase + (size_t)row * HD + ch * 8;
            uint32_t dst = st + (uint32_t)arr * 16384u + swz256(row, ch * 16);
            CP_ASYNC16(dst, gp);
        }
        CP_COMMIT();
    };

    const int nkt = 2 * qt + 2;
    issue_kv(0);
    if (nkt > 1) issue_kv(1); else CP_COMMIT();

    const int rA = w * 16 + (lane >> 2);
    const int qa = q0 + rA, qb = qa + 8;
    float O[16][4];
#pragma unroll
    for (int j = 0; j < 16; ++j)
#pragma unroll
        for (int r = 0; r < 4; ++r) O[j][r] = 0.0f;
    float m_a = -1e30f, m_b = -1e30f, l_a = 0.0f, l_b = 0.0f;

    const int qa_row = w * 16 + ((lane >> 3) & 1) * 8 + (lane & 7);
    const int qa_cb  = (lane >> 4) * 16;
    const int kb_row = ((lane >> 4) & 1) * 8 + (lane & 7);
    const int kb_cb  = ((lane >> 3) & 1) * 16;
    const int vt_row = ((lane >> 3) & 1) * 8 + (lane & 7);
    const int vt_cb  = (lane >> 4) * 16;
    const int p_row = w * 16 + ((lane >> 3) & 1) * 8 + (lane & 7);
    const int p_ch  = (lane >> 4);

    for (int kt = 0; kt < nkt; ++kt) {
        CP_WAIT1();
        __syncthreads();
        const uint32_t st = sb + AT_KV(kt & 1);
        const bool skip = (kt * 64 > q0 + w * 16 + 15);

        if (!skip) {
            float sa[8][4];
#pragma unroll
            for (int j = 0; j < 8; ++j)
#pragma unroll
                for (int r = 0; r < 4; ++r) sa[j][r] = 0.0f;

#pragma unroll
            for (int kk = 0; kk < 8; ++kk) {
                const int cb = kk * 32;
                uint32_t aH[4], aL[4];
                ldsm_x4(aH[0], aH[1], aH[2], aH[3], sb + AT_QH + swz256(qa_row, qa_cb + cb));
                ldsm_x4(aL[0], aL[1], aL[2], aL[3], sb + AT_QL + swz256(qa_row, qa_cb + cb));
#pragma unroll
                for (int g = 0; g < 4; ++g) {
                    uint32_t b[4];
                    ldsm_x4(b[0], b[1], b[2], b[3],
                            st + swz256(g * 16 + kb_row, kb_cb + cb));          // Kh
                    mma16816(sa[2*g],   aH, b);
                    mma16816(sa[2*g+1], aH, b + 2);
                    mma16816(sa[2*g],   aL, b);
                    mma16816(sa[2*g+1], aL, b + 2);
                    ldsm_x4(b[0], b[1], b[2], b[3],
                            st + 16384u + swz256(g * 16 + kb_row, kb_cb + cb)); // Kl
                    mma16816(sa[2*g],   aH, b);
                    mma16816(sa[2*g+1], aH, b + 2);
                }
            }

            if (kt * 64 + 63 > q0 + w * 16) {
                const int colb = kt * 64 + (lane & 3) * 2;
#pragma unroll
                for (int j = 0; j < 8; ++j) {
                    int c0 = colb + j * 8, c1 = c0 + 1;
                    if (c0 > qa) sa[j][0] = -1e30f;
                    if (c1 > qa) sa[j][1] = -1e30f;
                    if (c0 > qb) sa[j][2] = -1e30f;
                    if (c1 > qb) sa[j][3] = -1e30f;
                }
            }

            float mxa = sa[0][0], mxb = sa[0][2];
#pragma unroll
            for (int j = 0; j < 8; ++j) {
                mxa = fmaxf(mxa, fmaxf(sa[j][0], sa[j][1]));
                mxb = fmaxf(mxb, fmaxf(sa[j][2], sa[j][3]));
            }
            mxa = fmaxf(mxa, __shfl_xor_sync(0xffffffffu, mxa, 1));
            mxa = fmaxf(mxa, __shfl_xor_sync(0xffffffffu, mxa, 2));
            mxb = fmaxf(mxb, __shfl_xor_sync(0xffffffffu, mxb, 1));
            mxb = fmaxf(mxb, __shfl_xor_sync(0xffffffffu, mxb, 2));
            float mna = fmaxf(m_a, mxa), mnb = fmaxf(m_b, mxb);
            float alpha_a = exp2s((m_a - mna) * SC);
            float alpha_b = exp2s((m_b - mnb) * SC);
            m_a = mna; m_b = mnb;

            float suma = 0.0f, sumb = 0.0f;
#pragma unroll
            for (int j = 0; j < 8; ++j) {
                sa[j][0] = exp2s((sa[j][0] - mna) * SC);
                sa[j][1] = exp2s((sa[j][1] - mna) * SC);
                sa[j][2] = exp2s((sa[j][2] - mnb) * SC);
                sa[j][3] = exp2s((sa[j][3] - mnb) * SC);
                suma += sa[j][0] + sa[j][1];
                sumb += sa[j][2] + sa[j][3];
            }
            suma += __shfl_xor_sync(0xffffffffu, suma, 1);
            suma += __shfl_xor_sync(0xffffffffu, suma, 2);
            sumb += __shfl_xor_sync(0xffffffffu, sumb, 1);
            sumb += __shfl_xor_sync(0xffffffffu, sumb, 2);
            l_a = l_a * alpha_a + suma;
            l_b = l_b * alpha_b + sumb;
#pragma unroll
            for (int j = 0; j < 16; ++j) {
                O[j][0] *= alpha_a; O[j][1] *= alpha_a;
                O[j][2] *= alpha_b; O[j][3] *= alpha_b;
            }

            const int rB = rA + 8;
            const int wb = (lane & 3) * 4;
#pragma unroll
            for (int j = 0; j < 8; ++j) {
                uint32_t hA = packbf(sa[j][0], sa[j][1]);
                uint32_t hB = packbf(sa[j][2], sa[j][3]);
                float2 fA = __bfloat1622float2(*(__nv_bfloat162*)&hA);
                float2 fB = __bfloat1622float2(*(__nv_bfloat162*)&hB);
                uint32_t lA = packbf(sa[j][0] - fA.x, sa[j][1] - fA.y);
                uint32_t lB = packbf(sa[j][2] - fB.x, sa[j][3] - fB.y);
                *(uint32_t*)(smc + AT_PH + rA*128 + ((j ^ (rA & 7)) * 16) + wb) = hA;
                *(uint32_t*)(smc + AT_PH + rB*128 + ((j ^ (rB & 7)) * 16) + wb) = hB;
                *(uint32_t*)(smc + AT_PL + rA*128 + ((j ^ (rA & 7)) * 16) + wb) = lA;
                *(uint32_t*)(smc + AT_PL + rB*128 + ((j ^ (rB & 7)) * 16) + wb) = lB;
            }
            __syncwarp();

            uint32_t aPh[4][4], aPl[4][4];
#pragma unroll
            for (int k2 = 0; k2 < 4; ++k2) {
                int ch = k2 * 2 + p_ch;
                uint32_t offH = AT_PH + (uint32_t)(p_row*128 + ((ch ^ (p_row & 7)) * 16));
                uint32_t offL = AT_PL + (uint32_t)(p_row*128 + ((ch ^ (p_row & 7)) * 16));
                ldsm_x4(aPh[k2][0], aPh[k2][1], aPh[k2][2], aPh[k2][3], sb + offH);
                ldsm_x4(aPl[k2][0], aPl[k2][1], aPl[k2][2], aPl[k2][3], sb + offL);
            }

#pragma unroll
            for (int g = 0; g < 8; ++g) {
#pragma unroll
                for (int k2 = 0; k2 < 4; ++k2) {
                    uint32_t b[4];
                    ldsm_x4_t(b[0], b[1], b[2], b[3],
                              st + 32768u + swz256(k2 * 16 + vt_row, g * 32 + vt_cb)); // Vh
                    mma16816(O[2*g],   aPh[k2], b);
                    mma16816(O[2*g+1], aPh[k2], b + 2);
                    mma16816(O[2*g],   aPl[k2], b);
                    mma16816(O[2*g+1], aPl[k2], b + 2);
                    ldsm_x4_t(b[0], b[1], b[2], b[3],
                              st + 49152u + swz256(k2 * 16 + vt_row, g * 32 + vt_cb)); // Vl
                    mma16816(O[2*g],   aPh[k2], b);
                    mma16816(O[2*g+1], aPh[k2], b + 2);
                }
            }
        }

        __syncthreads();
        if (kt + 2 < nkt) issue_kv(kt + 2);
        else CP_COMMIT();
    }

    const int b = bh >> 4, h = bh & 15;
    const float inva = 1.0f / l_a, invb = 1.0f / l_b;
    const size_t base_a = ((size_t)(b * SEQ + qa)) * EMB + h * HD;
    const size_t base_b = ((size_t)(b * SEQ + qb)) * EMB + h * HD;
#pragma unroll
    for (int j = 0; j < 16; ++j) {
        int dcol = j * 8 + (lane & 3) * 2;
        float oa0 = O[j][0] * inva, oa1 = O[j][1] * inva;
        float ob0 = O[j][2] * invb, ob1 = O[j][3] * invb;
        uint32_t ha = packbf(oa0, oa1);
        uint32_t hb = packbf(ob0, ob1);
        float2 fa = __bfloat1622float2(*(__nv_bfloat162*)&ha);
        float2 fb = __bfloat1622float2(*(__nv_bfloat162*)&hb);
        uint32_t la = packbf(oa0 - fa.x, oa1 - fa.y);
        uint32_t lb = packbf(ob0 - fb.x, ob1 - fb.y);
        *(uint32_t*)(g_AH[2] + base_a + dcol) = ha;
        *(uint32_t*)(g_AL[2] + base_a + dcol) = la;
        *(uint32_t*)(g_AH[2] + base_b + dcol) = hb;
        *(uint32_t*)(g_AL[2] + base_b + dcol) = lb;
    }
}

// =================================================================================
extern "C" void kernel_launch(void* const* d_in, const int* in_sizes, int n_in,
                              void* d_out, int out_size)
{
    const float* query = (const float*)d_in[0];
    const float* key   = (const float*)d_in[1];
    const float* value = (const float*)d_in[2];
    const float* cosT  = (const float*)d_in[4];
    const float* sinT  = (const float*)d_in[5];
    const float* Wq    = (const float*)d_in[6];
    const float* Wk    = (const float*)d_in[7];
    const float* Wv    = (const float*)d_in[8];
    const float* Wo    = (const float*)d_in[9];

    __nv_bfloat16 *pAH0, *pAL0, *pAH1, *pAL1, *pAH2, *pAL2;
    __nv_bfloat16 *pBH0, *pBL0, *pBH1, *pBL1, *pBH2, *pBL2, *pBH3, *pBL3;
    cudaGetSymbolAddress((void**)&pAH0, g_AH);
    cudaGetSymbolAddress((void**)&pAL0, g_AL);
    cudaGetSymbolAddress((void**)&pBH0, g_BH);
    cudaGetSymbolAddress((void**)&pBL0, g_BL);
    const size_t NA = (size_t)MROWS * EMB;
    const size_t NB = (size_t)EMB * EMB;
    pAH1 = pAH0 + NA; pAH2 = pAH0 + 2 * NA;
    pAL1 = pAL0 + NA; pAL2 = pAL0 + 2 * NA;
    pBH1 = pBH0 + NB; pBH2 = pBH0 + 2 * NB; pBH3 = pBH0 + 3 * NB;
    pBL1 = pBL0 + NB; pBL2 = pBL0 + 2 * NB; pBL3 = pBL0 + 3 * NB;

    cudaFuncSetAttribute(gemm_qkv, cudaFuncAttributeMaxDynamicSharedMemorySize, GEMM_SMEM);
    cudaFuncSetAttribute(gemm_out, cudaFuncAttributeMaxDynamicSharedMemorySize, GEMM_SMEM);
    cudaFuncSetAttribute(attn_tc2, cudaFuncAttributeMaxDynamicSharedMemorySize, AT2_SMEM);

    const int nX4 = MROWS * EMB / 4;
    const int nW4 = EMB * EMB / 4;

    split_batch<<<dim3(nX4 / 256, 3), 256>>>(
        query, key, value, query,
        pAH0, pAL0, pAH1, pAL1, pAH2, pAL2, pAH0, pAL0, nX4);
    split_batch<<<dim3(nW4 / 256, 4), 256>>>(
        Wq, Wk, Wv, Wo,
        pBH0, pBL0, pBH1, pBL1, pBH2, pBL2, pBH3, pBL3, nW4);

    // Q/K/V projections with fused RoPE+split epilogues
    gemm_qkv<<<dim3(EMB / GBN, MROWS / GBM, 3), 512, GEMM_SMEM>>>(cosT, sinT);

    // tensor-core flash attention -> ctx splits in g_AH/AL[2]
    attn_tc2<<<dim3(8, 64), 256, AT2_SMEM>>>();

    // output projection
    gemm_out<<<dim3(EMB / GBN, MROWS / GBM), 512, GEMM_SMEM>>>((float*)d_out);
}

// round 12
// speedup vs baseline: 1.5488x; 1.0063x over previous
#include <cuda_runtime.h>
#include <cuda_bf16.h>
#include <math.h>
#include <stdint.h>

#define BATCH 4
#define SEQ   1024
#define EMB   2048
#define NH    16
#define HD    128
#define MROWS (BATCH*SEQ)   /* 4096 */

// ---------------- scratch (device globals; no allocation allowed) ----------------
// activation input splits: [0]=query, [1]=key, [2]=value->ctx(later)
__device__ __nv_bfloat16 g_AH[3][(size_t)MROWS*EMB];
__device__ __nv_bfloat16 g_AL[3][(size_t)MROWS*EMB];
// weight splits: [0]=Wq [1]=Wk [2]=Wv [3]=Wo
__device__ __nv_bfloat16 g_BH[4][(size_t)EMB*EMB];
__device__ __nv_bfloat16 g_BL[4][(size_t)EMB*EMB];
// attention operand splits [B,H,S,D]
__device__ __nv_bfloat16 g_QH[(size_t)MROWS*EMB];
__device__ __nv_bfloat16 g_QL[(size_t)MROWS*EMB];
__device__ __nv_bfloat16 g_KH[(size_t)MROWS*EMB];
__device__ __nv_bfloat16 g_KL[(size_t)MROWS*EMB];
__device__ __nv_bfloat16 g_Vh[(size_t)MROWS*EMB];
__device__ __nv_bfloat16 g_Vl[(size_t)MROWS*EMB];

// ======================= portable PTX helpers (sm_80+) ===========================
__device__ __forceinline__ uint32_t smem_u32(const void* p) {
    uint32_t a;
    asm("{ .reg .u64 t; cvta.to.shared.u64 t, %1; cvt.u32.u64 %0, t; }" : "=r"(a) : "l"(p));
    return a;
}
#define CP_ASYNC16(dst, src) \
    asm volatile("cp.async.cg.shared.global [%0], [%1], 16;" :: "r"(dst), "l"(src) : "memory")
#define CP_COMMIT()   asm volatile("cp.async.commit_group;" ::: "memory")
#define CP_WAIT0()    asm volatile("cp.async.wait_group 0;" ::: "memory")
#define CP_WAIT2()    asm volatile("cp.async.wait_group 2;" ::: "memory")

__device__ __forceinline__ void ldsm_x4(uint32_t& r0, uint32_t& r1, uint32_t& r2,
                                        uint32_t& r3, uint32_t addr) {
    asm volatile("ldmatrix.sync.aligned.m8n8.x4.shared.b16 {%0,%1,%2,%3}, [%4];"
                 : "=r"(r0), "=r"(r1), "=r"(r2), "=r"(r3) : "r"(addr));
}
__device__ __forceinline__ void ldsm_x4_t(uint32_t& r0, uint32_t& r1, uint32_t& r2,
                                          uint32_t& r3, uint32_t addr) {
    asm volatile("ldmatrix.sync.aligned.m8n8.x4.trans.shared.b16 {%0,%1,%2,%3}, [%4];"
                 : "=r"(r0), "=r"(r1), "=r"(r2), "=r"(r3) : "r"(addr));
}
__device__ __forceinline__ void mma16816(float* d, const uint32_t* a, const uint32_t* b) {
    asm volatile("mma.sync.aligned.m16n8k16.row.col.f32.bf16.bf16.f32 "
                 "{%0,%1,%2,%3}, {%4,%5,%6,%7}, {%8,%9}, {%0,%1,%2,%3};"
                 : "+f"(d[0]), "+f"(d[1]), "+f"(d[2]), "+f"(d[3])
                 : "r"(a[0]), "r"(a[1]), "r"(a[2]), "r"(a[3]), "r"(b[0]), "r"(b[1]));
}
__device__ __forceinline__ uint32_t swz64(int row, int colByte) {
    return (uint32_t)(row * 64 + ((((colByte >> 4) ^ (row >> 1)) & 3) * 16));
}
__device__ __forceinline__ uint32_t swz256(int row, int cb) {
    int ch = cb >> 4;
    int sw = (ch & 8) | ((ch ^ row) & 7);
    return (uint32_t)(row * 256 + sw * 16);
}
__device__ __forceinline__ uint32_t packbf(float lo, float hi) {
    __nv_bfloat162 t = __floats2bfloat162_rn(lo, hi);
    return *(uint32_t*)&t;
}
__device__ __forceinline__ float exp2s(float x) {
    x = fmaxf(x, -126.0f);
    int i = __float2int_rn(x);
    float f = x - (float)i;
    float p = 0.00961812911f;
    p = fmaf(p, f, 0.0555041087f);
    p = fmaf(p, f, 0.240226507f);
    p = fmaf(p, f, 0.693147182f);
    p = fmaf(p, f, 1.0f);
    return p * __int_as_float((i + 127) << 23);
}

// ======================= batched split fp32 -> bf16 hi/lo ========================
__global__ __launch_bounds__(256)
void split_batch(const float* __restrict__ a0, const float* __restrict__ a1,
                 const float* __restrict__ a2, const float* __restrict__ a3,
                 __nv_bfloat16* __restrict__ h0, __nv_bfloat16* __restrict__ l0,
                 __nv_bfloat16* __restrict__ h1, __nv_bfloat16* __restrict__ l1,
                 __nv_bfloat16* __restrict__ h2, __nv_bfloat16* __restrict__ l2,
                 __nv_bfloat16* __restrict__ h3, __nv_bfloat16* __restrict__ l3,
                 int n4)
{
    int t = blockIdx.y;
    const float* X = (t == 0) ? a0 : (t == 1) ? a1 : (t == 2) ? a2 : a3;
    __nv_bfloat16* Hi = (t == 0) ? h0 : (t == 1) ? h1 : (t == 2) ? h2 : h3;
    __nv_bfloat16* Lo = (t == 0) ? l0 : (t == 1) ? l1 : (t == 2) ? l2 : l3;

    int i = blockIdx.x * 256 + threadIdx.x;
    if (i >= n4) return;
    float4 v = ((const float4*)X)[i];
    __nv_bfloat16 b0 = __float2bfloat16(v.x);
    __nv_bfloat16 b1 = __float2bfloat16(v.y);
    __nv_bfloat16 b2 = __float2bfloat16(v.z);
    __nv_bfloat16 b3 = __float2bfloat16(v.w);
    __nv_bfloat16 c0 = __float2bfloat16(v.x - __bfloat162float(b0));
    __nv_bfloat16 c1 = __float2bfloat16(v.y - __bfloat162float(b1));
    __nv_bfloat16 c2 = __float2bfloat16(v.z - __bfloat162float(b2));
    __nv_bfloat16 c3 = __float2bfloat16(v.w - __bfloat162float(b3));
    __nv_bfloat162* H2 = (__nv_bfloat162*)Hi;
    __nv_bfloat162* L2 = (__nv_bfloat162*)Lo;
    H2[2*i]   = __nv_bfloat162(b0, b1);
    H2[2*i+1] = __nv_bfloat162(b2, b3);
    L2[2*i]   = __nv_bfloat162(c0, c1);
    L2[2*i+1] = __nv_bfloat162(c2, c3);
}

// ======================= split-bf16 GEMM core (one sync per chunk) ==============
#define GBM 128
#define GBN 256
#define GBK 32
#define OFF_AH 0
#define OFF_AL 8192
#define OFF_BH 16384
#define OFF_BL 32768
#define STAGE_BYTES 49152
#define GSTAGES 4
#define GEMM_SMEM (GSTAGES * STAGE_BYTES)   /* 196608 */

__device__ __forceinline__ void gemm_issue_stage(
    const __nv_bfloat16* __restrict__ Ah, const __nv_bfloat16* __restrict__ Al,
    const __nv_bfloat16* __restrict__ Bh, const __nv_bfloat16* __restrict__ Bl,
    uint32_t sb, int tid, int m0, int n0, int c)
{
    const uint32_t st = sb + (uint32_t)(c % GSTAGES) * STAGE_BYTES;
    const int kc = c * GBK;
#pragma unroll
    for (int u = 0; u < 6; ++u) {
        int f = tid + u * 512;
        uint32_t dst; const __nv_bfloat16* gp;
        if (f < 1024) {
            int rel = f & 511;
            int row = rel >> 2, ch = rel & 3;
            const __nv_bfloat16* base = (f < 512) ? Ah : Al;
            gp  = base + (size_t)(m0 + row) * EMB + kc + ch * 8;
            dst = st + ((f < 512) ? OFF_AH : OFF_AL) + swz64(row, ch * 16);
        } else {
            int rel = (f - 1024) & 1023;
            int row = rel >> 2, ch = rel & 3;
            const __nv_bfloat16* base = (f < 2048) ? Bh : Bl;
            gp  = base + (size_t)(n0 + row) * EMB + kc + ch * 8;
            dst = st + ((f < 2048) ? OFF_BH : OFF_BL) + swz64(row, ch * 16);
        }
        CP_ASYNC16(dst, gp);
    }
    CP_COMMIT();
}

__device__ __forceinline__ void gemm_core(
    const __nv_bfloat16* __restrict__ Ah, const __nv_bfloat16* __restrict__ Al,
    const __nv_bfloat16* __restrict__ Bh, const __nv_bfloat16* __restrict__ Bl,
    uint32_t sb, int tid, int lane, int wid, int m0, int n0,
    float (&acc)[2][8][4])
{
#pragma unroll
    for (int i = 0; i < 2; ++i)
#pragma unroll
        for (int j = 0; j < 8; ++j)
#pragma unroll
            for (int r = 0; r < 4; ++r) acc[i][j][r] = 0.0f;

    const int warp_m = wid & 3;
    const int warp_n = wid >> 2;
    const int a_row = warp_m * 32 + ((lane >> 3) & 1) * 8 + (lane & 7);
    const int a_cb  = (lane >> 4) * 16;
    const int b_row = warp_n * 64 + ((lane >> 4) & 1) * 8 + (lane & 7);
    const int b_cb  = ((lane >> 3) & 1) * 16;

    gemm_issue_stage(Ah, Al, Bh, Bl, sb, tid, m0, n0, 0);
    gemm_issue_stage(Ah, Al, Bh, Bl, sb, tid, m0, n0, 1);
    gemm_issue_stage(Ah, Al, Bh, Bl, sb, tid, m0, n0, 2);

    const int NC = EMB / GBK;   // 64
    for (int c = 0; c < NC; ++c) {
        CP_WAIT2();
        __syncthreads();
        if (c + 3 < NC) gemm_issue_stage(Ah, Al, Bh, Bl, sb, tid, m0, n0, c + 3);
        else CP_COMMIT();

        const uint32_t st = sb + (uint32_t)(c % GSTAGES) * STAGE_BYTES;
#pragma unroll
        for (int ks = 0; ks < 2; ++ks) {
            const int cb = ks * 32;
            uint32_t a[2][2][4];
#pragma unroll
            for (int i = 0; i < 2; ++i) {
                ldsm_x4(a[0][i][0], a[0][i][1], a[0][i][2], a[0][i][3],
                        st + OFF_AH + swz64(a_row + i * 16, a_cb + cb));
                ldsm_x4(a[1][i][0], a[1][i][1], a[1][i][2], a[1][i][3],
                        st + OFF_AL + swz64(a_row + i * 16, a_cb + cb));
            }
            uint32_t b[8][2];
#pragma unroll
            for (int q = 0; q < 4; ++q)
                ldsm_x4(b[2*q][0], b[2*q][1], b[2*q+1][0], b[2*q+1][1],
                        st + OFF_BH + swz64(b_row + q * 16, b_cb + cb));
#pragma unroll
            for (int i = 0; i < 2; ++i)
#pragma unroll
                for (int j = 0; j < 8; ++j) {
                    mma16816(acc[i][j], a[0][i], b[j]);
                    mma16816(acc[i][j], a[1][i], b[j]);
                }
#pragma unroll
            for (int q = 0; q < 4; ++q)
                ldsm_x4(b[2*q][0], b[2*q][1], b[2*q+1][0], b[2*q+1][1],
                        st + OFF_BL + swz64(b_row + q * 16, b_cb + cb));
#pragma unroll
            for (int i = 0; i < 2; ++i)
#pragma unroll
                for (int j = 0; j < 8; ++j)
                    mma16816(acc[i][j], a[0][i], b[j]);
        }
    }
}

// ---- batched Q/K/V projection GEMM with fused RoPE+split epilogue -------------
#define SPAD 260

__global__ __launch_bounds__(512, 1)
void gemm_qkv(const float* __restrict__ cosT, const float* __restrict__ sinT)
{
    extern __shared__ __align__(128) char smc[];
    const uint32_t sb = smem_u32(smc);
    const int tid = threadIdx.x, lane = tid & 31, wid = tid >> 5;
    const int m0 = blockIdx.y * GBM, n0 = blockIdx.x * GBN;
    const int z = blockIdx.z;

    float acc[2][8][4];
    gemm_core(g_AH[z], g_AL[z], g_BH[z], g_BL[z], sb, tid, lane, wid, m0, n0, acc);

    const int warp_m = wid & 3, warp_n = wid >> 2;
    const int r0q = lane >> 2, c0q = (lane & 3) * 2;

    if (z == 2) {
#pragma unroll
        for (int i = 0; i < 2; ++i) {
#pragma unroll
            for (int j = 0; j < 8; ++j) {
                int mrow0 = m0 + warp_m * 32 + i * 16 + r0q;
                int ncol  = n0 + warp_n * 64 + j * 8 + c0q;
                int h = ncol >> 7, dc = ncol & 127;
                int b0 = mrow0 >> 10, s0 = mrow0 & 1023;
                int b1 = (mrow0 + 8) >> 10, s1 = (mrow0 + 8) & 1023;
                size_t o0 = (((size_t)(b0 * NH + h)) * SEQ + s0) * HD + dc;
                size_t o1 = (((size_t)(b1 * NH + h)) * SEQ + s1) * HD + dc;
                uint32_t h0 = packbf(acc[i][j][0], acc[i][j][1]);
                uint32_t h1 = packbf(acc[i][j][2], acc[i][j][3]);
                float2 f0 = __bfloat1622float2(*(__nv_bfloat162*)&h0);
                float2 f1 = __bfloat1622float2(*(__nv_bfloat162*)&h1);
                uint32_t l0 = packbf(acc[i][j][0] - f0.x, acc[i][j][1] - f0.y);
                uint32_t l1 = packbf(acc[i][j][2] - f1.x, acc[i][j][3] - f1.y);
                *(uint32_t*)(g_Vh + o0) = h0;
                *(uint32_t*)(g_Vh + o1) = h1;
                *(uint32_t*)(g_Vl + o0) = l0;
                *(uint32_t*)(g_Vl + o1) = l1;
            }
        }
    } else {
        float* stile = (float*)smc;
        __syncthreads();
#pragma unroll
        for (int i = 0; i < 2; ++i) {
#pragma unroll
            for (int j = 0; j < 8; ++j) {
                int lr0 = warp_m * 32 + i * 16 + r0q;
                int lc  = warp_n * 64 + j * 8 + c0q;
                stile[lr0 * SPAD + lc]           = acc[i][j][0];
                stile[lr0 * SPAD + lc + 1]       = acc[i][j][1];
                stile[(lr0 + 8) * SPAD + lc]     = acc[i][j][2];
                stile[(lr0 + 8) * SPAD + lc + 1] = acc[i][j][3];
            }
        }
        __syncthreads();

        __nv_bfloat16* H = (z == 0) ? g_QH : g_KH;
        __nv_bfloat16* L = (z == 0) ? g_QL : g_KL;
#pragma unroll
        for (int it = 0; it < 16; ++it) {
            int slot = tid + it * 512;
            int t  = slot & 31;
            int lr = (slot >> 5) & 127;
            int hh = slot >> 12;
            int d0 = t * 2;
            int gm = m0 + lr;
            int b  = gm >> 10, s = gm & 1023;
            float2 cc = *(const float2*)(cosT + s * HD + d0);
            float2 ss = *(const float2*)(sinT + s * HD + d0);
            const float* row = stile + lr * SPAD + hh * 128;
            float x1a = row[d0],      x1b = row[d0 + 1];
            float x2a = row[d0 + 64], x2b = row[d0 + 65];
            float r1a = x1a * cc.x - x2a * ss.x, r1b = x1b * cc.y - x2b * ss.y;
            float r2a = x2a * cc.x + x1a * ss.x, r2b = x2b * cc.y + x1b * ss.y;
            uint32_t h1 = packbf(r1a, r1b), h2 = packbf(r2a, r2b);
            float2 f1 = __bfloat1622float2(*(__nv_bfloat162*)&h1);
            float2 f2 = __bfloat1622float2(*(__nv_bfloat162*)&h2);
            uint32_t l1 = packbf(r1a - f1.x, r1b - f1.y);
            uint32_t l2 = packbf(r2a - f2.x, r2b - f2.y);
            int h = (n0 >> 7) + hh;
            size_t o = (((size_t)(b * NH + h)) * SEQ + s) * HD + d0;
            *(uint32_t*)(H + o)      = h1;
            *(uint32_t*)(L + o)      = l1;
            *(uint32_t*)(H + o + 64) = h2;
            *(uint32_t*)(L + o + 64) = l2;
        }
    }
}

// ---- output projection GEMM ----
__global__ __launch_bounds__(512, 1)
void gemm_out(float* __restrict__ Y)
{
    extern __shared__ __align__(128) char smc[];
    const uint32_t sb = smem_u32(smc);
    const int tid = threadIdx.x, lane = tid & 31, wid = tid >> 5;
    const int m0 = blockIdx.y * GBM, n0 = blockIdx.x * GBN;

    float acc[2][8][4];
    gemm_core(g_AH[2], g_AL[2], g_BH[3], g_BL[3], sb, tid, lane, wid, m0, n0, acc);

    const int warp_m = wid & 3, warp_n = wid >> 2;
    const int r0q = lane >> 2, c0q = (lane & 3) * 2;
#pragma unroll
    for (int i = 0; i < 2; ++i) {
#pragma unroll
        for (int j = 0; j < 8; ++j) {
            int mrow0 = m0 + warp_m * 32 + i * 16 + r0q;
            int ncol  = n0 + warp_n * 64 + j * 8 + c0q;
            *(float2*)(Y + (size_t)mrow0 * EMB + ncol) =
                make_float2(acc[i][j][0], acc[i][j][1]);
            *(float2*)(Y + (size_t)(mrow0 + 8) * EMB + ncol) =
                make_float2(acc[i][j][2], acc[i][j][3]);
        }
    }
}

// =================================================================================
// Tensor-core flash attention v3: 64-row Q tiles, 128 threads, single KV buffer,
// 2 CTAs/SM. Per-warp inner body identical to the proven R7-R11 kernel.
// smem: QH 16K | QL 16K | KH 16K | KL 16K | VH 16K | VL 16K | PH 8K | PL 8K = 112K
// =================================================================================
#define A3_QH 0u
#define A3_QL 16384u
#define A3_KV 32768u
#define A3_PH 98304u
#define A3_PL 106496u
#define A3_SMEM 114688

__global__ __launch_bounds__(128, 2)
void attn_tc3()
{
    extern __shared__ __align__(128) char smc[];
    const uint32_t sb = smem_u32(smc);
    const int tid = threadIdx.x, lane = tid & 31, w = tid >> 5;   // w 0..3
    const int qt = 15 - blockIdx.x;          // heaviest tiles first
    const int bh = blockIdx.y;
    const int q0 = qt * 64;
    const float SC = 0.12751743f;   // log2(e)/sqrt(128)

    // ---- Q tile (64 rows, both splits) ----
    {
        const size_t gbase = ((size_t)bh * SEQ + q0) * HD;
#pragma unroll
        for (int u = 0; u < 16; ++u) {
            int f = tid + u * 128;
            int rel = f & 1023;
            int row = rel >> 4, ch = rel & 15;
            const __nv_bfloat16* gp = ((f < 1024) ? g_QH : g_QL)
                                      + gbase + (size_t)row * HD + ch * 8;
            uint32_t dst = sb + ((f < 1024) ? A3_QH : A3_QL) + swz256(row, ch * 16);
            CP_ASYNC16(dst, gp);
        }
        CP_COMMIT();
    }

    auto issue_kv = [&](int kt) {
        const size_t gbase = ((size_t)bh * SEQ + kt * 64) * HD;
#pragma unroll
        for (int u = 0; u < 32; ++u) {
            int f = tid + u * 128;
            int rel = f & 1023;
            int row = rel >> 4, ch = rel & 15;
            int arr = f >> 10;
            const __nv_bfloat16* gb = (arr == 0) ? g_KH : (arr == 1) ? g_KL
                                     : (arr == 2) ? g_Vh : g_Vl;
            const __nv_bfloat16* gp = gb + gbase + (size_t)row * HD + ch * 8;
            uint32_t dst = sb + A3_KV + (uint32_t)arr * 16384u + swz256(row, ch * 16);
            CP_ASYNC16(dst, gp);
        }
        CP_COMMIT();
    };

    const int nkt = qt + 1;
    issue_kv(0);

    const int rA = w * 16 + (lane >> 2);     // 0..63
    const int qa = q0 + rA, qb = qa + 8;
    float O[16][4];
#pragma unroll
    for (int j = 0; j < 16; ++j)
#pragma unroll
        for (int r = 0; r < 4; ++r) O[j][r] = 0.0f;
    float m_a = -1e30f, m_b = -1e30f, l_a = 0.0f, l_b = 0.0f;

    const int qa_row = w * 16 + ((lane >> 3) & 1) * 8 + (lane & 7);
    const int qa_cb  = (lane >> 4) * 16;
    const int kb_row = ((lane >> 4) & 1) * 8 + (lane & 7);
    const int kb_cb  = ((lane >> 3) & 1) * 16;
    const int vt_row = ((lane >> 3) & 1) * 8 + (lane & 7);
    const int vt_cb  = (lane >> 4) * 16;
    const int p_row = w * 16 + ((lane >> 3) & 1) * 8 + (lane & 7);
    const int p_ch  = (lane >> 4);

    for (int kt = 0; kt < nkt; ++kt) {
        CP_WAIT0();
        __syncthreads();
        const uint32_t st = sb + A3_KV;

        // ---- S = Q K^T (3-term split) ----
        float sa[8][4];
#pragma unroll
        for (int j = 0; j < 8; ++j)
#pragma unroll
            for (int r = 0; r < 4; ++r) sa[j][r] = 0.0f;

#pragma unroll
        for (int kk = 0; kk < 8; ++kk) {
            const int cb = kk * 32;
            uint32_t aH[4], aL[4];
            ldsm_x4(aH[0], aH[1], aH[2], aH[3], sb + A3_QH + swz256(qa_row, qa_cb + cb));
            ldsm_x4(aL[0], aL[1], aL[2], aL[3], sb + A3_QL + swz256(qa_row, qa_cb + cb));
#pragma unroll
            for (int g = 0; g < 4; ++g) {
                uint32_t b[4];
                ldsm_x4(b[0], b[1], b[2], b[3],
                        st + swz256(g * 16 + kb_row, kb_cb + cb));          // Kh
                mma16816(sa[2*g],   aH, b);
                mma16816(sa[2*g+1], aH, b + 2);
                mma16816(sa[2*g],   aL, b);
                mma16816(sa[2*g+1], aL, b + 2);
                ldsm_x4(b[0], b[1], b[2], b[3],
                        st + 16384u + swz256(g * 16 + kb_row, kb_cb + cb)); // Kl
                mma16816(sa[2*g],   aH, b);
                mma16816(sa[2*g+1], aH, b + 2);
            }
        }

        // ---- causal mask (only the diagonal tile triggers) ----
        if (kt * 64 + 63 > q0 + w * 16) {
            const int colb = kt * 64 + (lane & 3) * 2;
#pragma unroll
            for (int j = 0; j < 8; ++j) {
                int c0 = colb + j * 8, c1 = c0 + 1;
                if (c0 > qa) sa[j][0] = -1e30f;
                if (c1 > qa) sa[j][1] = -1e30f;
                if (c0 > qb) sa[j][2] = -1e30f;
                if (c1 > qb) sa[j][3] = -1e30f;
            }
        }

        // ---- online softmax (exp2 domain) ----
        float mxa = sa[0][0], mxb = sa[0][2];
#pragma unroll
        for (int j = 0; j < 8; ++j) {
            mxa = fmaxf(mxa, fmaxf(sa[j][0], sa[j][1]));
            mxb = fmaxf(mxb, fmaxf(sa[j][2], sa[j][3]));
        }
        mxa = fmaxf(mxa, __shfl_xor_sync(0xffffffffu, mxa, 1));
        mxa = fmaxf(mxa, __shfl_xor_sync(0xffffffffu, mxa, 2));
        mxb = fmaxf(mxb, __shfl_xor_sync(0xffffffffu, mxb, 1));
        mxb = fmaxf(mxb, __shfl_xor_sync(0xffffffffu, mxb, 2));
        float mna = fmaxf(m_a, mxa), mnb = fmaxf(m_b, mxb);
        float alpha_a = exp2s((m_a - mna) * SC);
        float alpha_b = exp2s((m_b - mnb) * SC);
        m_a = mna; m_b = mnb;

        float suma = 0.0f, sumb = 0.0f;
#pragma unroll
        for (int j = 0; j < 8; ++j) {
            sa[j][0] = exp2s((sa[j][0] - mna) * SC);
            sa[j][1] = exp2s((sa[j][1] - mna) * SC);
            sa[j][2] = exp2s((sa[j][2] - mnb) * SC);
            sa[j][3] = exp2s((sa[j][3] - mnb) * SC);
            suma += sa[j][0] + sa[j][1];
            sumb += sa[j][2] + sa[j][3];
        }
        suma += __shfl_xor_sync(0xffffffffu, suma, 1);
        suma += __shfl_xor_sync(0xffffffffu, suma, 2);
        sumb += __shfl_xor_sync(0xffffffffu, sumb, 1);
        sumb += __shfl_xor_sync(0xffffffffu, sumb, 2);
        l_a = l_a * alpha_a + suma;
        l_b = l_b * alpha_b + sumb;
#pragma unroll
        for (int j = 0; j < 16; ++j) {
            O[j][0] *= alpha_a; O[j][1] *= alpha_a;
            O[j][2] *= alpha_b; O[j][3] *= alpha_b;
        }

        // ---- store P hi/lo to smem (per-warp private rows) ----
        const int rB = rA + 8;
        const int wb = (lane & 3) * 4;
#pragma unroll
        for (int j = 0; j < 8; ++j) {
            uint32_t hA = packbf(sa[j][0], sa[j][1]);
            uint32_t hB = packbf(sa[j][2], sa[j][3]);
            float2 fA = __bfloat1622float2(*(__nv_bfloat162*)&hA);
            float2 fB = __bfloat1622float2(*(__nv_bfloat162*)&hB);
            uint32_t lA = packbf(sa[j][0] - fA.x, sa[j][1] - fA.y);
            uint32_t lB = packbf(sa[j][2] - fB.x, sa[j][3] - fB.y);
            *(uint32_t*)(smc + A3_PH + rA*128 + ((j ^ (rA & 7)) * 16) + wb) = hA;
            *(uint32_t*)(smc + A3_PH + rB*128 + ((j ^ (rB & 7)) * 16) + wb) = hB;
            *(uint32_t*)(smc + A3_PL + rA*128 + ((j ^ (rA & 7)) * 16) + wb) = lA;
            *(uint32_t*)(smc + A3_PL + rB*128 + ((j ^ (rB & 7)) * 16) + wb) = lB;
        }
        __syncwarp();

        // ---- load P A-fragments back ----
        uint32_t aPh[4][4], aPl[4][4];
#pragma unroll
        for (int k2 = 0; k2 < 4; ++k2) {
            int ch = k2 * 2 + p_ch;
            uint32_t offH = A3_PH + (uint32_t)(p_row*128 + ((ch ^ (p_row & 7)) * 16));
            uint32_t offL = A3_PL + (uint32_t)(p_row*128 + ((ch ^ (p_row & 7)) * 16));
            ldsm_x4(aPh[k2][0], aPh[k2][1], aPh[k2][2], aPh[k2][3], sb + offH);
            ldsm_x4(aPl[k2][0], aPl[k2][1], aPl[k2][2], aPl[k2][3], sb + offL);
        }

        // ---- O += P V (3-term split) ----
#pragma unroll
        for (int g = 0; g < 8; ++g) {
#pragma unroll
            for (int k2 = 0; k2 < 4; ++k2) {
                uint32_t b[4];
                ldsm_x4_t(b[0], b[1], b[2], b[3],
                          st + 32768u + swz256(k2 * 16 + vt_row, g * 32 + vt_cb)); // Vh
                mma16816(O[2*g],   aPh[k2], b);
                mma16816(O[2*g+1], aPh[k2], b + 2);
                mma16816(O[2*g],   aPl[k2], b);
                mma16816(O[2*g+1], aPl[k2], b + 2);
                ldsm_x4_t(b[0], b[1], b[2], b[3],
                          st + 49152u + swz256(k2 * 16 + vt_row, g * 32 + vt_cb)); // Vl
                mma16816(O[2*g],   aPh[k2], b);
                mma16816(O[2*g+1], aPh[k2], b + 2);
            }
        }

        __syncthreads();   // all warps done reading KV buffer
        if (kt + 1 < nkt) issue_kv(kt + 1);
    }

    // ---- epilogue: normalize, split to bf16 hi/lo, write ctx [B,S,E] ----
    const int b = bh >> 4, h = bh & 15;
    const float inva = 1.0f / l_a, invb = 1.0f / l_b;
    const size_t base_a = ((size_t)(b * SEQ + qa)) * EMB + h * HD;
    const size_t base_b = ((size_t)(b * SEQ + qb)) * EMB + h * HD;
#pragma unroll
    for (int j = 0; j < 16; ++j) {
        int dcol = j * 8 + (lane & 3) * 2;
        float oa0 = O[j][0] * inva, oa1 = O[j][1] * inva;
        float ob0 = O[j][2] * invb, ob1 = O[j][3] * invb;
        uint32_t ha = packbf(oa0, oa1);
        uint32_t hb = packbf(ob0, ob1);
        float2 fa = __bfloat1622float2(*(__nv_bfloat162*)&ha);
        float2 fb = __bfloat1622float2(*(__nv_bfloat162*)&hb);
        uint32_t la = packbf(oa0 - fa.x, oa1 - fa.y);
        uint32_t lb = packbf(ob0 - fb.x, ob1 - fb.y);
        *(uint32_t*)(g_AH[2] + base_a + dcol) = ha;
        *(uint32_t*)(g_AL[2] + base_a + dcol) = la;
        *(uint32_t*)(g_AH[2] + base_b + dcol) = hb;
        *(uint32_t*)(g_AL[2] + base_b + dcol) = lb;
    }
}

// =================================================================================
extern "C" void kernel_launch(void* const* d_in, const int* in_sizes, int n_in,
                              void* d_out, int out_size)
{
    const float* query = (const float*)d_in[0];
    const float* key   = (const float*)d_in[1];
    const float* value = (const float*)d_in[2];
    const float* cosT  = (const float*)d_in[4];
    const float* sinT  = (const float*)d_in[5];
    const float* Wq    = (const float*)d_in[6];
    const float* Wk    = (const float*)d_in[7];
    const float* Wv    = (const float*)d_in[8];
    const float* Wo    = (const float*)d_in[9];

    __nv_bfloat16 *pAH0, *pAL0, *pAH1, *pAL1, *pAH2, *pAL2;
    __nv_bfloat16 *pBH0, *pBL0, *pBH1, *pBL1, *pBH2, *pBL2, *pBH3, *pBL3;
    cudaGetSymbolAddress((void**)&pAH0, g_AH);
    cudaGetSymbolAddress((void**)&pAL0, g_AL);
    cudaGetSymbolAddress((void**)&pBH0, g_BH);
    cudaGetSymbolAddress((void**)&pBL0, g_BL);
    const size_t NA = (size_t)MROWS * EMB;
    const size_t NB = (size_t)EMB * EMB;
    pAH1 = pAH0 + NA; pAH2 = pAH0 + 2 * NA;
    pAL1 = pAL0 + NA; pAL2 = pAL0 + 2 * NA;
    pBH1 = pBH0 + NB; pBH2 = pBH0 + 2 * NB; pBH3 = pBH0 + 3 * NB;
    pBL1 = pBL0 + NB; pBL2 = pBL0 + 2 * NB; pBL3 = pBL0 + 3 * NB;

    cudaFuncSetAttribute(gemm_qkv, cudaFuncAttributeMaxDynamicSharedMemorySize, GEMM_SMEM);
    cudaFuncSetAttribute(gemm_out, cudaFuncAttributeMaxDynamicSharedMemorySize, GEMM_SMEM);
    cudaFuncSetAttribute(attn_tc3, cudaFuncAttributeMaxDynamicSharedMemorySize, A3_SMEM);

    const int nX4 = MROWS * EMB / 4;
    const int nW4 = EMB * EMB / 4;

    split_batch<<<dim3(nX4 / 256, 3), 256>>>(
        query, key, value, query,
        pAH0, pAL0, pAH1, pAL1, pAH2, pAL2, pAH0, pAL0, nX4);
    split_batch<<<dim3(nW4 / 256, 4), 256>>>(
        Wq, Wk, Wv, Wo,
        pBH0, pBL0, pBH1, pBL1, pBH2, pBL2, pBH3, pBL3, nW4);

    // Q/K/V projections with fused RoPE+split epilogues
    gemm_qkv<<<dim3(EMB / GBN, MROWS / GBM, 3), 512, GEMM_SMEM>>>(cosT, sinT);

    // tensor-core flash attention v3 (64-row Q tiles, 2 CTAs/SM)
    attn_tc3<<<dim3(16, 64), 128, A3_SMEM>>>();

    // output projection
    gemm_out<<<dim3(EMB / GBN, MROWS / GBM), 512, GEMM_SMEM>>>((float*)d_out);
}

// round 13
// speedup vs baseline: 1.6791x; 1.0841x over previous
#include <cuda_runtime.h>
#include <cuda_bf16.h>
#include <math.h>
#include <stdint.h>

#define BATCH 4
#define SEQ   1024
#define EMB   2048
#define NH    16
#define HD    128
#define MROWS (BATCH*SEQ)   /* 4096 */

// ---------------- scratch (device globals; no allocation allowed) ----------------
__device__ __nv_bfloat16 g_AH[3][(size_t)MROWS*EMB];   // [0]=query [1]=key [2]=value->ctx
__device__ __nv_bfloat16 g_AL[3][(size_t)MROWS*EMB];
__device__ __nv_bfloat16 g_BH[4][(size_t)EMB*EMB];     // Wq Wk Wv Wo
__device__ __nv_bfloat16 g_BL[4][(size_t)EMB*EMB];
__device__ __nv_bfloat16 g_QH[(size_t)MROWS*EMB];
__device__ __nv_bfloat16 g_QL[(size_t)MROWS*EMB];
__device__ __nv_bfloat16 g_KH[(size_t)MROWS*EMB];
__device__ __nv_bfloat16 g_KL[(size_t)MROWS*EMB];
__device__ __nv_bfloat16 g_Vh[(size_t)MROWS*EMB];
__device__ __nv_bfloat16 g_Vl[(size_t)MROWS*EMB];

// ======================= portable PTX helpers (sm_80+) ===========================
__device__ __forceinline__ uint32_t smem_u32(const void* p) {
    uint32_t a;
    asm("{ .reg .u64 t; cvta.to.shared.u64 t, %1; cvt.u32.u64 %0, t; }" : "=r"(a) : "l"(p));
    return a;
}
#define CP_ASYNC16(dst, src) \
    asm volatile("cp.async.cg.shared.global [%0], [%1], 16;" :: "r"(dst), "l"(src) : "memory")
#define CP_COMMIT()   asm volatile("cp.async.commit_group;" ::: "memory")
#define CP_WAIT0()    asm volatile("cp.async.wait_group 0;" ::: "memory")
#define CP_WAIT1()    asm volatile("cp.async.wait_group 1;" ::: "memory")

__device__ __forceinline__ void ldsm_x4(uint32_t& r0, uint32_t& r1, uint32_t& r2,
                                        uint32_t& r3, uint32_t addr) {
    asm volatile("ldmatrix.sync.aligned.m8n8.x4.shared.b16 {%0,%1,%2,%3}, [%4];"
                 : "=r"(r0), "=r"(r1), "=r"(r2), "=r"(r3) : "r"(addr));
}
__device__ __forceinline__ void ldsm_x4_t(uint32_t& r0, uint32_t& r1, uint32_t& r2,
                                          uint32_t& r3, uint32_t addr) {
    asm volatile("ldmatrix.sync.aligned.m8n8.x4.trans.shared.b16 {%0,%1,%2,%3}, [%4];"
                 : "=r"(r0), "=r"(r1), "=r"(r2), "=r"(r3) : "r"(addr));
}
__device__ __forceinline__ void mma16816(float* d, const uint32_t* a, const uint32_t* b) {
    asm volatile("mma.sync.aligned.m16n8k16.row.col.f32.bf16.bf16.f32 "
                 "{%0,%1,%2,%3}, {%4,%5,%6,%7}, {%8,%9}, {%0,%1,%2,%3};"
                 : "+f"(d[0]), "+f"(d[1]), "+f"(d[2]), "+f"(d[3])
                 : "r"(a[0]), "r"(a[1]), "r"(a[2]), "r"(a[3]), "r"(b[0]), "r"(b[1]));
}
__device__ __forceinline__ uint32_t swz64(int row, int colByte) {
    return (uint32_t)(row * 64 + ((((colByte >> 4) ^ (row >> 1)) & 3) * 16));
}
__device__ __forceinline__ uint32_t swz256(int row, int cb) {
    int ch = cb >> 4;
    int sw = (ch & 8) | ((ch ^ row) & 7);
    return (uint32_t)(row * 256 + sw * 16);
}
__device__ __forceinline__ uint32_t packbf(float lo, float hi) {
    __nv_bfloat162 t = __floats2bfloat162_rn(lo, hi);
    return *(uint32_t*)&t;
}
__device__ __forceinline__ float exp2s(float x) {
    x = fmaxf(x, -126.0f);
    int i = __float2int_rn(x);
    float f = x - (float)i;
    float p = 0.00961812911f;
    p = fmaf(p, f, 0.0555041087f);
    p = fmaf(p, f, 0.240226507f);
    p = fmaf(p, f, 0.693147182f);
    p = fmaf(p, f, 1.0f);
    return p * __int_as_float((i + 127) << 23);
}

// ======================= batched split fp32 -> bf16 hi/lo ========================
__global__ __launch_bounds__(256)
void split_batch(const float* __restrict__ a0, const float* __restrict__ a1,
                 const float* __restrict__ a2, const float* __restrict__ a3,
                 __nv_bfloat16* __restrict__ h0, __nv_bfloat16* __restrict__ l0,
                 __nv_bfloat16* __restrict__ h1, __nv_bfloat16* __restrict__ l1,
                 __nv_bfloat16* __restrict__ h2, __nv_bfloat16* __restrict__ l2,
                 __nv_bfloat16* __restrict__ h3, __nv_bfloat16* __restrict__ l3,
                 int n4)
{
    int t = blockIdx.y;
    const float* X = (t == 0) ? a0 : (t == 1) ? a1 : (t == 2) ? a2 : a3;
    __nv_bfloat16* Hi = (t == 0) ? h0 : (t == 1) ? h1 : (t == 2) ? h2 : h3;
    __nv_bfloat16* Lo = (t == 0) ? l0 : (t == 1) ? l1 : (t == 2) ? l2 : l3;

    int i = blockIdx.x * 256 + threadIdx.x;
    if (i >= n4) return;
    float4 v = ((const float4*)X)[i];
    __nv_bfloat16 b0 = __float2bfloat16(v.x);
    __nv_bfloat16 b1 = __float2bfloat16(v.y);
    __nv_bfloat16 b2 = __float2bfloat16(v.z);
    __nv_bfloat16 b3 = __float2bfloat16(v.w);
    __nv_bfloat16 c0 = __float2bfloat16(v.x - __bfloat162float(b0));
    __nv_bfloat16 c1 = __float2bfloat16(v.y - __bfloat162float(b1));
    __nv_bfloat16 c2 = __float2bfloat16(v.z - __bfloat162float(b2));
    __nv_bfloat16 c3 = __float2bfloat16(v.w - __bfloat162float(b3));
    __nv_bfloat162* H2 = (__nv_bfloat162*)Hi;
    __nv_bfloat162* L2 = (__nv_bfloat162*)Lo;
    H2[2*i]   = __nv_bfloat162(b0, b1);
    H2[2*i+1] = __nv_bfloat162(b2, b3);
    L2[2*i]   = __nv_bfloat162(c0, c1);
    L2[2*i+1] = __nv_bfloat162(c2, c3);
}

// ======================= split-bf16 GEMM core v2 =================================
// Tile 128x128, 256 threads (8 warps: 4m x 2n, warp tile 32x64), BK=32,
// 3 stages x 32KB = 96KB smem, 2 CTAs/SM. Single sync per chunk:
// issue(c+2) targets stage (c+2)%3 == (c-1)%3, freed by the leading sync.
#define GBM 128
#define GBN 128
#define GBK 32
#define OFF_AH 0
#define OFF_AL 8192
#define OFF_BH 16384
#define OFF_BL 24576
#define STAGE_BYTES 32768
#define GEMM_SMEM (3 * STAGE_BYTES)   /* 98304 */

__device__ __forceinline__ void gemm_issue_stage(
    const __nv_bfloat16* __restrict__ Ah, const __nv_bfloat16* __restrict__ Al,
    const __nv_bfloat16* __restrict__ Bh, const __nv_bfloat16* __restrict__ Bl,
    uint32_t sb, int tid, int m0, int n0, int c)
{
    const uint32_t st = sb + (uint32_t)(c % 3) * STAGE_BYTES;
    const int kc = c * GBK;
#pragma unroll
    for (int u = 0; u < 8; ++u) {
        int f = tid + u * 256;
        uint32_t dst; const __nv_bfloat16* gp;
        if (f < 1024) {
            int rel = f & 511;
            int row = rel >> 2, ch = rel & 3;
            const __nv_bfloat16* base = (f < 512) ? Ah : Al;
            gp  = base + (size_t)(m0 + row) * EMB + kc + ch * 8;
            dst = st + ((f < 512) ? OFF_AH : OFF_AL) + swz64(row, ch * 16);
        } else {
            int rel = f & 511;
            int row = rel >> 2, ch = rel & 3;
            const __nv_bfloat16* base = (f < 1536) ? Bh : Bl;
            gp  = base + (size_t)(n0 + row) * EMB + kc + ch * 8;
            dst = st + ((f < 1536) ? OFF_BH : OFF_BL) + swz64(row, ch * 16);
        }
        CP_ASYNC16(dst, gp);
    }
    CP_COMMIT();
}

__device__ __forceinline__ void gemm_core(
    const __nv_bfloat16* __restrict__ Ah, const __nv_bfloat16* __restrict__ Al,
    const __nv_bfloat16* __restrict__ Bh, const __nv_bfloat16* __restrict__ Bl,
    uint32_t sb, int tid, int lane, int wid, int m0, int n0,
    float (&acc)[2][8][4])
{
#pragma unroll
    for (int i = 0; i < 2; ++i)
#pragma unroll
        for (int j = 0; j < 8; ++j)
#pragma unroll
            for (int r = 0; r < 4; ++r) acc[i][j][r] = 0.0f;

    const int warp_m = wid & 3;      // 4 groups x 32 rows
    const int warp_n = wid >> 2;     // 2 groups x 64 cols
    const int a_row = warp_m * 32 + ((lane >> 3) & 1) * 8 + (lane & 7);
    const int a_cb  = (lane >> 4) * 16;
    const int b_row = warp_n * 64 + ((lane >> 4) & 1) * 8 + (lane & 7);
    const int b_cb  = ((lane >> 3) & 1) * 16;

    gemm_issue_stage(Ah, Al, Bh, Bl, sb, tid, m0, n0, 0);
    gemm_issue_stage(Ah, Al, Bh, Bl, sb, tid, m0, n0, 1);

    const int NC = EMB / GBK;   // 64
    for (int c = 0; c < NC; ++c) {
        CP_WAIT1();
        __syncthreads();   // chunk c arrived AND all warps done reading chunk c-1
        if (c + 2 < NC) gemm_issue_stage(Ah, Al, Bh, Bl, sb, tid, m0, n0, c + 2);
        else CP_COMMIT();

        const uint32_t st = sb + (uint32_t)(c % 3) * STAGE_BYTES;
#pragma unroll
        for (int ks = 0; ks < 2; ++ks) {
            const int cb = ks * 32;
            uint32_t a[2][2][4];
#pragma unroll
            for (int i = 0; i < 2; ++i) {
                ldsm_x4(a[0][i][0], a[0][i][1], a[0][i][2], a[0][i][3],
                        st + OFF_AH + swz64(a_row + i * 16, a_cb + cb));
                ldsm_x4(a[1][i][0], a[1][i][1], a[1][i][2], a[1][i][3],
                        st + OFF_AL + swz64(a_row + i * 16, a_cb + cb));
            }
            uint32_t b[8][2];
#pragma unroll
            for (int q = 0; q < 4; ++q)
                ldsm_x4(b[2*q][0], b[2*q][1], b[2*q+1][0], b[2*q+1][1],
                        st + OFF_BH + swz64(b_row + q * 16, b_cb + cb));
#pragma unroll
            for (int i = 0; i < 2; ++i)
#pragma unroll
                for (int j = 0; j < 8; ++j) {
                    mma16816(acc[i][j], a[0][i], b[j]);
                    mma16816(acc[i][j], a[1][i], b[j]);
                }
#pragma unroll
            for (int q = 0; q < 4; ++q)
                ldsm_x4(b[2*q][0], b[2*q][1], b[2*q+1][0], b[2*q+1][1],
                        st + OFF_BL + swz64(b_row + q * 16, b_cb + cb));
#pragma unroll
            for (int i = 0; i < 2; ++i)
#pragma unroll
                for (int j = 0; j < 8; ++j)
                    mma16816(acc[i][j], a[0][i], b[j]);
        }
        // no trailing sync: next iteration's leading sync provides the WAR guard
    }
}

// ---- batched Q/K/V projection GEMM with fused RoPE+split epilogue -------------
// Column block = exactly one head (GBN == HD).
#define SPAD 132

__global__ __launch_bounds__(256, 2)
void gemm_qkv(const float* __restrict__ cosT, const float* __restrict__ sinT)
{
    extern __shared__ __align__(128) char smc[];
    const uint32_t sb = smem_u32(smc);
    const int tid = threadIdx.x, lane = tid & 31, wid = tid >> 5;
    const int m0 = blockIdx.y * GBM, n0 = blockIdx.x * GBN;
    const int z = blockIdx.z;

    float acc[2][8][4];
    gemm_core(g_AH[z], g_AL[z], g_BH[z], g_BL[z], sb, tid, lane, wid, m0, n0, acc);

    const int warp_m = wid & 3, warp_n = wid >> 2;
    const int r0q = lane >> 2, c0q = (lane & 3) * 2;

    if (z == 2) {
        const int h = n0 >> 7;   // one head per column block
#pragma unroll
        for (int i = 0; i < 2; ++i) {
#pragma unroll
            for (int j = 0; j < 8; ++j) {
                int mrow0 = m0 + warp_m * 32 + i * 16 + r0q;
                int dc    = warp_n * 64 + j * 8 + c0q;
                int b0 = mrow0 >> 10, s0 = mrow0 & 1023;
                int b1 = (mrow0 + 8) >> 10, s1 = (mrow0 + 8) & 1023;
                size_t o0 = (((size_t)(b0 * NH + h)) * SEQ + s0) * HD + dc;
                size_t o1 = (((size_t)(b1 * NH + h)) * SEQ + s1) * HD + dc;
                uint32_t h0 = packbf(acc[i][j][0], acc[i][j][1]);
                uint32_t h1 = packbf(acc[i][j][2], acc[i][j][3]);
                float2 f0 = __bfloat1622float2(*(__nv_bfloat162*)&h0);
                float2 f1 = __bfloat1622float2(*(__nv_bfloat162*)&h1);
                uint32_t l0 = packbf(acc[i][j][0] - f0.x, acc[i][j][1] - f0.y);
                uint32_t l1 = packbf(acc[i][j][2] - f1.x, acc[i][j][3] - f1.y);
                *(uint32_t*)(g_Vh + o0) = h0;
                *(uint32_t*)(g_Vh + o1) = h1;
                *(uint32_t*)(g_Vl + o0) = l0;
                *(uint32_t*)(g_Vl + o1) = l1;
            }
        }
    } else {
        float* stile = (float*)smc;   // [128][SPAD] = 67584 B <= 98304
        __syncthreads();
#pragma unroll
        for (int i = 0; i < 2; ++i) {
#pragma unroll
            for (int j = 0; j < 8; ++j) {
                int lr0 = warp_m * 32 + i * 16 + r0q;
                int lc  = warp_n * 64 + j * 8 + c0q;
                stile[lr0 * SPAD + lc]           = acc[i][j][0];
                stile[lr0 * SPAD + lc + 1]       = acc[i][j][1];
                stile[(lr0 + 8) * SPAD + lc]     = acc[i][j][2];
                stile[(lr0 + 8) * SPAD + lc + 1] = acc[i][j][3];
            }
        }
        __syncthreads();

        __nv_bfloat16* H = (z == 0) ? g_QH : g_KH;
        __nv_bfloat16* L = (z == 0) ? g_QL : g_KL;
        const int h = n0 >> 7;
#pragma unroll
        for (int it = 0; it < 16; ++it) {
            int slot = tid + it * 256;        // 4096 = 128 rows x 32 dpairs
            int t  = slot & 31;
            int lr = slot >> 5;
            int d0 = t * 2;
            int gm = m0 + lr;
            int b  = gm >> 10, s = gm & 1023;
            float2 cc = *(const float2*)(cosT + s * HD + d0);
            float2 ss = *(const float2*)(sinT + s * HD + d0);
            const float* row = stile + lr * SPAD;
            float x1a = row[d0],      x1b = row[d0 + 1];
            float x2a = row[d0 + 64], x2b = row[d0 + 65];
            float r1a = x1a * cc.x - x2a * ss.x, r1b = x1b * cc.y - x2b * ss.y;
            float r2a = x2a * cc.x + x1a * ss.x, r2b = x2b * cc.y + x1b * ss.y;
            uint32_t h1 = packbf(r1a, r1b), h2 = packbf(r2a, r2b);
            float2 f1 = __bfloat1622float2(*(__nv_bfloat162*)&h1);
            float2 f2 = __bfloat1622float2(*(__nv_bfloat162*)&h2);
            uint32_t l1 = packbf(r1a - f1.x, r1b - f1.y);
            uint32_t l2 = packbf(r2a - f2.x, r2b - f2.y);
            size_t o = (((size_t)(b * NH + h)) * SEQ + s) * HD + d0;
            *(uint32_t*)(H + o)      = h1;
            *(uint32_t*)(L + o)      = l1;
            *(uint32_t*)(H + o + 64) = h2;
            *(uint32_t*)(L + o + 64) = l2;
        }
    }
}

// ---- output projection GEMM ----
__global__ __launch_bounds__(256, 2)
void gemm_out(float* __restrict__ Y)
{
    extern __shared__ __align__(128) char smc[];
    const uint32_t sb = smem_u32(smc);
    const int tid = threadIdx.x, lane = tid & 31, wid = tid >> 5;
    const int m0 = blockIdx.y * GBM, n0 = blockIdx.x * GBN;

    float acc[2][8][4];
    gemm_core(g_AH[2], g_AL[2], g_BH[3], g_BL[3], sb, tid, lane, wid, m0, n0, acc);

    const int warp_m = wid & 3, warp_n = wid >> 2;
    const int r0q = lane >> 2, c0q = (lane & 3) * 2;
#pragma unroll
    for (int i = 0; i < 2; ++i) {
#pragma unroll
        for (int j = 0; j < 8; ++j) {
            int mrow0 = m0 + warp_m * 32 + i * 16 + r0q;
            int ncol  = n0 + warp_n * 64 + j * 8 + c0q;
            *(float2*)(Y + (size_t)mrow0 * EMB + ncol) =
                make_float2(acc[i][j][0], acc[i][j][1]);
            *(float2*)(Y + (size_t)(mrow0 + 8) * EMB + ncol) =
                make_float2(acc[i][j][2], acc[i][j][3]);
        }
    }
}

// =================================================================================
// Tensor-core flash attention v3 (R12 proven): 64-row Q tiles, 128 thr, 2 CTAs/SM.
// =================================================================================
#define A3_QH 0u
#define A3_QL 16384u
#define A3_KV 32768u
#define A3_PH 98304u
#define A3_PL 106496u
#define A3_SMEM 114688

__global__ __launch_bounds__(128, 2)
void attn_tc3()
{
    extern __shared__ __align__(128) char smc[];
    const uint32_t sb = smem_u32(smc);
    const int tid = threadIdx.x, lane = tid & 31, w = tid >> 5;
    const int qt = 15 - blockIdx.x;
    const int bh = blockIdx.y;
    const int q0 = qt * 64;
    const float SC = 0.12751743f;

    {
        const size_t gbase = ((size_t)bh * SEQ + q0) * HD;
#pragma unroll
        for (int u = 0; u < 16; ++u) {
            int f = tid + u * 128;
            int rel = f & 1023;
            int row = rel >> 4, ch = rel & 15;
            const __nv_bfloat16* gp = ((f < 1024) ? g_QH : g_QL)
                                      + gbase + (size_t)row * HD + ch * 8;
            uint32_t dst = sb + ((f < 1024) ? A3_QH : A3_QL) + swz256(row, ch * 16);
            CP_ASYNC16(dst, gp);
        }
        CP_COMMIT();
    }

    auto issue_kv = [&](int kt) {
        const size_t gbase = ((size_t)bh * SEQ + kt * 64) * HD;
#pragma unroll
        for (int u = 0; u < 32; ++u) {
            int f = tid + u * 128;
            int rel = f & 1023;
            int row = rel >> 4, ch = rel & 15;
            int arr = f >> 10;
            const __nv_bfloat16* gb = (arr == 0) ? g_KH : (arr == 1) ? g_KL
                                     : (arr == 2) ? g_Vh : g_Vl;
            const __nv_bfloat16* gp = gb + gbase + (size_t)row * HD + ch * 8;
            uint32_t dst = sb + A3_KV + (uint32_t)arr * 16384u + swz256(row, ch * 16);
            CP_ASYNC16(dst, gp);
        }
        CP_COMMIT();
    };

    const int nkt = qt + 1;
    issue_kv(0);

    const int rA = w * 16 + (lane >> 2);
    const int qa = q0 + rA, qb = qa + 8;
    float O[16][4];
#pragma unroll
    for (int j = 0; j < 16; ++j)
#pragma unroll
        for (int r = 0; r < 4; ++r) O[j][r] = 0.0f;
    float m_a = -1e30f, m_b = -1e30f, l_a = 0.0f, l_b = 0.0f;

    const int qa_row = w * 16 + ((lane >> 3) & 1) * 8 + (lane & 7);
    const int qa_cb  = (lane >> 4) * 16;
    const int kb_row = ((lane >> 4) & 1) * 8 + (lane & 7);
    const int kb_cb  = ((lane >> 3) & 1) * 16;
    const int vt_row = ((lane >> 3) & 1) * 8 + (lane & 7);
    const int vt_cb  = (lane >> 4) * 16;
    const int p_row = w * 16 + ((lane >> 3) & 1) * 8 + (lane & 7);
    const int p_ch  = (lane >> 4);

    for (int kt = 0; kt < nkt; ++kt) {
        CP_WAIT0();
        __syncthreads();
        const uint32_t st = sb + A3_KV;

        float sa[8][4];
#pragma unroll
        for (int j = 0; j < 8; ++j)
#pragma unroll
            for (int r = 0; r < 4; ++r) sa[j][r] = 0.0f;

#pragma unroll
        for (int kk = 0; kk < 8; ++kk) {
            const int cb = kk * 32;
            uint32_t aH[4], aL[4];
            ldsm_x4(aH[0], aH[1], aH[2], aH[3], sb + A3_QH + swz256(qa_row, qa_cb + cb));
            ldsm_x4(aL[0], aL[1], aL[2], aL[3], sb + A3_QL + swz256(qa_row, qa_cb + cb));
#pragma unroll
            for (int g = 0; g < 4; ++g) {
                uint32_t b[4];
                ldsm_x4(b[0], b[1], b[2], b[3],
                        st + swz256(g * 16 + kb_row, kb_cb + cb));
                mma16816(sa[2*g],   aH, b);
                mma16816(sa[2*g+1], aH, b + 2);
                mma16816(sa[2*g],   aL, b);
                mma16816(sa[2*g+1], aL, b + 2);
                ldsm_x4(b[0], b[1], b[2], b[3],
                        st + 16384u + swz256(g * 16 + kb_row, kb_cb + cb));
                mma16816(sa[2*g],   aH, b);
                mma16816(sa[2*g+1], aH, b + 2);
            }
        }

        if (kt * 64 + 63 > q0 + w * 16) {
            const int colb = kt * 64 + (lane & 3) * 2;
#pragma unroll
            for (int j = 0; j < 8; ++j) {
                int c0 = colb + j * 8, c1 = c0 + 1;
                if (c0 > qa) sa[j][0] = -1e30f;
                if (c1 > qa) sa[j][1] = -1e30f;
                if (c0 > qb) sa[j][2] = -1e30f;
                if (c1 > qb) sa[j][3] = -1e30f;
            }
        }

        float mxa = sa[0][0], mxb = sa[0][2];
#pragma unroll
        for (int j = 0; j < 8; ++j) {
            mxa = fmaxf(mxa, fmaxf(sa[j][0], sa[j][1]));
            mxb = fmaxf(mxb, fmaxf(sa[j][2], sa[j][3]));
        }
        mxa = fmaxf(mxa, __shfl_xor_sync(0xffffffffu, mxa, 1));
        mxa = fmaxf(mxa, __shfl_xor_sync(0xffffffffu, mxa, 2));
        mxb = fmaxf(mxb, __shfl_xor_sync(0xffffffffu, mxb, 1));
        mxb = fmaxf(mxb, __shfl_xor_sync(0xffffffffu, mxb, 2));
        float mna = fmaxf(m_a, mxa), mnb = fmaxf(m_b, mxb);
        float alpha_a = exp2s((m_a - mna) * SC);
        float alpha_b = exp2s((m_b - mnb) * SC);
        m_a = mna; m_b = mnb;

        float suma = 0.0f, sumb = 0.0f;
#pragma unroll
        for (int j = 0; j < 8; ++j) {
            sa[j][0] = exp2s((sa[j][0] - mna) * SC);
            sa[j][1] = exp2s((sa[j][1] - mna) * SC);
            sa[j][2] = exp2s((sa[j][2] - mnb) * SC);
            sa[j][3] = exp2s((sa[j][3] - mnb) * SC);
            suma += sa[j][0] + sa[j][1];
            sumb += sa[j][2] + sa[j][3];
        }
        suma += __shfl_xor_sync(0xffffffffu, suma, 1);
        suma += __shfl_xor_sync(0xffffffffu, suma, 2);
        sumb += __shfl_xor_sync(0xffffffffu, sumb, 1);
        sumb += __shfl_xor_sync(0xffffffffu, sumb, 2);
        l_a = l_a * alpha_a + suma;
        l_b = l_b * alpha_b + sumb;
#pragma unroll
        for (int j = 0; j < 16; ++j) {
            O[j][0] *= alpha_a; O[j][1] *= alpha_a;
            O[j][2] *= alpha_b; O[j][3] *= alpha_b;
        }

        const int rB = rA + 8;
        const int wb = (lane & 3) * 4;
#pragma unroll
        for (int j = 0; j < 8; ++j) {
            uint32_t hA = packbf(sa[j][0], sa[j][1]);
            uint32_t hB = packbf(sa[j][2], sa[j][3]);
            float2 fA = __bfloat1622float2(*(__nv_bfloat162*)&hA);
            float2 fB = __bfloat1622float2(*(__nv_bfloat162*)&hB);
            uint32_t lA = packbf(sa[j][0] - fA.x, sa[j][1] - fA.y);
            uint32_t lB = packbf(sa[j][2] - fB.x, sa[j][3] - fB.y);
            *(uint32_t*)(smc + A3_PH + rA*128 + ((j ^ (rA & 7)) * 16) + wb) = hA;
            *(uint32_t*)(smc + A3_PH + rB*128 + ((j ^ (rB & 7)) * 16) + wb) = hB;
            *(uint32_t*)(smc + A3_PL + rA*128 + ((j ^ (rA & 7)) * 16) + wb) = lA;
            *(uint32_t*)(smc + A3_PL + rB*128 + ((j ^ (rB & 7)) * 16) + wb) = lB;
        }
        __syncwarp();

        uint32_t aPh[4][4], aPl[4][4];
#pragma unroll
        for (int k2 = 0; k2 < 4; ++k2) {
            int ch = k2 * 2 + p_ch;
            uint32_t offH = A3_PH + (uint32_t)(p_row*128 + ((ch ^ (p_row & 7)) * 16));
            uint32_t offL = A3_PL + (uint32_t)(p_row*128 + ((ch ^ (p_row & 7)) * 16));
            ldsm_x4(aPh[k2][0], aPh[k2][1], aPh[k2][2], aPh[k2][3], sb + offH);
            ldsm_x4(aPl[k2][0], aPl[k2][1], aPl[k2][2], aPl[k2][3], sb + offL);
        }

#pragma unroll
        for (int g = 0; g < 8; ++g) {
#pragma unroll
            for (int k2 = 0; k2 < 4; ++k2) {
                uint32_t b[4];
                ldsm_x4_t(b[0], b[1], b[2], b[3],
                          st + 32768u + swz256(k2 * 16 + vt_row, g * 32 + vt_cb));
                mma16816(O[2*g],   aPh[k2], b);
                mma16816(O[2*g+1], aPh[k2], b + 2);
                mma16816(O[2*g],   aPl[k2], b);
                mma16816(O[2*g+1], aPl[k2], b + 2);
                ldsm_x4_t(b[0], b[1], b[2], b[3],
                          st + 49152u + swz256(k2 * 16 + vt_row, g * 32 + vt_cb));
                mma16816(O[2*g],   aPh[k2], b);
                mma16816(O[2*g+1], aPh[k2], b + 2);
            }
        }

        __syncthreads();
        if (kt + 1 < nkt) issue_kv(kt + 1);
    }

    const int b = bh >> 4, h = bh & 15;
    const float inva = 1.0f / l_a, invb = 1.0f / l_b;
    const size_t base_a = ((size_t)(b * SEQ + qa)) * EMB + h * HD;
    const size_t base_b = ((size_t)(b * SEQ + qb)) * EMB + h * HD;
#pragma unroll
    for (int j = 0; j < 16; ++j) {
        int dcol = j * 8 + (lane & 3) * 2;
        float oa0 = O[j][0] * inva, oa1 = O[j][1] * inva;
        float ob0 = O[j][2] * invb, ob1 = O[j][3] * invb;
        uint32_t ha = packbf(oa0, oa1);
        uint32_t hb = packbf(ob0, ob1);
        float2 fa = __bfloat1622float2(*(__nv_bfloat162*)&ha);
        float2 fb = __bfloat1622float2(*(__nv_bfloat162*)&hb);
        uint32_t la = packbf(oa0 - fa.x, oa1 - fa.y);
        uint32_t lb = packbf(ob0 - fb.x, ob1 - fb.y);
        *(uint32_t*)(g_AH[2] + base_a + dcol) = ha;
        *(uint32_t*)(g_AL[2] + base_a + dcol) = la;
        *(uint32_t*)(g_AH[2] + base_b + dcol) = hb;
        *(uint32_t*)(g_AL[2] + base_b + dcol) = lb;
    }
}

// =================================================================================
extern "C" void kernel_launch(void* const* d_in, const int* in_sizes, int n_in,
                              void* d_out, int out_size)
{
    const float* query = (const float*)d_in[0];
    const float* key   = (const float*)d_in[1];
    const float* value = (const float*)d_in[2];
    const float* cosT  = (const float*)d_in[4];
    const float* sinT  = (const float*)d_in[5];
    const float* Wq    = (const float*)d_in[6];
    const float* Wk    = (const float*)d_in[7];
    const float* Wv    = (const float*)d_in[8];
    const float* Wo    = (const float*)d_in[9];

    __nv_bfloat16 *pAH0, *pAL0, *pAH1, *pAL1, *pAH2, *pAL2;
    __nv_bfloat16 *pBH0, *pBL0, *pBH1, *pBL1, *pBH2, *pBL2, *pBH3, *pBL3;
    cudaGetSymbolAddress((void**)&pAH0, g_AH);
    cudaGetSymbolAddress((void**)&pAL0, g_AL);
    cudaGetSymbolAddress((void**)&pBH0, g_BH);
    cudaGetSymbolAddress((void**)&pBL0, g_BL);
    const size_t NA = (size_t)MROWS * EMB;
    const size_t NB = (size_t)EMB * EMB;
    pAH1 = pAH0 + NA; pAH2 = pAH0 + 2 * NA;
    pAL1 = pAL0 + NA; pAL2 = pAL0 + 2 * NA;
    pBH1 = pBH0 + NB; pBH2 = pBH0 + 2 * NB; pBH3 = pBH0 + 3 * NB;
    pBL1 = pBL0 + NB; pBL2 = pBL0 + 2 * NB; pBL3 = pBL0 + 3 * NB;

    cudaFuncSetAttribute(gemm_qkv, cudaFuncAttributeMaxDynamicSharedMemorySize, GEMM_SMEM);
    cudaFuncSetAttribute(gemm_out, cudaFuncAttributeMaxDynamicSharedMemorySize, GEMM_SMEM);
    cudaFuncSetAttribute(attn_tc3, cudaFuncAttributeMaxDynamicSharedMemorySize, A3_SMEM);

    const int nX4 = MROWS * EMB / 4;
    const int nW4 = EMB * EMB / 4;

    split_batch<<<dim3(nX4 / 256, 3), 256>>>(
        query, key, value, query,
        pAH0, pAL0, pAH1, pAL1, pAH2, pAL2, pAH0, pAL0, nX4);
    split_batch<<<dim3(nW4 / 256, 4), 256>>>(
        Wq, Wk, Wv, Wo,
        pBH0, pBL0, pBH1, pBL1, pBH2, pBL2, pBH3, pBL3, nW4);

    // Q/K/V projections (128x128 tiles, 2 CTAs/SM) with fused RoPE+split epilogues
    gemm_qkv<<<dim3(EMB / GBN, MROWS / GBM, 3), 256, GEMM_SMEM>>>(cosT, sinT);

    // tensor-core flash attention v3
    attn_tc3<<<dim3(16, 64), 128, A3_SMEM>>>();

    // output projection
    gemm_out<<<dim3(EMB / GBN, MROWS / GBM), 256, GEMM_SMEM>>>((float*)d_out);
}

// round 14
// speedup vs baseline: 1.6932x; 1.0084x over previous
#include <cuda_runtime.h>
#include <cuda_bf16.h>
#include <math.h>
#include <stdint.h>

#define BATCH 4
#define SEQ   1024
#define EMB   2048
#define NH    16
#define HD    128
#define MROWS (BATCH*SEQ)   /* 4096 */

// ---------------- scratch (device globals; no allocation allowed) ----------------
__device__ __nv_bfloat16 g_AH[3][(size_t)MROWS*EMB];   // [0]=query [1]=key [2]=value->ctx
__device__ __nv_bfloat16 g_AL[3][(size_t)MROWS*EMB];
__device__ __nv_bfloat16 g_BH[4][(size_t)EMB*EMB];     // Wq Wk Wv Wo
__device__ __nv_bfloat16 g_BL[4][(size_t)EMB*EMB];
__device__ __nv_bfloat16 g_QH[(size_t)MROWS*EMB];
__device__ __nv_bfloat16 g_QL[(size_t)MROWS*EMB];
__device__ __nv_bfloat16 g_KH[(size_t)MROWS*EMB];
__device__ __nv_bfloat16 g_KL[(size_t)MROWS*EMB];
__device__ __nv_bfloat16 g_Vh[(size_t)MROWS*EMB];
__device__ __nv_bfloat16 g_Vl[(size_t)MROWS*EMB];

// ======================= portable PTX helpers (sm_80+) ===========================
__device__ __forceinline__ uint32_t smem_u32(const void* p) {
    uint32_t a;
    asm("{ .reg .u64 t; cvta.to.shared.u64 t, %1; cvt.u32.u64 %0, t; }" : "=r"(a) : "l"(p));
    return a;
}
#define CP_ASYNC16(dst, src) \
    asm volatile("cp.async.cg.shared.global [%0], [%1], 16;" :: "r"(dst), "l"(src) : "memory")
#define CP_COMMIT()   asm volatile("cp.async.commit_group;" ::: "memory")
#define CP_WAIT0()    asm volatile("cp.async.wait_group 0;" ::: "memory")
#define CP_WAIT1()    asm volatile("cp.async.wait_group 1;" ::: "memory")

__device__ __forceinline__ void ldsm_x4(uint32_t& r0, uint32_t& r1, uint32_t& r2,
                                        uint32_t& r3, uint32_t addr) {
    asm volatile("ldmatrix.sync.aligned.m8n8.x4.shared.b16 {%0,%1,%2,%3}, [%4];"
                 : "=r"(r0), "=r"(r1), "=r"(r2), "=r"(r3) : "r"(addr));
}
__device__ __forceinline__ void ldsm_x4_t(uint32_t& r0, uint32_t& r1, uint32_t& r2,
                                          uint32_t& r3, uint32_t addr) {
    asm volatile("ldmatrix.sync.aligned.m8n8.x4.trans.shared.b16 {%0,%1,%2,%3}, [%4];"
                 : "=r"(r0), "=r"(r1), "=r"(r2), "=r"(r3) : "r"(addr));
}
__device__ __forceinline__ void mma16816(float* d, const uint32_t* a, const uint32_t* b) {
    asm volatile("mma.sync.aligned.m16n8k16.row.col.f32.bf16.bf16.f32 "
                 "{%0,%1,%2,%3}, {%4,%5,%6,%7}, {%8,%9}, {%0,%1,%2,%3};"
                 : "+f"(d[0]), "+f"(d[1]), "+f"(d[2]), "+f"(d[3])
                 : "r"(a[0]), "r"(a[1]), "r"(a[2]), "r"(a[3]), "r"(b[0]), "r"(b[1]));
}
__device__ __forceinline__ uint32_t swz64(int row, int colByte) {
    return (uint32_t)(row * 64 + ((((colByte >> 4) ^ (row >> 1)) & 3) * 16));
}
__device__ __forceinline__ uint32_t swz256(int row, int cb) {
    int ch = cb >> 4;
    int sw = (ch & 8) | ((ch ^ row) & 7);
    return (uint32_t)(row * 256 + sw * 16);
}
__device__ __forceinline__ uint32_t packbf(float lo, float hi) {
    __nv_bfloat162 t = __floats2bfloat162_rn(lo, hi);
    return *(uint32_t*)&t;
}
__device__ __forceinline__ float exp2s(float x) {
    x = fmaxf(x, -126.0f);
    int i = __float2int_rn(x);
    float f = x - (float)i;
    float p = 0.00961812911f;
    p = fmaf(p, f, 0.0555041087f);
    p = fmaf(p, f, 0.240226507f);
    p = fmaf(p, f, 0.693147182f);
    p = fmaf(p, f, 1.0f);
    return p * __int_as_float((i + 127) << 23);
}

// ======================= batched split fp32 -> bf16 hi/lo ========================
__global__ __launch_bounds__(256)
void split_batch(const float* __restrict__ a0, const float* __restrict__ a1,
                 const float* __restrict__ a2, const float* __restrict__ a3,
                 __nv_bfloat16* __restrict__ h0, __nv_bfloat16* __restrict__ l0,
                 __nv_bfloat16* __restrict__ h1, __nv_bfloat16* __restrict__ l1,
                 __nv_bfloat16* __restrict__ h2, __nv_bfloat16* __restrict__ l2,
                 __nv_bfloat16* __restrict__ h3, __nv_bfloat16* __restrict__ l3,
                 int n4)
{
    int t = blockIdx.y;
    const float* X = (t == 0) ? a0 : (t == 1) ? a1 : (t == 2) ? a2 : a3;
    __nv_bfloat16* Hi = (t == 0) ? h0 : (t == 1) ? h1 : (t == 2) ? h2 : h3;
    __nv_bfloat16* Lo = (t == 0) ? l0 : (t == 1) ? l1 : (t == 2) ? l2 : l3;

    int i = blockIdx.x * 256 + threadIdx.x;
    if (i >= n4) return;
    float4 v = ((const float4*)X)[i];
    uint32_t h01 = packbf(v.x, v.y);
    uint32_t h23 = packbf(v.z, v.w);
    float2 f01 = __bfloat1622float2(*(__nv_bfloat162*)&h01);
    float2 f23 = __bfloat1622float2(*(__nv_bfloat162*)&h23);
    uint32_t l01 = packbf(v.x - f01.x, v.y - f01.y);
    uint32_t l23 = packbf(v.z - f23.x, v.w - f23.y);
    *(uint2*)(Hi + (size_t)i * 4) = make_uint2(h01, h23);
    *(uint2*)(Lo + (size_t)i * 4) = make_uint2(l01, l23);
}

// ======================= split-bf16 GEMM core v2 (R13 proven) ====================
#define GBM 128
#define GBN 128
#define GBK 32
#define OFF_AH 0
#define OFF_AL 8192
#define OFF_BH 16384
#define OFF_BL 24576
#define STAGE_BYTES 32768
#define GEMM_SMEM (3 * STAGE_BYTES)   /* 98304 */

__device__ __forceinline__ void gemm_issue_stage(
    const __nv_bfloat16* __restrict__ Ah, const __nv_bfloat16* __restrict__ Al,
    const __nv_bfloat16* __restrict__ Bh, const __nv_bfloat16* __restrict__ Bl,
    uint32_t sb, int tid, int m0, int n0, int c)
{
    const uint32_t st = sb + (uint32_t)(c % 3) * STAGE_BYTES;
    const int kc = c * GBK;
#pragma unroll
    for (int u = 0; u < 8; ++u) {
        int f = tid + u * 256;
        uint32_t dst; const __nv_bfloat16* gp;
        if (f < 1024) {
            int rel = f & 511;
            int row = rel >> 2, ch = rel & 3;
            const __nv_bfloat16* base = (f < 512) ? Ah : Al;
            gp  = base + (size_t)(m0 + row) * EMB + kc + ch * 8;
            dst = st + ((f < 512) ? OFF_AH : OFF_AL) + swz64(row, ch * 16);
        } else {
            int rel = f & 511;
            int row = rel >> 2, ch = rel & 3;
            const __nv_bfloat16* base = (f < 1536) ? Bh : Bl;
            gp  = base + (size_t)(n0 + row) * EMB + kc + ch * 8;
            dst = st + ((f < 1536) ? OFF_BH : OFF_BL) + swz64(row, ch * 16);
        }
        CP_ASYNC16(dst, gp);
    }
    CP_COMMIT();
}

__device__ __forceinline__ void gemm_core(
    const __nv_bfloat16* __restrict__ Ah, const __nv_bfloat16* __restrict__ Al,
    const __nv_bfloat16* __restrict__ Bh, const __nv_bfloat16* __restrict__ Bl,
    uint32_t sb, int tid, int lane, int wid, int m0, int n0,
    float (&acc)[2][8][4])
{
#pragma unroll
    for (int i = 0; i < 2; ++i)
#pragma unroll
        for (int j = 0; j < 8; ++j)
#pragma unroll
            for (int r = 0; r < 4; ++r) acc[i][j][r] = 0.0f;

    const int warp_m = wid & 3;
    const int warp_n = wid >> 2;
    const int a_row = warp_m * 32 + ((lane >> 3) & 1) * 8 + (lane & 7);
    const int a_cb  = (lane >> 4) * 16;
    const int b_row = warp_n * 64 + ((lane >> 4) & 1) * 8 + (lane & 7);
    const int b_cb  = ((lane >> 3) & 1) * 16;

    gemm_issue_stage(Ah, Al, Bh, Bl, sb, tid, m0, n0, 0);
    gemm_issue_stage(Ah, Al, Bh, Bl, sb, tid, m0, n0, 1);

    const int NC = EMB / GBK;   // 64
    for (int c = 0; c < NC; ++c) {
        CP_WAIT1();
        __syncthreads();
        if (c + 2 < NC) gemm_issue_stage(Ah, Al, Bh, Bl, sb, tid, m0, n0, c + 2);
        else CP_COMMIT();

        const uint32_t st = sb + (uint32_t)(c % 3) * STAGE_BYTES;
#pragma unroll
        for (int ks = 0; ks < 2; ++ks) {
            const int cb = ks * 32;
            uint32_t a[2][2][4];
#pragma unroll
            for (int i = 0; i < 2; ++i) {
                ldsm_x4(a[0][i][0], a[0][i][1], a[0][i][2], a[0][i][3],
                        st + OFF_AH + swz64(a_row + i * 16, a_cb + cb));
                ldsm_x4(a[1][i][0], a[1][i][1], a[1][i][2], a[1][i][3],
                        st + OFF_AL + swz64(a_row + i * 16, a_cb + cb));
            }
            uint32_t b[8][2];
#pragma unroll
            for (int q = 0; q < 4; ++q)
                ldsm_x4(b[2*q][0], b[2*q][1], b[2*q+1][0], b[2*q+1][1],
                        st + OFF_BH + swz64(b_row + q * 16, b_cb + cb));
#pragma unroll
            for (int i = 0; i < 2; ++i)
#pragma unroll
                for (int j = 0; j < 8; ++j) {
                    mma16816(acc[i][j], a[0][i], b[j]);
                    mma16816(acc[i][j], a[1][i], b[j]);
                }
#pragma unroll
            for (int q = 0; q < 4; ++q)
                ldsm_x4(b[2*q][0], b[2*q][1], b[2*q+1][0], b[2*q+1][1],
                        st + OFF_BL + swz64(b_row + q * 16, b_cb + cb));
#pragma unroll
            for (int i = 0; i < 2; ++i)
#pragma unroll
                for (int j = 0; j < 8; ++j)
                    mma16816(acc[i][j], a[0][i], b[j]);
        }
    }
}

// ---- batched Q/K/V projection GEMM with fused RoPE+split epilogue -------------
#define SPAD 132

__global__ __launch_bounds__(256, 2)
void gemm_qkv(const float* __restrict__ cosT, const float* __restrict__ sinT)
{
    extern __shared__ __align__(128) char smc[];
    const uint32_t sb = smem_u32(smc);
    const int tid = threadIdx.x, lane = tid & 31, wid = tid >> 5;
    const int m0 = blockIdx.y * GBM, n0 = blockIdx.x * GBN;
    const int z = blockIdx.z;

    float acc[2][8][4];
    gemm_core(g_AH[z], g_AL[z], g_BH[z], g_BL[z], sb, tid, lane, wid, m0, n0, acc);

    const int warp_m = wid & 3, warp_n = wid >> 2;
    const int r0q = lane >> 2, c0q = (lane & 3) * 2;

    if (z == 2) {
        const int h = n0 >> 7;
#pragma unroll
        for (int i = 0; i < 2; ++i) {
#pragma unroll
            for (int j = 0; j < 8; ++j) {
                int mrow0 = m0 + warp_m * 32 + i * 16 + r0q;
                int dc    = warp_n * 64 + j * 8 + c0q;
                int b0 = mrow0 >> 10, s0 = mrow0 & 1023;
                int b1 = (mrow0 + 8) >> 10, s1 = (mrow0 + 8) & 1023;
                size_t o0 = (((size_t)(b0 * NH + h)) * SEQ + s0) * HD + dc;
                size_t o1 = (((size_t)(b1 * NH + h)) * SEQ + s1) * HD + dc;
                uint32_t h0 = packbf(acc[i][j][0], acc[i][j][1]);
                uint32_t h1 = packbf(acc[i][j][2], acc[i][j][3]);
                float2 f0 = __bfloat1622float2(*(__nv_bfloat162*)&h0);
                float2 f1 = __bfloat1622float2(*(__nv_bfloat162*)&h1);
                uint32_t l0 = packbf(acc[i][j][0] - f0.x, acc[i][j][1] - f0.y);
                uint32_t l1 = packbf(acc[i][j][2] - f1.x, acc[i][j][3] - f1.y);
                *(uint32_t*)(g_Vh + o0) = h0;
                *(uint32_t*)(g_Vh + o1) = h1;
                *(uint32_t*)(g_Vl + o0) = l0;
                *(uint32_t*)(g_Vl + o1) = l1;
            }
        }
    } else {
        float* stile = (float*)smc;
        __syncthreads();
#pragma unroll
        for (int i = 0; i < 2; ++i) {
#pragma unroll
            for (int j = 0; j < 8; ++j) {
                int lr0 = warp_m * 32 + i * 16 + r0q;
                int lc  = warp_n * 64 + j * 8 + c0q;
                stile[lr0 * SPAD + lc]           = acc[i][j][0];
                stile[lr0 * SPAD + lc + 1]       = acc[i][j][1];
                stile[(lr0 + 8) * SPAD + lc]     = acc[i][j][2];
                stile[(lr0 + 8) * SPAD + lc + 1] = acc[i][j][3];
            }
        }
        __syncthreads();

        __nv_bfloat16* H = (z == 0) ? g_QH : g_KH;
        __nv_bfloat16* L = (z == 0) ? g_QL : g_KL;
        const int h = n0 >> 7;
#pragma unroll
        for (int it = 0; it < 16; ++it) {
            int slot = tid + it * 256;
            int t  = slot & 31;
            int lr = slot >> 5;
            int d0 = t * 2;
            int gm = m0 + lr;
            int b  = gm >> 10, s = gm & 1023;
            float2 cc = *(const float2*)(cosT + s * HD + d0);
            float2 ss = *(const float2*)(sinT + s * HD + d0);
            const float* row = stile + lr * SPAD;
            float x1a = row[d0],      x1b = row[d0 + 1];
            float x2a = row[d0 + 64], x2b = row[d0 + 65];
            float r1a = x1a * cc.x - x2a * ss.x, r1b = x1b * cc.y - x2b * ss.y;
            float r2a = x2a * cc.x + x1a * ss.x, r2b = x2b * cc.y + x1b * ss.y;
            uint32_t h1 = packbf(r1a, r1b), h2 = packbf(r2a, r2b);
            float2 f1 = __bfloat1622float2(*(__nv_bfloat162*)&h1);
            float2 f2 = __bfloat1622float2(*(__nv_bfloat162*)&h2);
            uint32_t l1 = packbf(r1a - f1.x, r1b - f1.y);
            uint32_t l2 = packbf(r2a - f2.x, r2b - f2.y);
            size_t o = (((size_t)(b * NH + h)) * SEQ + s) * HD + d0;
            *(uint32_t*)(H + o)      = h1;
            *(uint32_t*)(L + o)      = l1;
            *(uint32_t*)(H + o + 64) = h2;
            *(uint32_t*)(L + o + 64) = l2;
        }
    }
}

// ---- output projection GEMM ----
__global__ __launch_bounds__(256, 2)
void gemm_out(float* __restrict__ Y)
{
    extern __shared__ __align__(128) char smc[];
    const uint32_t sb = smem_u32(smc);
    const int tid = threadIdx.x, lane = tid & 31, wid = tid >> 5;
    const int m0 = blockIdx.y * GBM, n0 = blockIdx.x * GBN;

    float acc[2][8][4];
    gemm_core(g_AH[2], g_AL[2], g_BH[3], g_BL[3], sb, tid, lane, wid, m0, n0, acc);

    const int warp_m = wid & 3, warp_n = wid >> 2;
    const int r0q = lane >> 2, c0q = (lane & 3) * 2;
#pragma unroll
    for (int i = 0; i < 2; ++i) {
#pragma unroll
        for (int j = 0; j < 8; ++j) {
            int mrow0 = m0 + warp_m * 32 + i * 16 + r0q;
            int ncol  = n0 + warp_n * 64 + j * 8 + c0q;
            *(float2*)(Y + (size_t)mrow0 * EMB + ncol) =
                make_float2(acc[i][j][0], acc[i][j][1]);
            *(float2*)(Y + (size_t)(mrow0 + 8) * EMB + ncol) =
                make_float2(acc[i][j][2], acc[i][j][3]);
        }
    }
}

// =================================================================================
// Tensor-core flash attention v4: 64-row Q tiles, 128 thr, 2 CTAs/SM.
// Register P->A-fragment repack (no smem roundtrip); K/V loads issued in
// separate phases so the K(kt+1) load overlaps softmax+PV compute.
// smem: QH 16K | QL 16K | KH 16K | KL 16K | VH 16K | VL 16K = 96K
// =================================================================================
#define A4_QH 0u
#define A4_QL 16384u
#define A4_KV 32768u
#define A4_SMEM 98304

__global__ __launch_bounds__(128, 2)
void attn_tc4()
{
    extern __shared__ __align__(128) char smc[];
    const uint32_t sb = smem_u32(smc);
    const int tid = threadIdx.x, lane = tid & 31, w = tid >> 5;
    const int qt = 15 - blockIdx.x;
    const int bh = blockIdx.y;
    const int q0 = qt * 64;
    const float SC = 0.12751743f;   // log2(e)/sqrt(128)

    // ---- Q tile (64 rows, both splits) ----
    {
        const size_t gbase = ((size_t)bh * SEQ + q0) * HD;
#pragma unroll
        for (int u = 0; u < 16; ++u) {
            int f = tid + u * 128;
            int rel = f & 1023;
            int row = rel >> 4, ch = rel & 15;
            const __nv_bfloat16* gp = ((f < 1024) ? g_QH : g_QL)
                                      + gbase + (size_t)row * HD + ch * 8;
            uint32_t dst = sb + ((f < 1024) ? A4_QH : A4_QL) + swz256(row, ch * 16);
            CP_ASYNC16(dst, gp);
        }
        CP_COMMIT();
    }

    auto issue_k = [&](int kt) {
        const size_t gbase = ((size_t)bh * SEQ + kt * 64) * HD;
#pragma unroll
        for (int u = 0; u < 16; ++u) {
            int f = tid + u * 128;
            int rel = f & 1023;
            int row = rel >> 4, ch = rel & 15;
            const __nv_bfloat16* gb = (f < 1024) ? g_KH : g_KL;
            uint32_t dst = sb + A4_KV + ((f < 1024) ? 0u : 16384u) + swz256(row, ch * 16);
            CP_ASYNC16(dst, gb + gbase + (size_t)row * HD + ch * 8);
        }
        CP_COMMIT();
    };
    auto issue_v = [&](int kt) {
        const size_t gbase = ((size_t)bh * SEQ + kt * 64) * HD;
#pragma unroll
        for (int u = 0; u < 16; ++u) {
            int f = tid + u * 128;
            int rel = f & 1023;
            int row = rel >> 4, ch = rel & 15;
            const __nv_bfloat16* gb = (f < 1024) ? g_Vh : g_Vl;
            uint32_t dst = sb + A4_KV + ((f < 1024) ? 32768u : 49152u) + swz256(row, ch * 16);
            CP_ASYNC16(dst, gb + gbase + (size_t)row * HD + ch * 8);
        }
        CP_COMMIT();
    };

    const int nkt = qt + 1;
    issue_k(0);
    issue_v(0);

    const int rA = w * 16 + (lane >> 2);
    const int qa = q0 + rA, qb = qa + 8;
    float O[16][4];
#pragma unroll
    for (int j = 0; j < 16; ++j)
#pragma unroll
        for (int r = 0; r < 4; ++r) O[j][r] = 0.0f;
    float m_a = -1e30f, m_b = -1e30f, l_a = 0.0f, l_b = 0.0f;

    const int qa_row = w * 16 + ((lane >> 3) & 1) * 8 + (lane & 7);
    const int qa_cb  = (lane >> 4) * 16;
    const int kb_row = ((lane >> 4) & 1) * 8 + (lane & 7);
    const int kb_cb  = ((lane >> 3) & 1) * 16;
    const int vt_row = ((lane >> 3) & 1) * 8 + (lane & 7);
    const int vt_cb  = (lane >> 4) * 16;

    for (int kt = 0; kt < nkt; ++kt) {
        CP_WAIT0();
        __syncthreads();   // K(kt), V(kt) both resident
        const uint32_t st = sb + A4_KV;

        // ---- S = Q K^T (3-term split) ----
        float sa[8][4];
#pragma unroll
        for (int j = 0; j < 8; ++j)
#pragma unroll
            for (int r = 0; r < 4; ++r) sa[j][r] = 0.0f;

#pragma unroll
        for (int kk = 0; kk < 8; ++kk) {
            const int cb = kk * 32;
            uint32_t aH[4], aL[4];
            ldsm_x4(aH[0], aH[1], aH[2], aH[3], sb + A4_QH + swz256(qa_row, qa_cb + cb));
            ldsm_x4(aL[0], aL[1], aL[2], aL[3], sb + A4_QL + swz256(qa_row, qa_cb + cb));
#pragma unroll
            for (int g = 0; g < 4; ++g) {
                uint32_t b[4];
                ldsm_x4(b[0], b[1], b[2], b[3],
                        st + swz256(g * 16 + kb_row, kb_cb + cb));          // Kh
                mma16816(sa[2*g],   aH, b);
                mma16816(sa[2*g+1], aH, b + 2);
                mma16816(sa[2*g],   aL, b);
                mma16816(sa[2*g+1], aL, b + 2);
                ldsm_x4(b[0], b[1], b[2], b[3],
                        st + 16384u + swz256(g * 16 + kb_row, kb_cb + cb)); // Kl
                mma16816(sa[2*g],   aH, b);
                mma16816(sa[2*g+1], aH, b + 2);
            }
        }

        __syncthreads();               // all warps done reading K(kt)
        if (kt + 1 < nkt) issue_k(kt + 1);   // K load overlaps softmax + PV

        // ---- causal mask (only the diagonal tile triggers) ----
        if (kt * 64 + 63 > q0 + w * 16) {
            const int colb = kt * 64 + (lane & 3) * 2;
#pragma unroll
            for (int j = 0; j < 8; ++j) {
                int c0 = colb + j * 8, c1 = c0 + 1;
                if (c0 > qa) sa[j][0] = -1e30f;
                if (c1 > qa) sa[j][1] = -1e30f;
                if (c0 > qb) sa[j][2] = -1e30f;
                if (c1 > qb) sa[j][3] = -1e30f;
            }
        }

        // ---- online softmax (exp2 domain) ----
        float mxa = sa[0][0], mxb = sa[0][2];
#pragma unroll
        for (int j = 0; j < 8; ++j) {
            mxa = fmaxf(mxa, fmaxf(sa[j][0], sa[j][1]));
            mxb = fmaxf(mxb, fmaxf(sa[j][2], sa[j][3]));
        }
        mxa = fmaxf(mxa, __shfl_xor_sync(0xffffffffu, mxa, 1));
        mxa = fmaxf(mxa, __shfl_xor_sync(0xffffffffu, mxa, 2));
        mxb = fmaxf(mxb, __shfl_xor_sync(0xffffffffu, mxb, 1));
        mxb = fmaxf(mxb, __shfl_xor_sync(0xffffffffu, mxb, 2));
        float mna = fmaxf(m_a, mxa), mnb = fmaxf(m_b, mxb);
        float alpha_a = exp2s((m_a - mna) * SC);
        float alpha_b = exp2s((m_b - mnb) * SC);
        m_a = mna; m_b = mnb;

        float suma = 0.0f, sumb = 0.0f;
#pragma unroll
        for (int j = 0; j < 8; ++j) {
            sa[j][0] = exp2s((sa[j][0] - mna) * SC);
            sa[j][1] = exp2s((sa[j][1] - mna) * SC);
            sa[j][2] = exp2s((sa[j][2] - mnb) * SC);
            sa[j][3] = exp2s((sa[j][3] - mnb) * SC);
            suma += sa[j][0] + sa[j][1];
            sumb += sa[j][2] + sa[j][3];
        }
        suma += __shfl_xor_sync(0xffffffffu, suma, 1);
        suma += __shfl_xor_sync(0xffffffffu, suma, 2);
        sumb += __shfl_xor_sync(0xffffffffu, sumb, 1);
        sumb += __shfl_xor_sync(0xffffffffu, sumb, 2);
        l_a = l_a * alpha_a + suma;
        l_b = l_b * alpha_b + sumb;
#pragma unroll
        for (int j = 0; j < 16; ++j) {
            O[j][0] *= alpha_a; O[j][1] *= alpha_a;
            O[j][2] *= alpha_b; O[j][3] *= alpha_b;
        }

        // ---- register P -> A-fragment repack (C-frag maps directly to A-frag) ----
        uint32_t aPh[4][4], aPl[4][4];
#pragma unroll
        for (int k2 = 0; k2 < 4; ++k2) {
            const float* p0 = sa[2*k2];
            const float* p1 = sa[2*k2+1];
            aPh[k2][0] = packbf(p0[0], p0[1]);
            aPh[k2][1] = packbf(p0[2], p0[3]);
            aPh[k2][2] = packbf(p1[0], p1[1]);
            aPh[k2][3] = packbf(p1[2], p1[3]);
            float2 h0 = __bfloat1622float2(*(__nv_bfloat162*)&aPh[k2][0]);
            float2 h1 = __bfloat1622float2(*(__nv_bfloat162*)&aPh[k2][1]);
            float2 h2 = __bfloat1622float2(*(__nv_bfloat162*)&aPh[k2][2]);
            float2 h3 = __bfloat1622float2(*(__nv_bfloat162*)&aPh[k2][3]);
            aPl[k2][0] = packbf(p0[0] - h0.x, p0[1] - h0.y);
            aPl[k2][1] = packbf(p0[2] - h1.x, p0[3] - h1.y);
            aPl[k2][2] = packbf(p1[0] - h2.x, p1[1] - h2.y);
            aPl[k2][3] = packbf(p1[2] - h3.x, p1[3] - h3.y);
        }

        // ---- O += P V (3-term split) ----
#pragma unroll
        for (int g = 0; g < 8; ++g) {
#pragma unroll
            for (int k2 = 0; k2 < 4; ++k2) {
                uint32_t b[4];
                ldsm_x4_t(b[0], b[1], b[2], b[3],
                          st + 32768u + swz256(k2 * 16 + vt_row, g * 32 + vt_cb)); // Vh
                mma16816(O[2*g],   aPh[k2], b);
                mma16816(O[2*g+1], aPh[k2], b + 2);
                mma16816(O[2*g],   aPl[k2], b);
                mma16816(O[2*g+1], aPl[k2], b + 2);
                ldsm_x4_t(b[0], b[1], b[2], b[3],
                          st + 49152u + swz256(k2 * 16 + vt_row, g * 32 + vt_cb)); // Vl
                mma16816(O[2*g],   aPh[k2], b);
                mma16816(O[2*g+1], aPh[k2], b + 2);
            }
        }

        __syncthreads();               // all warps done reading V(kt)
        if (kt + 1 < nkt) issue_v(kt + 1);
    }

    // ---- epilogue: normalize, split to bf16 hi/lo, write ctx [B,S,E] ----
    const int b = bh >> 4, h = bh & 15;
    const float inva = 1.0f / l_a, invb = 1.0f / l_b;
    const size_t base_a = ((size_t)(b * SEQ + qa)) * EMB + h * HD;
    const size_t base_b = ((size_t)(b * SEQ + qb)) * EMB + h * HD;
#pragma unroll
    for (int j = 0; j < 16; ++j) {
        int dcol = j * 8 + (lane & 3) * 2;
        float oa0 = O[j][0] * inva, oa1 = O[j][1] * inva;
        float ob0 = O[j][2] * invb, ob1 = O[j][3] * invb;
        uint32_t ha = packbf(oa0, oa1);
        uint32_t hb = packbf(ob0, ob1);
        float2 fa = __bfloat1622float2(*(__nv_bfloat162*)&ha);
        float2 fb = __bfloat1622float2(*(__nv_bfloat162*)&hb);
        uint32_t la = packbf(oa0 - fa.x, oa1 - fa.y);
        uint32_t lb = packbf(ob0 - fb.x, ob1 - fb.y);
        *(uint32_t*)(g_AH[2] + base_a + dcol) = ha;
        *(uint32_t*)(g_AL[2] + base_a + dcol) = la;
        *(uint32_t*)(g_AH[2] + base_b + dcol) = hb;
        *(uint32_t*)(g_AL[2] + base_b + dcol) = lb;
    }
}

// =================================================================================
extern "C" void kernel_launch(void* const* d_in, const int* in_sizes, int n_in,
                              void* d_out, int out_size)
{
    const float* query = (const float*)d_in[0];
    const float* key   = (const float*)d_in[1];
    const float* value = (const float*)d_in[2];
    const float* cosT  = (const float*)d_in[4];
    const float* sinT  = (const float*)d_in[5];
    const float* Wq    = (const float*)d_in[6];
    const float* Wk    = (const float*)d_in[7];
    const float* Wv    = (const float*)d_in[8];
    const float* Wo    = (const float*)d_in[9];

    __nv_bfloat16 *pAH0, *pAL0, *pAH1, *pAL1, *pAH2, *pAL2;
    __nv_bfloat16 *pBH0, *pBL0, *pBH1, *pBL1, *pBH2, *pBL2, *pBH3, *pBL3;
    cudaGetSymbolAddress((void**)&pAH0, g_AH);
    cudaGetSymbolAddress((void**)&pAL0, g_AL);
    cudaGetSymbolAddress((void**)&pBH0, g_BH);
    cudaGetSymbolAddress((void**)&pBL0, g_BL);
    const size_t NA = (size_t)MROWS * EMB;
    const size_t NB = (size_t)EMB * EMB;
    pAH1 = pAH0 + NA; pAH2 = pAH0 + 2 * NA;
    pAL1 = pAL0 + NA; pAL2 = pAL0 + 2 * NA;
    pBH1 = pBH0 + NB; pBH2 = pBH0 + 2 * NB; pBH3 = pBH0 + 3 * NB;
    pBL1 = pBL0 + NB; pBL2 = pBL0 + 2 * NB; pBL3 = pBL0 + 3 * NB;

    cudaFuncSetAttribute(gemm_qkv, cudaFuncAttributeMaxDynamicSharedMemorySize, GEMM_SMEM);
    cudaFuncSetAttribute(gemm_out, cudaFuncAttributeMaxDynamicSharedMemorySize, GEMM_SMEM);
    cudaFuncSetAttribute(attn_tc4, cudaFuncAttributeMaxDynamicSharedMemorySize, A4_SMEM);

    const int nX4 = MROWS * EMB / 4;
    const int nW4 = EMB * EMB / 4;

    split_batch<<<dim3(nX4 / 256, 3), 256>>>(
        query, key, value, query,
        pAH0, pAL0, pAH1, pAL1, pAH2, pAL2, pAH0, pAL0, nX4);
    split_batch<<<dim3(nW4 / 256, 4), 256>>>(
        Wq, Wk, Wv, Wo,
        pBH0, pBL0, pBH1, pBL1, pBH2, pBL2, pBH3, pBL3, nW4);

    // Q/K/V projections (128x128 tiles, 2 CTAs/SM) with fused RoPE+split epilogues
    gemm_qkv<<<dim3(EMB / GBN, MROWS / GBM, 3), 256, GEMM_SMEM>>>(cosT, sinT);

    // tensor-core flash attention v4
    attn_tc4<<<dim3(16, 64), 128, A4_SMEM>>>();

    // output projection
    gemm_out<<<dim3(EMB / GBN, MROWS / GBM), 256, GEMM_SMEM>>>((float*)d_out);
}